// round 7
// baseline (speedup 1.0000x reference)
#include <cuda_runtime.h>
#include <cuda_bf16.h>
#include <cstdint>

#define BB    2
#define CC    256
#define HW    2304
#define HEADS 8
#define DK    32
#define NCH   (BB*CC*HW)

// ---------------- scratch (device globals; no allocation) ----------------
__device__ float g_w[NCH];              // wf projection (fp32)
__device__ float g_mn[BB*64*HW];        // m (rows 0-31) and n (rows 32-63)
__device__ float g_tsa[NCH];
__device__ float g_gsa[NCH];
__device__ float g_l[BB*HW];            // GSA softmax row sums
__device__ float g_pa[(size_t)BB*HW*HW]; // unnormalized exp(scores)
__device__ __nv_bfloat16 g_qh[NCH];     // [bh][t][d], pre-scaled
__device__ __nv_bfloat16 g_kh[NCH];     // [bh][t][d]
__device__ __nv_bfloat16 g_vh[NCH];     // [bh][d][t]

// ---------------- fast exp on the FMA pipe ----------------
__device__ __forceinline__ float fexp(float x) {
    float t = x * 1.4426950408889634f;
    t = fmaxf(t, -126.0f);
    float r = t + 12582912.0f;
    int   ii = __float_as_int(r) - 0x4B400000;
    float fi = r - 12582912.0f;
    float f  = t - fi;
    float p  = 1.3333558e-3f;
    p = fmaf(p, f, 9.6181291e-3f);
    p = fmaf(p, f, 5.5504109e-2f);
    p = fmaf(p, f, 2.4022651e-1f);
    p = fmaf(p, f, 6.9314718e-1f);
    p = fmaf(p, f, 1.0f);
    return __int_as_float(__float_as_int(p) + (ii << 23));
}

// ---------------- mma helpers ----------------
__device__ __forceinline__ void mma16816(float* c, const uint32_t* a, uint32_t b0, uint32_t b1) {
    asm volatile(
        "mma.sync.aligned.m16n8k16.row.col.f32.bf16.bf16.f32 "
        "{%0,%1,%2,%3}, {%4,%5,%6,%7}, {%8,%9}, {%0,%1,%2,%3};"
        : "+f"(c[0]), "+f"(c[1]), "+f"(c[2]), "+f"(c[3])
        : "r"(a[0]), "r"(a[1]), "r"(a[2]), "r"(a[3]), "r"(b0), "r"(b1));
}
__device__ __forceinline__ void mma_tf32(float* c, const uint32_t* a, uint32_t b0, uint32_t b1) {
    asm volatile(
        "mma.sync.aligned.m16n8k8.row.col.f32.tf32.tf32.f32 "
        "{%0,%1,%2,%3}, {%4,%5,%6,%7}, {%8,%9}, {%0,%1,%2,%3};"
        : "+f"(c[0]), "+f"(c[1]), "+f"(c[2]), "+f"(c[3])
        : "r"(a[0]), "r"(a[1]), "r"(a[2]), "r"(a[3]), "r"(b0), "r"(b1));
}
__device__ __forceinline__ uint32_t pack_bf16x2(float hi, float lo) {
    uint32_t w;
    asm("cvt.rn.satfinite.bf16x2.f32 %0, %1, %2;" : "=r"(w) : "f"(hi), "f"(lo));
    return w;
}
__device__ __forceinline__ uint32_t cvt_tf32(float f) {
    uint32_t r;
    asm("cvt.rna.tf32.f32 %0, %1;" : "=r"(r) : "f"(f));
    return r;
}
__device__ __forceinline__ uint4 cvt4_tf32(float4 v) {
    uint4 o;
    o.x = cvt_tf32(v.x); o.y = cvt_tf32(v.y); o.z = cvt_tf32(v.z); o.w = cvt_tf32(v.w);
    return o;
}

#define AS_STR 36
#define BS_STR 136
#define ASZ (64 * AS_STR)
#define BSZ (32 * BS_STR)
#define A128 (128 * AS_STR)

__device__ __forceinline__ void tf32_chunk(
    const uint32_t* Ap, const uint32_t* Bp, float c[2][4][4],
    int warpm, int warpn, int gr, int gc)
{
#pragma unroll
    for (int ks = 0; ks < 4; ks++) {
        uint32_t a[2][4], bq[4][2];
#pragma unroll
        for (int mt = 0; mt < 2; mt++) {
            const uint32_t* ab = Ap + (warpm * 32 + mt * 16) * AS_STR + ks * 8 + gc;
            a[mt][0] = ab[gr * AS_STR];
            a[mt][1] = ab[(gr + 8) * AS_STR];
            a[mt][2] = ab[gr * AS_STR + 4];
            a[mt][3] = ab[(gr + 8) * AS_STR + 4];
        }
#pragma unroll
        for (int nt = 0; nt < 4; nt++) {
            const uint32_t* bb = Bp + (ks * 8 + gc) * BS_STR + warpn * 32 + nt * 8 + gr;
            bq[nt][0] = bb[0];
            bq[nt][1] = bb[4 * BS_STR];
        }
#pragma unroll
        for (int mt = 0; mt < 2; mt++)
#pragma unroll
            for (int nt = 0; nt < 4; nt++)
                mma_tf32(c[mt][nt], a[mt], bq[nt][0], bq[nt][1]);
    }
}

// ============ Launch A: fused mn-projection (fp32) + QKVW proj4 (tf32) ====
// grid 648: bid<72 -> mn proj; else proj4 (t = bid-72: sel=(t/36)>>2 ...).
__global__ void __launch_bounds__(256) proj_all(
    const float* __restrict__ wm, const float* __restrict__ bm,
    const float* __restrict__ wn, const float* __restrict__ bn,
    const float* __restrict__ wq, const float* __restrict__ bq,
    const float* __restrict__ wk, const float* __restrict__ bk,
    const float* __restrict__ wv, const float* __restrict__ bv,
    const float* __restrict__ ww, const float* __restrict__ bw,
    const float* __restrict__ x)
{
    __shared__ __align__(16) char smu[(ASZ + BSZ) * 4];
    int bid = blockIdx.x;
    int tid = threadIdx.x;

    if (bid < 72) {
        // ---- m/n projection, fp32 SIMT (concentration-sensitive) ----
        float (*As)[64] = (float(*)[64])smu;
        float (*Bs)[64] = ((float(*)[64])smu) + 16;
        int jt  = bid;
        int b   = (jt * 64) / HW;
        int hw0 = (jt * 64) % HW;
        const float* xb = x + (size_t)b * CC * HW + hw0;
        int tx = tid & 15, ty = tid >> 4;
        float acc[4][4];
#pragma unroll
        for (int i = 0; i < 4; i++)
#pragma unroll
            for (int j = 0; j < 4; j++) acc[i][j] = 0.f;

        int lo  = tid >> 2;
        int lk4 = (tid & 3) * 4;
        int bk2 = tid >> 4;
        int bj4 = (tid & 15) * 4;
        const float* Wrow = lo < 32 ? wm + (size_t)lo * 256 : wn + (size_t)(lo - 32) * 256;

        for (int k0 = 0; k0 < CC; k0 += 16) {
            float4 wv4 = *(const float4*)(Wrow + k0 + lk4);
            As[lk4 + 0][lo] = wv4.x; As[lk4 + 1][lo] = wv4.y;
            As[lk4 + 2][lo] = wv4.z; As[lk4 + 3][lo] = wv4.w;
            float4 xv = *(const float4*)(xb + (size_t)(k0 + bk2) * HW + bj4);
            *(float4*)&Bs[bk2][bj4] = xv;
            __syncthreads();
#pragma unroll
            for (int k = 0; k < 16; k++) {
                float4 a  = *(float4*)&As[k][ty * 4];
                float4 bb = *(float4*)&Bs[k][tx * 4];
                float av[4] = {a.x, a.y, a.z, a.w};
                float bv2[4] = {bb.x, bb.y, bb.z, bb.w};
#pragma unroll
                for (int i = 0; i < 4; i++)
#pragma unroll
                    for (int j = 0; j < 4; j++)
                        acc[i][j] = fmaf(av[i], bv2[j], acc[i][j]);
            }
            __syncthreads();
        }
#pragma unroll
        for (int i = 0; i < 4; i++) {
            int o = ty * 4 + i;
            float bsv = o < 32 ? bm[o] : bn[o - 32];
            float4 ov = make_float4(acc[i][0] + bsv, acc[i][1] + bsv,
                                    acc[i][2] + bsv, acc[i][3] + bsv);
            *(float4*)(g_mn + (size_t)b * 64 * HW + (size_t)o * HW + hw0 + tx * 4) = ov;
        }
        return;
    }

    // ---- QKVW tf32 projection with bf16 epilogues ----
    uint32_t* As = (uint32_t*)smu;
    uint32_t* Bs = (uint32_t*)smu + ASZ;
    int t = bid - 72;
    int by = t / 36, bx = t % 36;
    int lane = tid & 31, wid = tid >> 5;
    int gr = lane >> 2, gc = lane & 3;
    int sel  = by >> 2;
    int row0 = (by & 3) * 64;
    const float* W    = sel == 0 ? wq : sel == 1 ? wk : sel == 2 ? wv : ww;
    const float* bias = sel == 0 ? bq : sel == 1 ? bk : sel == 2 ? bv : bw;
    int b = bx / 18, hw0 = (bx % 18) * 128;
    const float* Bb = x + (size_t)b * CC * HW + hw0;
    int warpm = wid >> 2, warpn = wid & 3;
    float c[2][4][4];
#pragma unroll
    for (int i = 0; i < 2; i++)
#pragma unroll
        for (int j = 0; j < 4; j++)
#pragma unroll
            for (int k = 0; k < 4; k++) c[i][j][k] = 0.f;

    for (int k0 = 0; k0 < 256; k0 += 32) {
#pragma unroll
        for (int i = 0; i < 2; i++) {
            int e = tid + i * 256;
            int r = e >> 3, k4 = (e & 7) * 4;
            float4 w4 = *(const float4*)(W + (size_t)(row0 + r) * 256 + k0 + k4);
            *(uint4*)(As + r * AS_STR + k4) = cvt4_tf32(w4);
        }
#pragma unroll
        for (int i = 0; i < 4; i++) {
            int e = tid + i * 256;
            int k = e >> 5, n4 = (e & 31) * 4;
            float4 v4 = *(const float4*)(Bb + (size_t)(k0 + k) * HW + n4);
            *(uint4*)(Bs + k * BS_STR + n4) = cvt4_tf32(v4);
        }
        __syncthreads();
        tf32_chunk(As, Bs, c, warpm, warpn, gr, gc);
        __syncthreads();
    }

    if (sel == 3) {
#pragma unroll
        for (int mt = 0; mt < 2; mt++)
#pragma unroll
            for (int rh = 0; rh < 2; rh++) {
                int r = row0 + warpm * 32 + mt * 16 + rh * 8 + gr;
                float bv2 = bias[r];
#pragma unroll
                for (int nt = 0; nt < 4; nt++) {
                    int col = hw0 + warpn * 32 + nt * 8 + gc * 2;
                    size_t idx = (size_t)b * CC * HW + (size_t)r * HW + col;
                    *(float2*)(g_w + idx) = make_float2(c[mt][nt][rh * 2 + 0] + bv2,
                                                        c[mt][nt][rh * 2 + 1] + bv2);
                }
            }
    } else if (sel == 2) {
#pragma unroll
        for (int mt = 0; mt < 2; mt++)
#pragma unroll
            for (int rh = 0; rh < 2; rh++) {
                int r = row0 + warpm * 32 + mt * 16 + rh * 8 + gr;
                float bv2 = bias[r];
#pragma unroll
                for (int nt = 0; nt < 4; nt++) {
                    int col = hw0 + warpn * 32 + nt * 8 + gc * 2;
                    size_t idx = (size_t)(b * 256 + r) * HW + col;
                    uint32_t pw = pack_bf16x2(c[mt][nt][rh * 2 + 1] + bv2,
                                              c[mt][nt][rh * 2 + 0] + bv2);
                    *(uint32_t*)(g_vh + idx) = pw;
                }
            }
    } else {
        float scale = sel == 0 ? 0.17677669529663687f : 1.0f;
        __nv_bfloat16* dst = sel == 0 ? g_qh : g_kh;
#pragma unroll
        for (int mt = 0; mt < 2; mt++)
#pragma unroll
            for (int rh = 0; rh < 2; rh++) {
                int r = row0 + warpm * 32 + mt * 16 + rh * 8 + gr;
                float bv2 = bias[r];
                size_t hb = (size_t)(b * 8 + (r >> 5)) * HW;
                int d = r & 31;
#pragma unroll
                for (int nt = 0; nt < 4; nt++) {
                    int col = hw0 + warpn * 32 + nt * 8 + gc * 2;
                    float v0 = (c[mt][nt][rh * 2 + 0] + bv2) * scale;
                    float v1 = (c[mt][nt][rh * 2 + 1] + bv2) * scale;
                    dst[(hb + col)     * 32 + d] = __float2bfloat16(v0);
                    dst[(hb + col + 1) * 32 + d] = __float2bfloat16(v1);
                }
            }
    }
}

// ============ Launch B: fused flash TSA + GSA scores/exp ==================
#define QS_STR 40
#define VS_STR 136
#define PAB_STR 68
__global__ void __launch_bounds__(256) flash_pa()
{
    __shared__ __align__(16) char smu[29184];
    int tid = threadIdx.x, wid = tid >> 5, lane = tid & 31;
    int bid = blockIdx.x;

    if (bid < 288) {
        // ---------------- flash TSA ----------------
        __nv_bfloat16* Qs = (__nv_bfloat16*)smu;            // 128*40
        __nv_bfloat16* Ks = Qs + 128 * QS_STR;              // 128*40
        __nv_bfloat16* Vs = Ks + 128 * QS_STR;              // 32*136
        int bh = bid / 18, i0 = (bid % 18) * 128;
        int gr = lane >> 2, gc = (lane & 3) * 2;

        const __nv_bfloat16* qsrc = g_qh + ((size_t)bh * HW + i0) * DK;
        const __nv_bfloat16* ksrc = g_kh + (size_t)bh * HW * DK;
        const __nv_bfloat16* vsrc = g_vh + (size_t)bh * DK * HW;

        for (int e = tid; e < 512; e += 256) {
            int r = e >> 2, c8 = (e & 3) * 8;
            *(uint4*)(Qs + r * QS_STR + c8) = *(const uint4*)(qsrc + r * DK + c8);
        }
        __syncthreads();

        uint32_t qa[2][4];
        {
            const __nv_bfloat16* qb = Qs + (wid * 16 + gr) * QS_STR;
#pragma unroll
            for (int kc = 0; kc < 2; kc++) {
                qa[kc][0] = *(const uint32_t*)(qb + kc * 16 + gc);
                qa[kc][1] = *(const uint32_t*)(qb + 8 * QS_STR + kc * 16 + gc);
                qa[kc][2] = *(const uint32_t*)(qb + kc * 16 + gc + 8);
                qa[kc][3] = *(const uint32_t*)(qb + 8 * QS_STR + kc * 16 + gc + 8);
            }
        }

        float o[4][4];
#pragma unroll
        for (int i = 0; i < 4; i++)
#pragma unroll
            for (int j = 0; j < 4; j++) o[i][j] = 0.f;
        float l0 = 0.f, l1 = 0.f;

        for (int kt = 0; kt < 18; kt++) {
            int j0 = kt * 128;
            __syncthreads();
            for (int e = tid; e < 512; e += 256) {
                int r = e >> 2, c8 = (e & 3) * 8;
                *(uint4*)(Ks + r * QS_STR + c8) = *(const uint4*)(ksrc + (size_t)(j0 + r) * DK + c8);
            }
            for (int e = tid; e < 512; e += 256) {
                int d = e >> 4, c8 = (e & 15) * 8;
                *(uint4*)(Vs + d * VS_STR + c8) = *(const uint4*)(vsrc + (size_t)d * HW + j0 + c8);
            }
            __syncthreads();

            float s[16][4];
#pragma unroll
            for (int nt = 0; nt < 16; nt++) {
                s[nt][0] = 0.f; s[nt][1] = 0.f; s[nt][2] = 0.f; s[nt][3] = 0.f;
                const __nv_bfloat16* kb = Ks + (nt * 8 + gr) * QS_STR;
#pragma unroll
                for (int kc = 0; kc < 2; kc++) {
                    uint32_t b0 = *(const uint32_t*)(kb + kc * 16 + gc);
                    uint32_t b1 = *(const uint32_t*)(kb + kc * 16 + gc + 8);
                    mma16816(s[nt], qa[kc], b0, b1);
                }
            }

            // exp split 6:2 across MUFU and FMA pipes
            uint32_t pa_[8][4];
#pragma unroll
            for (int h2 = 0; h2 < 8; h2++) {
                float e00 = __expf(s[2 * h2][0]),     e01 = __expf(s[2 * h2][1]);
                float e02 = __expf(s[2 * h2][2]),     e03 = fexp(s[2 * h2][3]);
                float f00 = __expf(s[2 * h2 + 1][0]), f01 = __expf(s[2 * h2 + 1][1]);
                float f02 = __expf(s[2 * h2 + 1][2]), f03 = fexp(s[2 * h2 + 1][3]);
                l0 += (e00 + e01) + (f00 + f01);
                l1 += (e02 + e03) + (f02 + f03);
                pa_[h2][0] = pack_bf16x2(e01, e00);
                pa_[h2][1] = pack_bf16x2(e03, e02);
                pa_[h2][2] = pack_bf16x2(f01, f00);
                pa_[h2][3] = pack_bf16x2(f03, f02);
            }

#pragma unroll
            for (int kc2 = 0; kc2 < 8; kc2++) {
#pragma unroll
                for (int dt = 0; dt < 4; dt++) {
                    const __nv_bfloat16* vb = Vs + (dt * 8 + gr) * VS_STR + kc2 * 16 + gc;
                    uint32_t b0 = *(const uint32_t*)(vb);
                    uint32_t b1 = *(const uint32_t*)(vb + 8);
                    mma16816(o[dt], pa_[kc2], b0, b1);
                }
            }
        }

        l0 += __shfl_xor_sync(0xffffffffu, l0, 1);
        l0 += __shfl_xor_sync(0xffffffffu, l0, 2);
        l1 += __shfl_xor_sync(0xffffffffu, l1, 1);
        l1 += __shfl_xor_sync(0xffffffffu, l1, 2);
        float inv0 = 1.f / l0, inv1 = 1.f / l1;

        int b = bh >> 3, h = bh & 7;
        float* ob = g_tsa + ((size_t)b * CC + h * DK) * HW;
        int tok0 = i0 + wid * 16 + gr;
#pragma unroll
        for (int dt = 0; dt < 4; dt++) {
            int d = dt * 8 + gc;
            ob[(size_t)(d)     * HW + tok0]     = o[dt][0] * inv0;
            ob[(size_t)(d + 1) * HW + tok0]     = o[dt][1] * inv0;
            ob[(size_t)(d)     * HW + tok0 + 8] = o[dt][2] * inv1;
            ob[(size_t)(d + 1) * HW + tok0 + 8] = o[dt][3] * inv1;
        }
        return;
    }

    // ---------------- GSA scores + exp (split-tf32, fp32-accurate) --------
    {
        uint32_t* Ahi = (uint32_t*)smu;           // 32*36
        uint32_t* Alo = Ahi + 32 * 36;            // 32*36
        uint32_t* Bhi = Alo + 32 * 36;            // 32*68
        uint32_t* Blo = Bhi + 32 * PAB_STR;       // 32*68
        float*    red = (float*)(Blo + 32 * PAB_STR);  // 256 floats
        int gr = lane >> 2, gc = lane & 3;
        int t2 = bid - 288;
        int b = t2 / 72, n0 = (t2 % 72) * 32;
        const float* Mp = g_mn + (size_t)b * 64 * HW;
        const float* Np = Mp + (size_t)32 * HW;

        for (int e = tid; e < 1024; e += 256) {
            int ch = e >> 5, n = e & 31;
            float v = Mp[(size_t)ch * HW + n0 + n];
            uint32_t h = cvt_tf32(v);
            Ahi[n * 36 + ch] = h;
            Alo[n * 36 + ch] = cvt_tf32(v - __uint_as_float(h));
        }

        int bm2 = tid & 63, bc0 = tid >> 6;
        float rbv[8];
#pragma unroll
        for (int i = 0; i < 8; i++)
            rbv[i] = Np[(size_t)(bc0 + i * 4) * HW + bm2];

        float rs[2][2] = {{0.f, 0.f}, {0.f, 0.f}};
        float* pab = g_pa + (size_t)b * HW * HW;
        __syncthreads();

        for (int t = 0; t < 36; t++) {
#pragma unroll
            for (int i = 0; i < 8; i++) {
                int ch = bc0 + i * 4;
                uint32_t h = cvt_tf32(rbv[i]);
                Bhi[ch * PAB_STR + bm2] = h;
                Blo[ch * PAB_STR + bm2] = cvt_tf32(rbv[i] - __uint_as_float(h));
            }
            __syncthreads();
            if (t + 1 < 36) {
#pragma unroll
                for (int i = 0; i < 8; i++)
                    rbv[i] = Np[(size_t)(bc0 + i * 4) * HW + (t + 1) * 64 + bm2];
            }
            float c[2][4];
#pragma unroll
            for (int mt = 0; mt < 2; mt++)
#pragma unroll
                for (int j = 0; j < 4; j++) c[mt][j] = 0.f;
#pragma unroll
            for (int ks = 0; ks < 4; ks++) {
                uint32_t ah[2][4], al[2][4];
#pragma unroll
                for (int mt = 0; mt < 2; mt++) {
                    int rb2 = mt * 16;
                    ah[mt][0] = Ahi[(rb2 + gr) * 36 + ks * 8 + gc];
                    ah[mt][1] = Ahi[(rb2 + gr + 8) * 36 + ks * 8 + gc];
                    ah[mt][2] = Ahi[(rb2 + gr) * 36 + ks * 8 + gc + 4];
                    ah[mt][3] = Ahi[(rb2 + gr + 8) * 36 + ks * 8 + gc + 4];
                    al[mt][0] = Alo[(rb2 + gr) * 36 + ks * 8 + gc];
                    al[mt][1] = Alo[(rb2 + gr + 8) * 36 + ks * 8 + gc];
                    al[mt][2] = Alo[(rb2 + gr) * 36 + ks * 8 + gc + 4];
                    al[mt][3] = Alo[(rb2 + gr + 8) * 36 + ks * 8 + gc + 4];
                }
                int colb = wid * 8 + gr;
                uint32_t bh0 = Bhi[(ks * 8 + gc) * PAB_STR + colb];
                uint32_t bh1 = Bhi[(ks * 8 + gc + 4) * PAB_STR + colb];
                uint32_t bl0 = Blo[(ks * 8 + gc) * PAB_STR + colb];
                uint32_t bl1 = Blo[(ks * 8 + gc + 4) * PAB_STR + colb];
#pragma unroll
                for (int mt = 0; mt < 2; mt++) {
                    mma_tf32(c[mt], ah[mt], bh0, bh1);
                    mma_tf32(c[mt], ah[mt], bl0, bl1);
                    mma_tf32(c[mt], al[mt], bh0, bh1);
                }
            }
            int m_base = t * 64 + wid * 8 + gc * 2;
#pragma unroll
            for (int mt = 0; mt < 2; mt++)
#pragma unroll
                for (int rh = 0; rh < 2; rh++) {
                    float p0 = __expf(c[mt][rh * 2 + 0]);
                    float p1 = __expf(c[mt][rh * 2 + 1]);
                    rs[mt][rh] += p0 + p1;
                    int n = n0 + mt * 16 + rh * 8 + gr;
                    *(float2*)(pab + (size_t)n * HW + m_base) = make_float2(p0, p1);
                }
            __syncthreads();
        }

#pragma unroll
        for (int mt = 0; mt < 2; mt++)
#pragma unroll
            for (int rh = 0; rh < 2; rh++) {
                float v = rs[mt][rh];
                v += __shfl_xor_sync(0xffffffffu, v, 1);
                v += __shfl_xor_sync(0xffffffffu, v, 2);
                if (gc == 0) red[(mt * 16 + rh * 8 + gr) * 8 + wid] = v;
            }
        __syncthreads();
        if (tid < 32) {
            float s = 0.f;
#pragma unroll
            for (int w = 0; w < 8; w++) s += red[tid * 8 + w];
            g_l[(size_t)b * HW + n0 + tid] = s;
        }
    }
}

// ============ Launch C: 128x128 double-buffered tf32 GSA ==================
// grid (18, 2, 2): x=n-block(128), y=c-block(128), z=batch. K=2304.
__global__ void __launch_bounds__(256) tf32_gsa()
{
    extern __shared__ uint32_t dsm[];
    uint32_t* As = dsm;               // [2][A128]
    uint32_t* Bs = dsm + 2 * A128;    // [2][BSZ]
    int tid = threadIdx.x, lane = tid & 31, wid = tid >> 5;
    int gr = lane >> 2, gc = lane & 3;
    int b = blockIdx.z, c0 = blockIdx.y * 128, n0 = blockIdx.x * 128;
    const float* wfb = g_w + (size_t)b * CC * HW;
    const float* pab = g_pa + (size_t)b * HW * HW;
    int warpm = wid >> 2, warpn = wid & 3;

    int ar = tid >> 3, ak4 = (tid & 7) * 4;     // A: r = ar + 32*i
    int bn = tid & 127, bk4_0 = (tid >> 7) * 4; // B: k4 = bk4_0 + 8*i

    float4 ra[4], rb[4];
#pragma unroll
    for (int i = 0; i < 4; i++)
        ra[i] = *(const float4*)(wfb + (size_t)(c0 + ar + 32 * i) * HW + 0 + ak4);
#pragma unroll
    for (int i = 0; i < 4; i++)
        rb[i] = *(const float4*)(pab + (size_t)(n0 + bn) * HW + 0 + (bk4_0 + i * 8));
#pragma unroll
    for (int i = 0; i < 4; i++)
        *(uint4*)(As + (ar + 32 * i) * AS_STR + ak4) = cvt4_tf32(ra[i]);
#pragma unroll
    for (int i = 0; i < 4; i++) {
        int k4 = bk4_0 + i * 8;
        Bs[(k4 + 0) * BS_STR + bn] = cvt_tf32(rb[i].x);
        Bs[(k4 + 1) * BS_STR + bn] = cvt_tf32(rb[i].y);
        Bs[(k4 + 2) * BS_STR + bn] = cvt_tf32(rb[i].z);
        Bs[(k4 + 3) * BS_STR + bn] = cvt_tf32(rb[i].w);
    }
    __syncthreads();

    float c[4][4][4];
#pragma unroll
    for (int i = 0; i < 4; i++)
#pragma unroll
        for (int j = 0; j < 4; j++)
#pragma unroll
            for (int k = 0; k < 4; k++) c[i][j][k] = 0.f;

    for (int it = 0; it < 72; it++) {
        int p = it & 1;
        int m1 = (it + 1) * 32;
        if (it + 1 < 72) {
#pragma unroll
            for (int i = 0; i < 4; i++)
                ra[i] = *(const float4*)(wfb + (size_t)(c0 + ar + 32 * i) * HW + m1 + ak4);
#pragma unroll
            for (int i = 0; i < 4; i++)
                rb[i] = *(const float4*)(pab + (size_t)(n0 + bn) * HW + m1 + (bk4_0 + i * 8));
        }
        {
            const uint32_t* Ap = As + p * A128;
            const uint32_t* Bp = Bs + p * BSZ;
#pragma unroll
            for (int ks = 0; ks < 4; ks++) {
                uint32_t a[4][4], bq[4][2];
#pragma unroll
                for (int mt = 0; mt < 4; mt++) {
                    const uint32_t* ab = Ap + (warpm * 64 + mt * 16) * AS_STR + ks * 8 + gc;
                    a[mt][0] = ab[gr * AS_STR];
                    a[mt][1] = ab[(gr + 8) * AS_STR];
                    a[mt][2] = ab[gr * AS_STR + 4];
                    a[mt][3] = ab[(gr + 8) * AS_STR + 4];
                }
#pragma unroll
                for (int nt = 0; nt < 4; nt++) {
                    const uint32_t* bb = Bp + (ks * 8 + gc) * BS_STR + warpn * 32 + nt * 8 + gr;
                    bq[nt][0] = bb[0];
                    bq[nt][1] = bb[4 * BS_STR];
                }
#pragma unroll
                for (int mt = 0; mt < 4; mt++)
#pragma unroll
                    for (int nt = 0; nt < 4; nt++)
                        mma_tf32(c[mt][nt], a[mt], bq[nt][0], bq[nt][1]);
            }
        }
        if (it + 1 < 72) {
            uint32_t* Ad = As + (p ^ 1) * A128;
            uint32_t* Bd = Bs + (p ^ 1) * BSZ;
#pragma unroll
            for (int i = 0; i < 4; i++)
                *(uint4*)(Ad + (ar + 32 * i) * AS_STR + ak4) = cvt4_tf32(ra[i]);
#pragma unroll
            for (int i = 0; i < 4; i++) {
                int k4 = bk4_0 + i * 8;
                Bd[(k4 + 0) * BS_STR + bn] = cvt_tf32(rb[i].x);
                Bd[(k4 + 1) * BS_STR + bn] = cvt_tf32(rb[i].y);
                Bd[(k4 + 2) * BS_STR + bn] = cvt_tf32(rb[i].z);
                Bd[(k4 + 3) * BS_STR + bn] = cvt_tf32(rb[i].w);
            }
        }
        __syncthreads();
    }

    float inv[4][2];
#pragma unroll
    for (int nt = 0; nt < 4; nt++) {
        int col = n0 + warpn * 32 + nt * 8 + gc * 2;
        inv[nt][0] = 1.f / g_l[(size_t)b * HW + col];
        inv[nt][1] = 1.f / g_l[(size_t)b * HW + col + 1];
    }
    float* ob = g_gsa + (size_t)b * CC * HW;
#pragma unroll
    for (int mt = 0; mt < 4; mt++)
#pragma unroll
        for (int rh = 0; rh < 2; rh++) {
            int r = c0 + warpm * 64 + mt * 16 + rh * 8 + gr;
#pragma unroll
            for (int nt = 0; nt < 4; nt++) {
                int col = n0 + warpn * 32 + nt * 8 + gc * 2;
                *(float2*)(ob + (size_t)r * HW + col) =
                    make_float2(c[mt][nt][rh * 2 + 0] * inv[nt][0],
                                c[mt][nt][rh * 2 + 1] * inv[nt][1]);
            }
        }
}

// ============ Launch D: final GEMM + fusion epilogue ======================
__global__ void __launch_bounds__(256) tf32_final(
    const float* __restrict__ wo, const float* __restrict__ bo,
    const float* __restrict__ xin,
    const float* __restrict__ gt_p, const float* __restrict__ gg_p,
    float* __restrict__ out)
{
    extern __shared__ uint32_t dsm[];
    uint32_t* As = dsm;
    uint32_t* Bs = dsm + 2 * ASZ;
    int tid = threadIdx.x, lane = tid & 31, wid = tid >> 5;
    int gr = lane >> 2, gc = lane & 3;
    int row0 = blockIdx.y * 64;
    int b = blockIdx.x / 18, hw0 = (blockIdx.x % 18) * 128;
    const float* Bb = g_gsa + (size_t)b * CC * HW + hw0;
    int warpm = wid >> 2, warpn = wid & 3;

    int ar = tid >> 3, ak4 = (tid & 7) * 4;
    int ar2 = (tid + 256) >> 3;
    int bk = tid >> 5, bn4 = (tid & 31) * 4;

    float4 ra[2], rb[4];
#pragma unroll
    for (int i = 0; i < 2; i++) {
        int r = (i == 0) ? ar : ar2;
        ra[i] = *(const float4*)(wo + (size_t)(row0 + r) * 256 + 0 + ak4);
    }
#pragma unroll
    for (int i = 0; i < 4; i++)
        rb[i] = *(const float4*)(Bb + (size_t)(0 + bk + i * 8) * HW + bn4);
#pragma unroll
    for (int i = 0; i < 2; i++) {
        int r = (i == 0) ? ar : ar2;
        *(uint4*)(As + r * AS_STR + ak4) = cvt4_tf32(ra[i]);
    }
#pragma unroll
    for (int i = 0; i < 4; i++)
        *(uint4*)(Bs + (bk + i * 8) * BS_STR + bn4) = cvt4_tf32(rb[i]);
    __syncthreads();

    float c[2][4][4];
#pragma unroll
    for (int i = 0; i < 2; i++)
#pragma unroll
        for (int j = 0; j < 4; j++)
#pragma unroll
            for (int k = 0; k < 4; k++) c[i][j][k] = 0.f;

    for (int it = 0; it < 8; it++) {
        int p = it & 1;
        int k1 = (it + 1) * 32;
        if (it + 1 < 8) {
#pragma unroll
            for (int i = 0; i < 2; i++) {
                int r = (i == 0) ? ar : ar2;
                ra[i] = *(const float4*)(wo + (size_t)(row0 + r) * 256 + k1 + ak4);
            }
#pragma unroll
            for (int i = 0; i < 4; i++)
                rb[i] = *(const float4*)(Bb + (size_t)(k1 + bk + i * 8) * HW + bn4);
        }
        tf32_chunk(As + p * ASZ, Bs + p * BSZ, c, warpm, warpn, gr, gc);
        if (it + 1 < 8) {
            uint32_t* Ad = As + (p ^ 1) * ASZ;
            uint32_t* Bd = Bs + (p ^ 1) * BSZ;
#pragma unroll
            for (int i = 0; i < 2; i++) {
                int r = (i == 0) ? ar : ar2;
                *(uint4*)(Ad + r * AS_STR + ak4) = cvt4_tf32(ra[i]);
            }
#pragma unroll
            for (int i = 0; i < 4; i++)
                *(uint4*)(Bd + (bk + i * 8) * BS_STR + bn4) = cvt4_tf32(rb[i]);
        }
        __syncthreads();
    }

    float gt = gt_p[0], gg = gg_p[0];
#pragma unroll
    for (int mt = 0; mt < 2; mt++)
#pragma unroll
        for (int rh = 0; rh < 2; rh++) {
            int r = row0 + warpm * 32 + mt * 16 + rh * 8 + gr;
            float bv = bo[r];
#pragma unroll
            for (int nt = 0; nt < 4; nt++) {
                int col = hw0 + warpn * 32 + nt * 8 + gc * 2;
                size_t idx = (size_t)b * CC * HW + (size_t)r * HW + col;
                float2 x2 = *(const float2*)(xin + idx);
                float2 t2 = *(const float2*)(g_tsa + idx);
                float2 o2;
                o2.x = gt * t2.x + gg * (c[mt][nt][rh * 2 + 0] + bv) + x2.x;
                o2.y = gt * t2.y + gg * (c[mt][nt][rh * 2 + 1] + bv) + x2.y;
                *(float2*)(out + idx) = o2;
            }
        }
}

// ---------------- launch ----------------
extern "C" void kernel_launch(void* const* d_in, const int* in_sizes, int n_in,
                              void* d_out, int out_size)
{
    const float* x   = (const float*)d_in[0];
    const float* wq  = (const float*)d_in[1];
    const float* bq  = (const float*)d_in[2];
    const float* wk  = (const float*)d_in[3];
    const float* bk  = (const float*)d_in[4];
    const float* wv  = (const float*)d_in[5];
    const float* bv  = (const float*)d_in[6];
    const float* wm  = (const float*)d_in[7];
    const float* bm  = (const float*)d_in[8];
    const float* wn  = (const float*)d_in[9];
    const float* bn  = (const float*)d_in[10];
    const float* ww  = (const float*)d_in[11];
    const float* bw  = (const float*)d_in[12];
    const float* wo  = (const float*)d_in[13];
    const float* bo  = (const float*)d_in[14];
    const float* gts = (const float*)d_in[15];
    const float* ggs = (const float*)d_in[16];
    float* out = (float*)d_out;

    static int smem_set = 0;
    const int GSA_SMEM = (2 * A128 + 2 * BSZ) * 4;   // 71680 B
    const int FIN_SMEM = (2 * ASZ + 2 * BSZ) * 4;    // 53248 B
    if (!smem_set) {
        cudaFuncSetAttribute(tf32_gsa, cudaFuncAttributeMaxDynamicSharedMemorySize, GSA_SMEM);
        cudaFuncSetAttribute(tf32_final, cudaFuncAttributeMaxDynamicSharedMemorySize, FIN_SMEM);
        smem_set = 1;
    }

    dim3 blk(256);

    proj_all<<<648, blk>>>(wm, bm, wn, bn, wq, bq, wk, bk, wv, bv, ww, bw, x);
    flash_pa<<<432, blk>>>();
    tf32_gsa<<<dim3(18, 2, 2), blk, GSA_SMEM>>>();
    tf32_final<<<dim3(36, 4), blk, FIN_SMEM>>>(wo, bo, x, gts, ggs, out);
}

// round 8
// speedup vs baseline: 1.0368x; 1.0368x over previous
#include <cuda_runtime.h>
#include <cuda_bf16.h>
#include <cstdint>

#define BB    2
#define CC    256
#define HW    2304
#define HEADS 8
#define DK    32
#define CR    32
#define NCH   (BB*CC*HW)

// ---------------- scratch (device globals; no allocation) ----------------
__device__ float g_w[NCH];              // wf projection (fp32)
__device__ float g_mn[BB*64*HW];        // m (rows 0-31) and n (rows 32-63)
__device__ float g_wmn[64*256];
__device__ float g_bmn[64];
__device__ float g_tsa[NCH];
__device__ float g_gsa[NCH];
__device__ float g_l[BB*HW];            // GSA softmax row sums
__device__ float g_pa[(size_t)BB*HW*HW]; // unnormalized exp(scores), 42.5 MB
__device__ __nv_bfloat16 g_qh[NCH];     // [bh][t][d], pre-scaled
__device__ __nv_bfloat16 g_kh[NCH];     // [bh][t][d]
__device__ __nv_bfloat16 g_vh[NCH];     // [bh][d][t]

// ---------------- fast exp on the FMA pipe ----------------
__device__ __forceinline__ float fexp(float x) {
    float t = x * 1.4426950408889634f;
    t = fmaxf(t, -126.0f);
    float r = t + 12582912.0f;
    int   ii = __float_as_int(r) - 0x4B400000;
    float fi = r - 12582912.0f;
    float f  = t - fi;
    float p  = 1.3333558e-3f;
    p = fmaf(p, f, 9.6181291e-3f);
    p = fmaf(p, f, 5.5504109e-2f);
    p = fmaf(p, f, 2.4022651e-1f);
    p = fmaf(p, f, 6.9314718e-1f);
    p = fmaf(p, f, 1.0f);
    return __int_as_float(__float_as_int(p) + (ii << 23));
}

// ---------------- mma helpers ----------------
__device__ __forceinline__ void mma16816(float* c, const uint32_t* a, uint32_t b0, uint32_t b1) {
    asm volatile(
        "mma.sync.aligned.m16n8k16.row.col.f32.bf16.bf16.f32 "
        "{%0,%1,%2,%3}, {%4,%5,%6,%7}, {%8,%9}, {%0,%1,%2,%3};"
        : "+f"(c[0]), "+f"(c[1]), "+f"(c[2]), "+f"(c[3])
        : "r"(a[0]), "r"(a[1]), "r"(a[2]), "r"(a[3]), "r"(b0), "r"(b1));
}
__device__ __forceinline__ void mma_tf32(float* c, const uint32_t* a, uint32_t b0, uint32_t b1) {
    asm volatile(
        "mma.sync.aligned.m16n8k8.row.col.f32.tf32.tf32.f32 "
        "{%0,%1,%2,%3}, {%4,%5,%6,%7}, {%8,%9}, {%0,%1,%2,%3};"
        : "+f"(c[0]), "+f"(c[1]), "+f"(c[2]), "+f"(c[3])
        : "r"(a[0]), "r"(a[1]), "r"(a[2]), "r"(a[3]), "r"(b0), "r"(b1));
}
__device__ __forceinline__ uint32_t pack_bf16x2(float hi, float lo) {
    uint32_t w;
    asm("cvt.rn.satfinite.bf16x2.f32 %0, %1, %2;" : "=r"(w) : "f"(hi), "f"(lo));
    return w;
}
__device__ __forceinline__ uint32_t cvt_tf32(float f) {
    uint32_t r;
    asm("cvt.rna.tf32.f32 %0, %1;" : "=r"(r) : "f"(f));
    return r;
}
__device__ __forceinline__ uint4 cvt4_tf32(float4 v) {
    uint4 o;
    o.x = cvt_tf32(v.x); o.y = cvt_tf32(v.y); o.z = cvt_tf32(v.z); o.w = cvt_tf32(v.w);
    return o;
}

#define AS_STR 36
#define BS_STR 136
#define ASZ (64 * AS_STR)
#define BSZ (32 * BS_STR)

__device__ __forceinline__ void tf32_chunk(
    const uint32_t* Ap, const uint32_t* Bp, float c[2][4][4],
    int warpm, int warpn, int gr, int gc)
{
#pragma unroll
    for (int ks = 0; ks < 4; ks++) {
        uint32_t a[2][4], bq[4][2];
#pragma unroll
        for (int mt = 0; mt < 2; mt++) {
            const uint32_t* ab = Ap + (warpm * 32 + mt * 16) * AS_STR + ks * 8 + gc;
            a[mt][0] = ab[gr * AS_STR];
            a[mt][1] = ab[(gr + 8) * AS_STR];
            a[mt][2] = ab[gr * AS_STR + 4];
            a[mt][3] = ab[(gr + 8) * AS_STR + 4];
        }
#pragma unroll
        for (int nt = 0; nt < 4; nt++) {
            const uint32_t* bb = Bp + (ks * 8 + gc) * BS_STR + warpn * 32 + nt * 8 + gr;
            bq[nt][0] = bb[0];
            bq[nt][1] = bb[4 * BS_STR];
        }
#pragma unroll
        for (int mt = 0; mt < 2; mt++)
#pragma unroll
            for (int nt = 0; nt < 4; nt++)
                mma_tf32(c[mt][nt], a[mt], bq[nt][0], bq[nt][1]);
    }
}

// ---------------- fused QKVW projection + bf16 layout epilogues -----------
// grid (36, 16), block 256. blockIdx.y>>2 selects q/k/v/w.
__global__ void __launch_bounds__(256) tf32_proj4(
    const float* __restrict__ wq, const float* __restrict__ bq,
    const float* __restrict__ wk, const float* __restrict__ bk,
    const float* __restrict__ wv, const float* __restrict__ bv,
    const float* __restrict__ ww, const float* __restrict__ bw,
    const float* __restrict__ x)
{
    __shared__ uint32_t As[ASZ];
    __shared__ uint32_t Bs[BSZ];
    int tid = threadIdx.x, lane = tid & 31, wid = tid >> 5;
    int gr = lane >> 2, gc = lane & 3;
    int sel  = blockIdx.y >> 2;
    int row0 = (blockIdx.y & 3) * 64;
    const float* W    = sel == 0 ? wq : sel == 1 ? wk : sel == 2 ? wv : ww;
    const float* bias = sel == 0 ? bq : sel == 1 ? bk : sel == 2 ? bv : bw;
    int b = blockIdx.x / 18, hw0 = (blockIdx.x % 18) * 128;
    const float* Bb = x + (size_t)b * CC * HW + hw0;
    int warpm = wid >> 2, warpn = wid & 3;
    float c[2][4][4];
#pragma unroll
    for (int i = 0; i < 2; i++)
#pragma unroll
        for (int j = 0; j < 4; j++)
#pragma unroll
            for (int k = 0; k < 4; k++) c[i][j][k] = 0.f;

    for (int k0 = 0; k0 < 256; k0 += 32) {
#pragma unroll
        for (int i = 0; i < 2; i++) {
            int e = tid + i * 256;
            int r = e >> 3, k4 = (e & 7) * 4;
            float4 w4 = *(const float4*)(W + (size_t)(row0 + r) * 256 + k0 + k4);
            *(uint4*)(As + r * AS_STR + k4) = cvt4_tf32(w4);
        }
#pragma unroll
        for (int i = 0; i < 4; i++) {
            int e = tid + i * 256;
            int k = e >> 5, n4 = (e & 31) * 4;
            float4 v4 = *(const float4*)(Bb + (size_t)(k0 + k) * HW + n4);
            *(uint4*)(Bs + k * BS_STR + n4) = cvt4_tf32(v4);
        }
        __syncthreads();
        tf32_chunk(As, Bs, c, warpm, warpn, gr, gc);
        __syncthreads();
    }

    if (sel == 3) {                       // wf: fp32, [b][c][t]
#pragma unroll
        for (int mt = 0; mt < 2; mt++)
#pragma unroll
            for (int rh = 0; rh < 2; rh++) {
                int r = row0 + warpm * 32 + mt * 16 + rh * 8 + gr;
                float bv2 = bias[r];
#pragma unroll
                for (int nt = 0; nt < 4; nt++) {
                    int col = hw0 + warpn * 32 + nt * 8 + gc * 2;
                    size_t idx = (size_t)b * CC * HW + (size_t)r * HW + col;
                    *(float2*)(g_w + idx) = make_float2(c[mt][nt][rh * 2 + 0] + bv2,
                                                        c[mt][nt][rh * 2 + 1] + bv2);
                }
            }
    } else if (sel == 2) {                // v: bf16 packed, [bh][d][t]
#pragma unroll
        for (int mt = 0; mt < 2; mt++)
#pragma unroll
            for (int rh = 0; rh < 2; rh++) {
                int r = row0 + warpm * 32 + mt * 16 + rh * 8 + gr;
                float bv2 = bias[r];
#pragma unroll
                for (int nt = 0; nt < 4; nt++) {
                    int col = hw0 + warpn * 32 + nt * 8 + gc * 2;
                    size_t idx = (size_t)(b * 256 + r) * HW + col;
                    uint32_t pw = pack_bf16x2(c[mt][nt][rh * 2 + 1] + bv2,
                                              c[mt][nt][rh * 2 + 0] + bv2);
                    *(uint32_t*)(g_vh + idx) = pw;
                }
            }
    } else {                              // q/k: bf16 scatter into [bh][t][d]
        float scale = sel == 0 ? 0.17677669529663687f : 1.0f;
        __nv_bfloat16* dst = sel == 0 ? g_qh : g_kh;
#pragma unroll
        for (int mt = 0; mt < 2; mt++)
#pragma unroll
            for (int rh = 0; rh < 2; rh++) {
                int r = row0 + warpm * 32 + mt * 16 + rh * 8 + gr;
                float bv2 = bias[r];
                size_t hb = (size_t)(b * 8 + (r >> 5)) * HW;
                int d = r & 31;
#pragma unroll
                for (int nt = 0; nt < 4; nt++) {
                    int col = hw0 + warpn * 32 + nt * 8 + gc * 2;
                    float v0 = (c[mt][nt][rh * 2 + 0] + bv2) * scale;
                    float v1 = (c[mt][nt][rh * 2 + 1] + bv2) * scale;
                    dst[(hb + col)     * 32 + d] = __float2bfloat16(v0);
                    dst[(hb + col + 1) * 32 + d] = __float2bfloat16(v1);
                }
            }
    }
}

// ---------------- fused GSA scores + exp (split-tf32, fp32-accurate) ------
#define PAB_STR 68
__global__ void __launch_bounds__(256) pa_softmax()
{
    __shared__ uint32_t Ahi[32 * 36], Alo[32 * 36];
    __shared__ uint32_t Bhi[32 * PAB_STR], Blo[32 * PAB_STR];
    __shared__ float red[32 * 8];
    int tid = threadIdx.x, lane = tid & 31, wid = tid >> 5;
    int gr = lane >> 2, gc = lane & 3;
    int b = blockIdx.y, n0 = blockIdx.x * 32;
    const float* Mp = g_mn + (size_t)b * 64 * HW;
    const float* Np = Mp + (size_t)32 * HW;

    for (int e = tid; e < 1024; e += 256) {
        int ch = e >> 5, n = e & 31;
        float v = Mp[(size_t)ch * HW + n0 + n];
        uint32_t h = cvt_tf32(v);
        Ahi[n * 36 + ch] = h;
        Alo[n * 36 + ch] = cvt_tf32(v - __uint_as_float(h));
    }

    int bm = tid & 63, bc0 = tid >> 6;
    float rbv[8];
#pragma unroll
    for (int i = 0; i < 8; i++)
        rbv[i] = Np[(size_t)(bc0 + i * 4) * HW + bm];

    float rs[2][2] = {{0.f, 0.f}, {0.f, 0.f}};
    float* pab = g_pa + (size_t)b * HW * HW;
    __syncthreads();

    for (int t = 0; t < 36; t++) {
#pragma unroll
        for (int i = 0; i < 8; i++) {
            int ch = bc0 + i * 4;
            uint32_t h = cvt_tf32(rbv[i]);
            Bhi[ch * PAB_STR + bm] = h;
            Blo[ch * PAB_STR + bm] = cvt_tf32(rbv[i] - __uint_as_float(h));
        }
        __syncthreads();
        if (t + 1 < 36) {
#pragma unroll
            for (int i = 0; i < 8; i++)
                rbv[i] = Np[(size_t)(bc0 + i * 4) * HW + (t + 1) * 64 + bm];
        }
        float c[2][4];
#pragma unroll
        for (int mt = 0; mt < 2; mt++)
#pragma unroll
            for (int j = 0; j < 4; j++) c[mt][j] = 0.f;
#pragma unroll
        for (int ks = 0; ks < 4; ks++) {
            uint32_t ah[2][4], al[2][4];
#pragma unroll
            for (int mt = 0; mt < 2; mt++) {
                int rb = mt * 16;
                ah[mt][0] = Ahi[(rb + gr) * 36 + ks * 8 + gc];
                ah[mt][1] = Ahi[(rb + gr + 8) * 36 + ks * 8 + gc];
                ah[mt][2] = Ahi[(rb + gr) * 36 + ks * 8 + gc + 4];
                ah[mt][3] = Ahi[(rb + gr + 8) * 36 + ks * 8 + gc + 4];
                al[mt][0] = Alo[(rb + gr) * 36 + ks * 8 + gc];
                al[mt][1] = Alo[(rb + gr + 8) * 36 + ks * 8 + gc];
                al[mt][2] = Alo[(rb + gr) * 36 + ks * 8 + gc + 4];
                al[mt][3] = Alo[(rb + gr + 8) * 36 + ks * 8 + gc + 4];
            }
            int colb = wid * 8 + gr;
            uint32_t bh0 = Bhi[(ks * 8 + gc) * PAB_STR + colb];
            uint32_t bh1 = Bhi[(ks * 8 + gc + 4) * PAB_STR + colb];
            uint32_t bl0 = Blo[(ks * 8 + gc) * PAB_STR + colb];
            uint32_t bl1 = Blo[(ks * 8 + gc + 4) * PAB_STR + colb];
#pragma unroll
            for (int mt = 0; mt < 2; mt++) {
                mma_tf32(c[mt], ah[mt], bh0, bh1);
                mma_tf32(c[mt], ah[mt], bl0, bl1);
                mma_tf32(c[mt], al[mt], bh0, bh1);
            }
        }
        int m_base = t * 64 + wid * 8 + gc * 2;
#pragma unroll
        for (int mt = 0; mt < 2; mt++)
#pragma unroll
            for (int rh = 0; rh < 2; rh++) {
                float p0 = __expf(c[mt][rh * 2 + 0]);
                float p1 = __expf(c[mt][rh * 2 + 1]);
                rs[mt][rh] += p0 + p1;
                int n = n0 + mt * 16 + rh * 8 + gr;
                *(float2*)(pab + (size_t)n * HW + m_base) = make_float2(p0, p1);
            }
        __syncthreads();
    }

#pragma unroll
    for (int mt = 0; mt < 2; mt++)
#pragma unroll
        for (int rh = 0; rh < 2; rh++) {
            float v = rs[mt][rh];
            v += __shfl_xor_sync(0xffffffffu, v, 1);
            v += __shfl_xor_sync(0xffffffffu, v, 2);
            if (gc == 0) red[(mt * 16 + rh * 8 + gr) * 8 + wid] = v;
        }
    __syncthreads();
    if (tid < 32) {
        float s = 0.f;
#pragma unroll
        for (int w = 0; w < 8; w++) s += red[tid * 8 + w];
        g_l[(size_t)b * HW + n0 + tid] = s;
    }
}

// ---------------- double-buffered tf32 GSA: gsa = (wf @ pa^T) / l ---------
__global__ void __launch_bounds__(256) tf32_gsa()
{
    extern __shared__ uint32_t dsm[];
    uint32_t* As = dsm;
    uint32_t* Bs = dsm + 2 * ASZ;
    int tid = threadIdx.x, lane = tid & 31, wid = tid >> 5;
    int gr = lane >> 2, gc = lane & 3;
    int c0 = blockIdx.y * 64;
    int b = blockIdx.x / 18, n0 = (blockIdx.x % 18) * 128;
    const float* wfb = g_w + (size_t)b * CC * HW;
    const float* pab = g_pa + (size_t)b * HW * HW;
    int warpm = wid >> 2, warpn = wid & 3;

    int ar = tid >> 3, ak4 = (tid & 7) * 4;
    int ar2 = (tid + 256) >> 3;
    int bn = tid & 127, bk4_0 = (tid >> 7) * 4;

    float4 ra[2], rb[4];
#pragma unroll
    for (int i = 0; i < 2; i++) {
        int r = (i == 0) ? ar : ar2;
        ra[i] = *(const float4*)(wfb + (size_t)(c0 + r) * HW + 0 + ak4);
    }
#pragma unroll
    for (int i = 0; i < 4; i++)
        rb[i] = *(const float4*)(pab + (size_t)(n0 + bn) * HW + 0 + (bk4_0 + i * 8));
#pragma unroll
    for (int i = 0; i < 2; i++) {
        int r = (i == 0) ? ar : ar2;
        *(uint4*)(As + r * AS_STR + ak4) = cvt4_tf32(ra[i]);
    }
#pragma unroll
    for (int i = 0; i < 4; i++) {
        int k4 = bk4_0 + i * 8;
        Bs[(k4 + 0) * BS_STR + bn] = cvt_tf32(rb[i].x);
        Bs[(k4 + 1) * BS_STR + bn] = cvt_tf32(rb[i].y);
        Bs[(k4 + 2) * BS_STR + bn] = cvt_tf32(rb[i].z);
        Bs[(k4 + 3) * BS_STR + bn] = cvt_tf32(rb[i].w);
    }
    __syncthreads();

    float c[2][4][4];
#pragma unroll
    for (int i = 0; i < 2; i++)
#pragma unroll
        for (int j = 0; j < 4; j++)
#pragma unroll
            for (int k = 0; k < 4; k++) c[i][j][k] = 0.f;

    for (int it = 0; it < 72; it++) {
        int p = it & 1;
        int m1 = (it + 1) * 32;
        if (it + 1 < 72) {
#pragma unroll
            for (int i = 0; i < 2; i++) {
                int r = (i == 0) ? ar : ar2;
                ra[i] = *(const float4*)(wfb + (size_t)(c0 + r) * HW + m1 + ak4);
            }
#pragma unroll
            for (int i = 0; i < 4; i++)
                rb[i] = *(const float4*)(pab + (size_t)(n0 + bn) * HW + m1 + (bk4_0 + i * 8));
        }
        tf32_chunk(As + p * ASZ, Bs + p * BSZ, c, warpm, warpn, gr, gc);
        if (it + 1 < 72) {
            uint32_t* Ad = As + (p ^ 1) * ASZ;
            uint32_t* Bd = Bs + (p ^ 1) * BSZ;
#pragma unroll
            for (int i = 0; i < 2; i++) {
                int r = (i == 0) ? ar : ar2;
                *(uint4*)(Ad + r * AS_STR + ak4) = cvt4_tf32(ra[i]);
            }
#pragma unroll
            for (int i = 0; i < 4; i++) {
                int k4 = bk4_0 + i * 8;
                Bd[(k4 + 0) * BS_STR + bn] = cvt_tf32(rb[i].x);
                Bd[(k4 + 1) * BS_STR + bn] = cvt_tf32(rb[i].y);
                Bd[(k4 + 2) * BS_STR + bn] = cvt_tf32(rb[i].z);
                Bd[(k4 + 3) * BS_STR + bn] = cvt_tf32(rb[i].w);
            }
        }
        __syncthreads();
    }

    float inv[4][2];
#pragma unroll
    for (int nt = 0; nt < 4; nt++) {
        int col = n0 + warpn * 32 + nt * 8 + gc * 2;
        inv[nt][0] = 1.f / g_l[(size_t)b * HW + col];
        inv[nt][1] = 1.f / g_l[(size_t)b * HW + col + 1];
    }
    float* ob = g_gsa + (size_t)b * CC * HW;
#pragma unroll
    for (int mt = 0; mt < 2; mt++)
#pragma unroll
        for (int rh = 0; rh < 2; rh++) {
            int r = c0 + warpm * 32 + mt * 16 + rh * 8 + gr;
#pragma unroll
            for (int nt = 0; nt < 4; nt++) {
                int col = n0 + warpn * 32 + nt * 8 + gc * 2;
                *(float2*)(ob + (size_t)r * HW + col) =
                    make_float2(c[mt][nt][rh * 2 + 0] * inv[nt][0],
                                c[mt][nt][rh * 2 + 1] * inv[nt][1]);
            }
        }
}

// ---------------- double-buffered final GEMM + fusion epilogue ------------
__global__ void __launch_bounds__(256) tf32_final(
    const float* __restrict__ wo, const float* __restrict__ bo,
    const float* __restrict__ xin,
    const float* __restrict__ gt_p, const float* __restrict__ gg_p,
    float* __restrict__ out)
{
    extern __shared__ uint32_t dsm[];
    uint32_t* As = dsm;
    uint32_t* Bs = dsm + 2 * ASZ;
    int tid = threadIdx.x, lane = tid & 31, wid = tid >> 5;
    int gr = lane >> 2, gc = lane & 3;
    int row0 = blockIdx.y * 64;
    int b = blockIdx.x / 18, hw0 = (blockIdx.x % 18) * 128;
    const float* Bb = g_gsa + (size_t)b * CC * HW + hw0;
    int warpm = wid >> 2, warpn = wid & 3;

    int ar = tid >> 3, ak4 = (tid & 7) * 4;
    int ar2 = (tid + 256) >> 3;
    int bk = tid >> 5, bn4 = (tid & 31) * 4;

    float4 ra[2], rb[4];
#pragma unroll
    for (int i = 0; i < 2; i++) {
        int r = (i == 0) ? ar : ar2;
        ra[i] = *(const float4*)(wo + (size_t)(row0 + r) * 256 + 0 + ak4);
    }
#pragma unroll
    for (int i = 0; i < 4; i++)
        rb[i] = *(const float4*)(Bb + (size_t)(0 + bk + i * 8) * HW + bn4);
#pragma unroll
    for (int i = 0; i < 2; i++) {
        int r = (i == 0) ? ar : ar2;
        *(uint4*)(As + r * AS_STR + ak4) = cvt4_tf32(ra[i]);
    }
#pragma unroll
    for (int i = 0; i < 4; i++)
        *(uint4*)(Bs + (bk + i * 8) * BS_STR + bn4) = cvt4_tf32(rb[i]);
    __syncthreads();

    float c[2][4][4];
#pragma unroll
    for (int i = 0; i < 2; i++)
#pragma unroll
        for (int j = 0; j < 4; j++)
#pragma unroll
            for (int k = 0; k < 4; k++) c[i][j][k] = 0.f;

    for (int it = 0; it < 8; it++) {
        int p = it & 1;
        int k1 = (it + 1) * 32;
        if (it + 1 < 8) {
#pragma unroll
            for (int i = 0; i < 2; i++) {
                int r = (i == 0) ? ar : ar2;
                ra[i] = *(const float4*)(wo + (size_t)(row0 + r) * 256 + k1 + ak4);
            }
#pragma unroll
            for (int i = 0; i < 4; i++)
                rb[i] = *(const float4*)(Bb + (size_t)(k1 + bk + i * 8) * HW + bn4);
        }
        tf32_chunk(As + p * ASZ, Bs + p * BSZ, c, warpm, warpn, gr, gc);
        if (it + 1 < 8) {
            uint32_t* Ad = As + (p ^ 1) * ASZ;
            uint32_t* Bd = Bs + (p ^ 1) * BSZ;
#pragma unroll
            for (int i = 0; i < 2; i++) {
                int r = (i == 0) ? ar : ar2;
                *(uint4*)(Ad + r * AS_STR + ak4) = cvt4_tf32(ra[i]);
            }
#pragma unroll
            for (int i = 0; i < 4; i++)
                *(uint4*)(Bd + (bk + i * 8) * BS_STR + bn4) = cvt4_tf32(rb[i]);
        }
        __syncthreads();
    }

    float gt = gt_p[0], gg = gg_p[0];
#pragma unroll
    for (int mt = 0; mt < 2; mt++)
#pragma unroll
        for (int rh = 0; rh < 2; rh++) {
            int r = row0 + warpm * 32 + mt * 16 + rh * 8 + gr;
            float bv = bo[r];
#pragma unroll
            for (int nt = 0; nt < 4; nt++) {
                int col = hw0 + warpn * 32 + nt * 8 + gc * 2;
                size_t idx = (size_t)b * CC * HW + (size_t)r * HW + col;
                float2 x2 = *(const float2*)(xin + idx);
                float2 t2 = *(const float2*)(g_tsa + idx);
                float2 o2;
                o2.x = gt * t2.x + gg * (c[mt][nt][rh * 2 + 0] + bv) + x2.x;
                o2.y = gt * t2.y + gg * (c[mt][nt][rh * 2 + 1] + bv) + x2.y;
                *(float2*)(out + idx) = o2;
            }
        }
}

// ---------------- fp32 proj (m/n, concentration-sensitive) ----------------
__global__ void __launch_bounds__(256) proj_gemm(
    const float* __restrict__ W, const float* __restrict__ bias,
    const float* __restrict__ x, float* __restrict__ out, int Co)
{
    __shared__ float As[16][64];
    __shared__ float Bs[16][64];
    int jt  = blockIdx.x;
    int o0  = blockIdx.y * 64;
    int b   = (jt * 64) / HW;
    int hw0 = (jt * 64) % HW;
    const float* xb = x + (size_t)b * CC * HW + hw0;
    int tid = threadIdx.x;
    int tx = tid & 15, ty = tid >> 4;
    float acc[4][4];
#pragma unroll
    for (int i = 0; i < 4; i++)
#pragma unroll
        for (int j = 0; j < 4; j++) acc[i][j] = 0.f;

    int lo  = tid >> 2;
    int lk4 = (tid & 3) * 4;
    int bk  = tid >> 4;
    int bj4 = (tid & 15) * 4;

    for (int k0 = 0; k0 < CC; k0 += 16) {
        float4 wv = make_float4(0.f, 0.f, 0.f, 0.f);
        if (o0 + lo < Co)
            wv = *(const float4*)(W + (size_t)(o0 + lo) * CC + k0 + lk4);
        As[lk4 + 0][lo] = wv.x; As[lk4 + 1][lo] = wv.y;
        As[lk4 + 2][lo] = wv.z; As[lk4 + 3][lo] = wv.w;
        float4 xv = *(const float4*)(xb + (size_t)(k0 + bk) * HW + bj4);
        *(float4*)&Bs[bk][bj4] = xv;
        __syncthreads();
#pragma unroll
        for (int k = 0; k < 16; k++) {
            float4 a  = *(float4*)&As[k][ty * 4];
            float4 bb = *(float4*)&Bs[k][tx * 4];
            float av[4] = {a.x, a.y, a.z, a.w};
            float bv[4] = {bb.x, bb.y, bb.z, bb.w};
#pragma unroll
            for (int i = 0; i < 4; i++)
#pragma unroll
                for (int j = 0; j < 4; j++)
                    acc[i][j] = fmaf(av[i], bv[j], acc[i][j]);
        }
        __syncthreads();
    }
#pragma unroll
    for (int i = 0; i < 4; i++) {
        int o = o0 + ty * 4 + i;
        if (o < Co) {
            float bsv = bias[o];
            float4 ov = make_float4(acc[i][0] + bsv, acc[i][1] + bsv,
                                    acc[i][2] + bsv, acc[i][3] + bsv);
            *(float4*)(out + (size_t)b * Co * HW + (size_t)o * HW + hw0 + tx * 4) = ov;
        }
    }
}

__global__ void __launch_bounds__(256) concat_mn(
    const float* __restrict__ wm, const float* __restrict__ bm,
    const float* __restrict__ wn, const float* __restrict__ bn)
{
    int i = blockIdx.x * 256 + threadIdx.x;
    if (i < 32 * 256) { g_wmn[i] = wm[i]; g_wmn[32 * 256 + i] = wn[i]; }
    if (i < 32) { g_bmn[i] = bm[i]; g_bmn[32 + i] = bn[i]; }
}

// ---------------- FA2-style flash TSA with mma.sync bf16 ----------------
#define QS_STR 40
#define VS_STR 136
__global__ void __launch_bounds__(256) flash_mma()
{
    __shared__ __nv_bfloat16 Qs[128 * QS_STR];
    __shared__ __nv_bfloat16 Ks[128 * QS_STR];
    __shared__ __nv_bfloat16 Vs[32 * VS_STR];
    int tid = threadIdx.x, wid = tid >> 5, lane = tid & 31;
    int bh = blockIdx.y, i0 = blockIdx.x * 128;
    int gr = lane >> 2, gc = (lane & 3) * 2;

    const __nv_bfloat16* qsrc = g_qh + ((size_t)bh * HW + i0) * DK;
    const __nv_bfloat16* ksrc = g_kh + (size_t)bh * HW * DK;
    const __nv_bfloat16* vsrc = g_vh + (size_t)bh * DK * HW;

    for (int e = tid; e < 512; e += 256) {
        int r = e >> 2, c8 = (e & 3) * 8;
        *(uint4*)(Qs + r * QS_STR + c8) = *(const uint4*)(qsrc + r * DK + c8);
    }
    __syncthreads();

    uint32_t qa[2][4];
    {
        const __nv_bfloat16* qb = Qs + (wid * 16 + gr) * QS_STR;
#pragma unroll
        for (int kc = 0; kc < 2; kc++) {
            qa[kc][0] = *(const uint32_t*)(qb + kc * 16 + gc);
            qa[kc][1] = *(const uint32_t*)(qb + 8 * QS_STR + kc * 16 + gc);
            qa[kc][2] = *(const uint32_t*)(qb + kc * 16 + gc + 8);
            qa[kc][3] = *(const uint32_t*)(qb + 8 * QS_STR + kc * 16 + gc + 8);
        }
    }

    float o[4][4];
#pragma unroll
    for (int i = 0; i < 4; i++)
#pragma unroll
        for (int j = 0; j < 4; j++) o[i][j] = 0.f;
    float l0 = 0.f, l1 = 0.f;

    for (int kt = 0; kt < 18; kt++) {
        int j0 = kt * 128;
        __syncthreads();
        for (int e = tid; e < 512; e += 256) {
            int r = e >> 2, c8 = (e & 3) * 8;
            *(uint4*)(Ks + r * QS_STR + c8) = *(const uint4*)(ksrc + (size_t)(j0 + r) * DK + c8);
        }
        for (int e = tid; e < 512; e += 256) {
            int d = e >> 4, c8 = (e & 15) * 8;
            *(uint4*)(Vs + d * VS_STR + c8) = *(const uint4*)(vsrc + (size_t)d * HW + j0 + c8);
        }
        __syncthreads();

        float s[16][4];
#pragma unroll
        for (int nt = 0; nt < 16; nt++) {
            s[nt][0] = 0.f; s[nt][1] = 0.f; s[nt][2] = 0.f; s[nt][3] = 0.f;
            const __nv_bfloat16* kb = Ks + (nt * 8 + gr) * QS_STR;
#pragma unroll
            for (int kc = 0; kc < 2; kc++) {
                uint32_t b0 = *(const uint32_t*)(kb + kc * 16 + gc);
                uint32_t b1 = *(const uint32_t*)(kb + kc * 16 + gc + 8);
                mma16816(s[nt], qa[kc], b0, b1);
            }
        }

        // exp split 6:2 across MUFU and FMA pipes (the single change vs R6)
        uint32_t pa_[8][4];
#pragma unroll
        for (int h2 = 0; h2 < 8; h2++) {
            float e00 = __expf(s[2 * h2][0]),     e01 = __expf(s[2 * h2][1]);
            float e02 = __expf(s[2 * h2][2]),     e03 = fexp(s[2 * h2][3]);
            float f00 = __expf(s[2 * h2 + 1][0]), f01 = __expf(s[2 * h2 + 1][1]);
            float f02 = __expf(s[2 * h2 + 1][2]), f03 = fexp(s[2 * h2 + 1][3]);
            l0 += (e00 + e01) + (f00 + f01);
            l1 += (e02 + e03) + (f02 + f03);
            pa_[h2][0] = pack_bf16x2(e01, e00);
            pa_[h2][1] = pack_bf16x2(e03, e02);
            pa_[h2][2] = pack_bf16x2(f01, f00);
            pa_[h2][3] = pack_bf16x2(f03, f02);
        }

#pragma unroll
        for (int kc2 = 0; kc2 < 8; kc2++) {
#pragma unroll
            for (int dt = 0; dt < 4; dt++) {
                const __nv_bfloat16* vb = Vs + (dt * 8 + gr) * VS_STR + kc2 * 16 + gc;
                uint32_t b0 = *(const uint32_t*)(vb);
                uint32_t b1 = *(const uint32_t*)(vb + 8);
                mma16816(o[dt], pa_[kc2], b0, b1);
            }
        }
    }

    l0 += __shfl_xor_sync(0xffffffffu, l0, 1);
    l0 += __shfl_xor_sync(0xffffffffu, l0, 2);
    l1 += __shfl_xor_sync(0xffffffffu, l1, 1);
    l1 += __shfl_xor_sync(0xffffffffu, l1, 2);
    float inv0 = 1.f / l0, inv1 = 1.f / l1;

    int b = bh >> 3, h = bh & 7;
    float* ob = g_tsa + ((size_t)b * CC + h * DK) * HW;
    int tok0 = i0 + wid * 16 + gr;
#pragma unroll
    for (int dt = 0; dt < 4; dt++) {
        int d = dt * 8 + gc;
        ob[(size_t)(d)     * HW + tok0]     = o[dt][0] * inv0;
        ob[(size_t)(d + 1) * HW + tok0]     = o[dt][1] * inv0;
        ob[(size_t)(d)     * HW + tok0 + 8] = o[dt][2] * inv1;
        ob[(size_t)(d + 1) * HW + tok0 + 8] = o[dt][3] * inv1;
    }
}

// ---------------- launch ----------------
extern "C" void kernel_launch(void* const* d_in, const int* in_sizes, int n_in,
                              void* d_out, int out_size)
{
    const float* x   = (const float*)d_in[0];
    const float* wq  = (const float*)d_in[1];
    const float* bq  = (const float*)d_in[2];
    const float* wk  = (const float*)d_in[3];
    const float* bk  = (const float*)d_in[4];
    const float* wv  = (const float*)d_in[5];
    const float* bv  = (const float*)d_in[6];
    const float* wm  = (const float*)d_in[7];
    const float* bm  = (const float*)d_in[8];
    const float* wn  = (const float*)d_in[9];
    const float* bn  = (const float*)d_in[10];
    const float* ww  = (const float*)d_in[11];
    const float* bw  = (const float*)d_in[12];
    const float* wo  = (const float*)d_in[13];
    const float* bo  = (const float*)d_in[14];
    const float* gts = (const float*)d_in[15];
    const float* ggs = (const float*)d_in[16];
    float* out = (float*)d_out;

    float *pmn, *pwmn, *pbmn;
    cudaGetSymbolAddress((void**)&pmn, g_mn);
    cudaGetSymbolAddress((void**)&pwmn, g_wmn);
    cudaGetSymbolAddress((void**)&pbmn, g_bmn);

    static int smem_set = 0;
    const int DBUF_SMEM = (2 * ASZ + 2 * BSZ) * 4;   // 53248 B
    if (!smem_set) {
        cudaFuncSetAttribute(tf32_gsa, cudaFuncAttributeMaxDynamicSharedMemorySize, DBUF_SMEM);
        cudaFuncSetAttribute(tf32_final, cudaFuncAttributeMaxDynamicSharedMemorySize, DBUF_SMEM);
        smem_set = 1;
    }

    dim3 blk(256);

    concat_mn<<<32, blk>>>(wm, bm, wn, bn);

    tf32_proj4<<<dim3(36, 16), blk>>>(wq, bq, wk, bk, wv, bv, ww, bw, x);
    proj_gemm<<<dim3(BB * HW / 64, 1), blk>>>(pwmn, pbmn, x, pmn, 64);

    flash_mma<<<dim3(HW / 128, BB * HEADS), blk>>>();

    pa_softmax<<<dim3(HW / 32, BB), blk>>>();
    tf32_gsa<<<dim3(36, 4), blk, DBUF_SMEM>>>();

    tf32_final<<<dim3(36, 4), blk, DBUF_SMEM>>>(wo, bo, x, gts, ggs, out);
}

// round 10
// speedup vs baseline: 1.0536x; 1.0162x over previous
#include <cuda_runtime.h>
#include <cuda_bf16.h>
#include <cstdint>

#define BB    2
#define CC    256
#define HW    2304
#define HEADS 8
#define DK    32
#define CR    32
#define NCH   (BB*CC*HW)

// ---------------- scratch (device globals; no allocation) ----------------
__device__ float g_w[NCH];              // wf projection (fp32)
__device__ float g_mn[BB*64*HW];        // m (rows 0-31) and n (rows 32-63)
__device__ float g_wmn[64*256];
__device__ float g_bmn[64];
__device__ float g_tsa[NCH];
__device__ float g_gsa[NCH];
__device__ float g_l[BB*HW];            // GSA softmax row sums
__device__ float g_pa[(size_t)BB*HW*HW]; // unnormalized exp(scores), 42.5 MB
__device__ __nv_bfloat16 g_qh[NCH];     // [bh][t][d], pre-scaled
__device__ __nv_bfloat16 g_kh[NCH];     // [bh][t][d]
__device__ __nv_bfloat16 g_vh[NCH];     // [bh][d][t]

// ---------------- fast exp on the FMA pipe ----------------
__device__ __forceinline__ float fexp(float x) {
    float t = x * 1.4426950408889634f;
    t = fmaxf(t, -126.0f);
    float r = t + 12582912.0f;
    int   ii = __float_as_int(r) - 0x4B400000;
    float fi = r - 12582912.0f;
    float f  = t - fi;
    float p  = 1.3333558e-3f;
    p = fmaf(p, f, 9.6181291e-3f);
    p = fmaf(p, f, 5.5504109e-2f);
    p = fmaf(p, f, 2.4022651e-1f);
    p = fmaf(p, f, 6.9314718e-1f);
    p = fmaf(p, f, 1.0f);
    return __int_as_float(__float_as_int(p) + (ii << 23));
}

// ---------------- mma helpers ----------------
__device__ __forceinline__ void mma16816(float* c, const uint32_t* a, uint32_t b0, uint32_t b1) {
    asm volatile(
        "mma.sync.aligned.m16n8k16.row.col.f32.bf16.bf16.f32 "
        "{%0,%1,%2,%3}, {%4,%5,%6,%7}, {%8,%9}, {%0,%1,%2,%3};"
        : "+f"(c[0]), "+f"(c[1]), "+f"(c[2]), "+f"(c[3])
        : "r"(a[0]), "r"(a[1]), "r"(a[2]), "r"(a[3]), "r"(b0), "r"(b1));
}
__device__ __forceinline__ void mma_tf32(float* c, const uint32_t* a, uint32_t b0, uint32_t b1) {
    asm volatile(
        "mma.sync.aligned.m16n8k8.row.col.f32.tf32.tf32.f32 "
        "{%0,%1,%2,%3}, {%4,%5,%6,%7}, {%8,%9}, {%0,%1,%2,%3};"
        : "+f"(c[0]), "+f"(c[1]), "+f"(c[2]), "+f"(c[3])
        : "r"(a[0]), "r"(a[1]), "r"(a[2]), "r"(a[3]), "r"(b0), "r"(b1));
}
__device__ __forceinline__ uint32_t pack_bf16x2(float hi, float lo) {
    uint32_t w;
    asm("cvt.rn.satfinite.bf16x2.f32 %0, %1, %2;" : "=r"(w) : "f"(hi), "f"(lo));
    return w;
}
__device__ __forceinline__ uint32_t cvt_tf32(float f) {
    uint32_t r;
    asm("cvt.rna.tf32.f32 %0, %1;" : "=r"(r) : "f"(f));
    return r;
}
__device__ __forceinline__ uint4 cvt4_tf32(float4 v) {
    uint4 o;
    o.x = cvt_tf32(v.x); o.y = cvt_tf32(v.y); o.z = cvt_tf32(v.z); o.w = cvt_tf32(v.w);
    return o;
}

#define AS_STR 36
#define BS_STR 136
#define ASZ (64 * AS_STR)
#define BSZ (32 * BS_STR)

__device__ __forceinline__ void tf32_chunk(
    const uint32_t* Ap, const uint32_t* Bp, float c[2][4][4],
    int warpm, int warpn, int gr, int gc)
{
#pragma unroll
    for (int ks = 0; ks < 4; ks++) {
        uint32_t a[2][4], bq[4][2];
#pragma unroll
        for (int mt = 0; mt < 2; mt++) {
            const uint32_t* ab = Ap + (warpm * 32 + mt * 16) * AS_STR + ks * 8 + gc;
            a[mt][0] = ab[gr * AS_STR];
            a[mt][1] = ab[(gr + 8) * AS_STR];
            a[mt][2] = ab[gr * AS_STR + 4];
            a[mt][3] = ab[(gr + 8) * AS_STR + 4];
        }
#pragma unroll
        for (int nt = 0; nt < 4; nt++) {
            const uint32_t* bb = Bp + (ks * 8 + gc) * BS_STR + warpn * 32 + nt * 8 + gr;
            bq[nt][0] = bb[0];
            bq[nt][1] = bb[4 * BS_STR];
        }
#pragma unroll
        for (int mt = 0; mt < 2; mt++)
#pragma unroll
            for (int nt = 0; nt < 4; nt++)
                mma_tf32(c[mt][nt], a[mt], bq[nt][0], bq[nt][1]);
    }
}

// ---------------- fused QKVW projection + bf16 layout epilogues -----------
__global__ void __launch_bounds__(256) tf32_proj4(
    const float* __restrict__ wq, const float* __restrict__ bq,
    const float* __restrict__ wk, const float* __restrict__ bk,
    const float* __restrict__ wv, const float* __restrict__ bv,
    const float* __restrict__ ww, const float* __restrict__ bw,
    const float* __restrict__ x)
{
    __shared__ uint32_t As[ASZ];
    __shared__ uint32_t Bs[BSZ];
    int tid = threadIdx.x, lane = tid & 31, wid = tid >> 5;
    int gr = lane >> 2, gc = lane & 3;
    int sel  = blockIdx.y >> 2;
    int row0 = (blockIdx.y & 3) * 64;
    const float* W    = sel == 0 ? wq : sel == 1 ? wk : sel == 2 ? wv : ww;
    const float* bias = sel == 0 ? bq : sel == 1 ? bk : sel == 2 ? bv : bw;
    int b = blockIdx.x / 18, hw0 = (blockIdx.x % 18) * 128;
    const float* Bb = x + (size_t)b * CC * HW + hw0;
    int warpm = wid >> 2, warpn = wid & 3;
    float c[2][4][4];
#pragma unroll
    for (int i = 0; i < 2; i++)
#pragma unroll
        for (int j = 0; j < 4; j++)
#pragma unroll
            for (int k = 0; k < 4; k++) c[i][j][k] = 0.f;

    for (int k0 = 0; k0 < 256; k0 += 32) {
#pragma unroll
        for (int i = 0; i < 2; i++) {
            int e = tid + i * 256;
            int r = e >> 3, k4 = (e & 7) * 4;
            float4 w4 = *(const float4*)(W + (size_t)(row0 + r) * 256 + k0 + k4);
            *(uint4*)(As + r * AS_STR + k4) = cvt4_tf32(w4);
        }
#pragma unroll
        for (int i = 0; i < 4; i++) {
            int e = tid + i * 256;
            int k = e >> 5, n4 = (e & 31) * 4;
            float4 v4 = *(const float4*)(Bb + (size_t)(k0 + k) * HW + n4);
            *(uint4*)(Bs + k * BS_STR + n4) = cvt4_tf32(v4);
        }
        __syncthreads();
        tf32_chunk(As, Bs, c, warpm, warpn, gr, gc);
        __syncthreads();
    }

    if (sel == 3) {                       // wf: fp32, [b][c][t]
#pragma unroll
        for (int mt = 0; mt < 2; mt++)
#pragma unroll
            for (int rh = 0; rh < 2; rh++) {
                int r = row0 + warpm * 32 + mt * 16 + rh * 8 + gr;
                float bv2 = bias[r];
#pragma unroll
                for (int nt = 0; nt < 4; nt++) {
                    int col = hw0 + warpn * 32 + nt * 8 + gc * 2;
                    size_t idx = (size_t)b * CC * HW + (size_t)r * HW + col;
                    *(float2*)(g_w + idx) = make_float2(c[mt][nt][rh * 2 + 0] + bv2,
                                                        c[mt][nt][rh * 2 + 1] + bv2);
                }
            }
    } else if (sel == 2) {                // v: bf16 packed, [bh][d][t]
#pragma unroll
        for (int mt = 0; mt < 2; mt++)
#pragma unroll
            for (int rh = 0; rh < 2; rh++) {
                int r = row0 + warpm * 32 + mt * 16 + rh * 8 + gr;
                float bv2 = bias[r];
#pragma unroll
                for (int nt = 0; nt < 4; nt++) {
                    int col = hw0 + warpn * 32 + nt * 8 + gc * 2;
                    size_t idx = (size_t)(b * 256 + r) * HW + col;
                    uint32_t pw = pack_bf16x2(c[mt][nt][rh * 2 + 1] + bv2,
                                              c[mt][nt][rh * 2 + 0] + bv2);
                    *(uint32_t*)(g_vh + idx) = pw;
                }
            }
    } else {                              // q/k: bf16 scatter into [bh][t][d]
        float scale = sel == 0 ? 0.17677669529663687f : 1.0f;
        __nv_bfloat16* dst = sel == 0 ? g_qh : g_kh;
#pragma unroll
        for (int mt = 0; mt < 2; mt++)
#pragma unroll
            for (int rh = 0; rh < 2; rh++) {
                int r = row0 + warpm * 32 + mt * 16 + rh * 8 + gr;
                float bv2 = bias[r];
                size_t hb = (size_t)(b * 8 + (r >> 5)) * HW;
                int d = r & 31;
#pragma unroll
                for (int nt = 0; nt < 4; nt++) {
                    int col = hw0 + warpn * 32 + nt * 8 + gc * 2;
                    float v0 = (c[mt][nt][rh * 2 + 0] + bv2) * scale;
                    float v1 = (c[mt][nt][rh * 2 + 1] + bv2) * scale;
                    dst[(hb + col)     * 32 + d] = __float2bfloat16(v0);
                    dst[(hb + col + 1) * 32 + d] = __float2bfloat16(v1);
                }
            }
    }
}

// ---------------- fused GSA scores + exp (split-tf32, fp32-accurate) ------
#define PAB_STR 68
__global__ void __launch_bounds__(256) pa_softmax()
{
    __shared__ uint32_t Ahi[32 * 36], Alo[32 * 36];
    __shared__ uint32_t Bhi[32 * PAB_STR], Blo[32 * PAB_STR];
    __shared__ float red[32 * 8];
    int tid = threadIdx.x, lane = tid & 31, wid = tid >> 5;
    int gr = lane >> 2, gc = lane & 3;
    int b = blockIdx.y, n0 = blockIdx.x * 32;
    const float* Mp = g_mn + (size_t)b * 64 * HW;
    const float* Np = Mp + (size_t)32 * HW;

    for (int e = tid; e < 1024; e += 256) {
        int ch = e >> 5, n = e & 31;
        float v = Mp[(size_t)ch * HW + n0 + n];
        uint32_t h = cvt_tf32(v);
        Ahi[n * 36 + ch] = h;
        Alo[n * 36 + ch] = cvt_tf32(v - __uint_as_float(h));
    }

    int bm = tid & 63, bc0 = tid >> 6;
    float rbv[8];
#pragma unroll
    for (int i = 0; i < 8; i++)
        rbv[i] = Np[(size_t)(bc0 + i * 4) * HW + bm];

    float rs[2][2] = {{0.f, 0.f}, {0.f, 0.f}};
    float* pab = g_pa + (size_t)b * HW * HW;
    __syncthreads();

    for (int t = 0; t < 36; t++) {
#pragma unroll
        for (int i = 0; i < 8; i++) {
            int ch = bc0 + i * 4;
            uint32_t h = cvt_tf32(rbv[i]);
            Bhi[ch * PAB_STR + bm] = h;
            Blo[ch * PAB_STR + bm] = cvt_tf32(rbv[i] - __uint_as_float(h));
        }
        __syncthreads();
        if (t + 1 < 36) {
#pragma unroll
            for (int i = 0; i < 8; i++)
                rbv[i] = Np[(size_t)(bc0 + i * 4) * HW + (t + 1) * 64 + bm];
        }
        float c[2][4];
#pragma unroll
        for (int mt = 0; mt < 2; mt++)
#pragma unroll
            for (int j = 0; j < 4; j++) c[mt][j] = 0.f;
#pragma unroll
        for (int ks = 0; ks < 4; ks++) {
            uint32_t ah[2][4], al[2][4];
#pragma unroll
            for (int mt = 0; mt < 2; mt++) {
                int rb = mt * 16;
                ah[mt][0] = Ahi[(rb + gr) * 36 + ks * 8 + gc];
                ah[mt][1] = Ahi[(rb + gr + 8) * 36 + ks * 8 + gc];
                ah[mt][2] = Ahi[(rb + gr) * 36 + ks * 8 + gc + 4];
                ah[mt][3] = Ahi[(rb + gr + 8) * 36 + ks * 8 + gc + 4];
                al[mt][0] = Alo[(rb + gr) * 36 + ks * 8 + gc];
                al[mt][1] = Alo[(rb + gr + 8) * 36 + ks * 8 + gc];
                al[mt][2] = Alo[(rb + gr) * 36 + ks * 8 + gc + 4];
                al[mt][3] = Alo[(rb + gr + 8) * 36 + ks * 8 + gc + 4];
            }
            int colb = wid * 8 + gr;
            uint32_t bh0 = Bhi[(ks * 8 + gc) * PAB_STR + colb];
            uint32_t bh1 = Bhi[(ks * 8 + gc + 4) * PAB_STR + colb];
            uint32_t bl0 = Blo[(ks * 8 + gc) * PAB_STR + colb];
            uint32_t bl1 = Blo[(ks * 8 + gc + 4) * PAB_STR + colb];
#pragma unroll
            for (int mt = 0; mt < 2; mt++) {
                mma_tf32(c[mt], ah[mt], bh0, bh1);
                mma_tf32(c[mt], ah[mt], bl0, bl1);
                mma_tf32(c[mt], al[mt], bh0, bh1);
            }
        }
        int m_base = t * 64 + wid * 8 + gc * 2;
#pragma unroll
        for (int mt = 0; mt < 2; mt++)
#pragma unroll
            for (int rh = 0; rh < 2; rh++) {
                float p0 = __expf(c[mt][rh * 2 + 0]);
                float p1 = __expf(c[mt][rh * 2 + 1]);
                rs[mt][rh] += p0 + p1;
                int n = n0 + mt * 16 + rh * 8 + gr;
                *(float2*)(pab + (size_t)n * HW + m_base) = make_float2(p0, p1);
            }
        __syncthreads();
    }

#pragma unroll
    for (int mt = 0; mt < 2; mt++)
#pragma unroll
        for (int rh = 0; rh < 2; rh++) {
            float v = rs[mt][rh];
            v += __shfl_xor_sync(0xffffffffu, v, 1);
            v += __shfl_xor_sync(0xffffffffu, v, 2);
            if (gc == 0) red[(mt * 16 + rh * 8 + gr) * 8 + wid] = v;
        }
    __syncthreads();
    if (tid < 32) {
        float s = 0.f;
#pragma unroll
        for (int w = 0; w < 8; w++) s += red[tid * 8 + w];
        g_l[(size_t)b * HW + n0 + tid] = s;
    }
}

// ---------------- double-buffered tf32 GSA: gsa = (wf @ pa^T) / l ---------
__global__ void __launch_bounds__(256) tf32_gsa()
{
    extern __shared__ uint32_t dsm[];
    uint32_t* As = dsm;
    uint32_t* Bs = dsm + 2 * ASZ;
    int tid = threadIdx.x, lane = tid & 31, wid = tid >> 5;
    int gr = lane >> 2, gc = lane & 3;
    int c0 = blockIdx.y * 64;
    int b = blockIdx.x / 18, n0 = (blockIdx.x % 18) * 128;
    const float* wfb = g_w + (size_t)b * CC * HW;
    const float* pab = g_pa + (size_t)b * HW * HW;
    int warpm = wid >> 2, warpn = wid & 3;

    int ar = tid >> 3, ak4 = (tid & 7) * 4;
    int ar2 = (tid + 256) >> 3;
    int bn = tid & 127, bk4_0 = (tid >> 7) * 4;

    float4 ra[2], rb[4];
#pragma unroll
    for (int i = 0; i < 2; i++) {
        int r = (i == 0) ? ar : ar2;
        ra[i] = *(const float4*)(wfb + (size_t)(c0 + r) * HW + 0 + ak4);
    }
#pragma unroll
    for (int i = 0; i < 4; i++)
        rb[i] = *(const float4*)(pab + (size_t)(n0 + bn) * HW + 0 + (bk4_0 + i * 8));
#pragma unroll
    for (int i = 0; i < 2; i++) {
        int r = (i == 0) ? ar : ar2;
        *(uint4*)(As + r * AS_STR + ak4) = cvt4_tf32(ra[i]);
    }
#pragma unroll
    for (int i = 0; i < 4; i++) {
        int k4 = bk4_0 + i * 8;
        Bs[(k4 + 0) * BS_STR + bn] = cvt_tf32(rb[i].x);
        Bs[(k4 + 1) * BS_STR + bn] = cvt_tf32(rb[i].y);
        Bs[(k4 + 2) * BS_STR + bn] = cvt_tf32(rb[i].z);
        Bs[(k4 + 3) * BS_STR + bn] = cvt_tf32(rb[i].w);
    }
    __syncthreads();

    float c[2][4][4];
#pragma unroll
    for (int i = 0; i < 2; i++)
#pragma unroll
        for (int j = 0; j < 4; j++)
#pragma unroll
            for (int k = 0; k < 4; k++) c[i][j][k] = 0.f;

    for (int it = 0; it < 72; it++) {
        int p = it & 1;
        int m1 = (it + 1) * 32;
        if (it + 1 < 72) {
#pragma unroll
            for (int i = 0; i < 2; i++) {
                int r = (i == 0) ? ar : ar2;
                ra[i] = *(const float4*)(wfb + (size_t)(c0 + r) * HW + m1 + ak4);
            }
#pragma unroll
            for (int i = 0; i < 4; i++)
                rb[i] = *(const float4*)(pab + (size_t)(n0 + bn) * HW + m1 + (bk4_0 + i * 8));
        }
        tf32_chunk(As + p * ASZ, Bs + p * BSZ, c, warpm, warpn, gr, gc);
        if (it + 1 < 72) {
            uint32_t* Ad = As + (p ^ 1) * ASZ;
            uint32_t* Bd = Bs + (p ^ 1) * BSZ;
#pragma unroll
            for (int i = 0; i < 2; i++) {
                int r = (i == 0) ? ar : ar2;
                *(uint4*)(Ad + r * AS_STR + ak4) = cvt4_tf32(ra[i]);
            }
#pragma unroll
            for (int i = 0; i < 4; i++) {
                int k4 = bk4_0 + i * 8;
                Bd[(k4 + 0) * BS_STR + bn] = cvt_tf32(rb[i].x);
                Bd[(k4 + 1) * BS_STR + bn] = cvt_tf32(rb[i].y);
                Bd[(k4 + 2) * BS_STR + bn] = cvt_tf32(rb[i].z);
                Bd[(k4 + 3) * BS_STR + bn] = cvt_tf32(rb[i].w);
            }
        }
        __syncthreads();
    }

    float inv[4][2];
#pragma unroll
    for (int nt = 0; nt < 4; nt++) {
        int col = n0 + warpn * 32 + nt * 8 + gc * 2;
        inv[nt][0] = 1.f / g_l[(size_t)b * HW + col];
        inv[nt][1] = 1.f / g_l[(size_t)b * HW + col + 1];
    }
    float* ob = g_gsa + (size_t)b * CC * HW;
#pragma unroll
    for (int mt = 0; mt < 2; mt++)
#pragma unroll
        for (int rh = 0; rh < 2; rh++) {
            int r = c0 + warpm * 32 + mt * 16 + rh * 8 + gr;
#pragma unroll
            for (int nt = 0; nt < 4; nt++) {
                int col = n0 + warpn * 32 + nt * 8 + gc * 2;
                *(float2*)(ob + (size_t)r * HW + col) =
                    make_float2(c[mt][nt][rh * 2 + 0] * inv[nt][0],
                                c[mt][nt][rh * 2 + 1] * inv[nt][1]);
            }
        }
}

// ---------------- double-buffered final GEMM + fusion epilogue ------------
__global__ void __launch_bounds__(256) tf32_final(
    const float* __restrict__ wo, const float* __restrict__ bo,
    const float* __restrict__ xin,
    const float* __restrict__ gt_p, const float* __restrict__ gg_p,
    float* __restrict__ out)
{
    extern __shared__ uint32_t dsm[];
    uint32_t* As = dsm;
    uint32_t* Bs = dsm + 2 * ASZ;
    int tid = threadIdx.x, lane = tid & 31, wid = tid >> 5;
    int gr = lane >> 2, gc = lane & 3;
    int row0 = blockIdx.y * 64;
    int b = blockIdx.x / 18, hw0 = (blockIdx.x % 18) * 128;
    const float* Bb = g_gsa + (size_t)b * CC * HW + hw0;
    int warpm = wid >> 2, warpn = wid & 3;

    int ar = tid >> 3, ak4 = (tid & 7) * 4;
    int ar2 = (tid + 256) >> 3;
    int bk = tid >> 5, bn4 = (tid & 31) * 4;

    float4 ra[2], rb[4];
#pragma unroll
    for (int i = 0; i < 2; i++) {
        int r = (i == 0) ? ar : ar2;
        ra[i] = *(const float4*)(wo + (size_t)(row0 + r) * 256 + 0 + ak4);
    }
#pragma unroll
    for (int i = 0; i < 4; i++)
        rb[i] = *(const float4*)(Bb + (size_t)(0 + bk + i * 8) * HW + bn4);
#pragma unroll
    for (int i = 0; i < 2; i++) {
        int r = (i == 0) ? ar : ar2;
        *(uint4*)(As + r * AS_STR + ak4) = cvt4_tf32(ra[i]);
    }
#pragma unroll
    for (int i = 0; i < 4; i++)
        *(uint4*)(Bs + (bk + i * 8) * BS_STR + bn4) = cvt4_tf32(rb[i]);
    __syncthreads();

    float c[2][4][4];
#pragma unroll
    for (int i = 0; i < 2; i++)
#pragma unroll
        for (int j = 0; j < 4; j++)
#pragma unroll
            for (int k = 0; k < 4; k++) c[i][j][k] = 0.f;

    for (int it = 0; it < 8; it++) {
        int p = it & 1;
        int k1 = (it + 1) * 32;
        if (it + 1 < 8) {
#pragma unroll
            for (int i = 0; i < 2; i++) {
                int r = (i == 0) ? ar : ar2;
                ra[i] = *(const float4*)(wo + (size_t)(row0 + r) * 256 + k1 + ak4);
            }
#pragma unroll
            for (int i = 0; i < 4; i++)
                rb[i] = *(const float4*)(Bb + (size_t)(k1 + bk + i * 8) * HW + bn4);
        }
        tf32_chunk(As + p * ASZ, Bs + p * BSZ, c, warpm, warpn, gr, gc);
        if (it + 1 < 8) {
            uint32_t* Ad = As + (p ^ 1) * ASZ;
            uint32_t* Bd = Bs + (p ^ 1) * BSZ;
#pragma unroll
            for (int i = 0; i < 2; i++) {
                int r = (i == 0) ? ar : ar2;
                *(uint4*)(Ad + r * AS_STR + ak4) = cvt4_tf32(ra[i]);
            }
#pragma unroll
            for (int i = 0; i < 4; i++)
                *(uint4*)(Bd + (bk + i * 8) * BS_STR + bn4) = cvt4_tf32(rb[i]);
        }
        __syncthreads();
    }

    float gt = gt_p[0], gg = gg_p[0];
#pragma unroll
    for (int mt = 0; mt < 2; mt++)
#pragma unroll
        for (int rh = 0; rh < 2; rh++) {
            int r = row0 + warpm * 32 + mt * 16 + rh * 8 + gr;
            float bv = bo[r];
#pragma unroll
            for (int nt = 0; nt < 4; nt++) {
                int col = hw0 + warpn * 32 + nt * 8 + gc * 2;
                size_t idx = (size_t)b * CC * HW + (size_t)r * HW + col;
                float2 x2 = *(const float2*)(xin + idx);
                float2 t2 = *(const float2*)(g_tsa + idx);
                float2 o2;
                o2.x = gt * t2.x + gg * (c[mt][nt][rh * 2 + 0] + bv) + x2.x;
                o2.y = gt * t2.y + gg * (c[mt][nt][rh * 2 + 1] + bv) + x2.y;
                *(float2*)(out + idx) = o2;
            }
        }
}

// ---------------- fp32 proj (m/n, concentration-sensitive) ----------------
__global__ void __launch_bounds__(256) proj_gemm(
    const float* __restrict__ W, const float* __restrict__ bias,
    const float* __restrict__ x, float* __restrict__ out, int Co)
{
    __shared__ float As[16][64];
    __shared__ float Bs[16][64];
    int jt  = blockIdx.x;
    int o0  = blockIdx.y * 64;
    int b   = (jt * 64) / HW;
    int hw0 = (jt * 64) % HW;
    const float* xb = x + (size_t)b * CC * HW + hw0;
    int tid = threadIdx.x;
    int tx = tid & 15, ty = tid >> 4;
    float acc[4][4];
#pragma unroll
    for (int i = 0; i < 4; i++)
#pragma unroll
        for (int j = 0; j < 4; j++) acc[i][j] = 0.f;

    int lo  = tid >> 2;
    int lk4 = (tid & 3) * 4;
    int bk  = tid >> 4;
    int bj4 = (tid & 15) * 4;

    for (int k0 = 0; k0 < CC; k0 += 16) {
        float4 wv = make_float4(0.f, 0.f, 0.f, 0.f);
        if (o0 + lo < Co)
            wv = *(const float4*)(W + (size_t)(o0 + lo) * CC + k0 + lk4);
        As[lk4 + 0][lo] = wv.x; As[lk4 + 1][lo] = wv.y;
        As[lk4 + 2][lo] = wv.z; As[lk4 + 3][lo] = wv.w;
        float4 xv = *(const float4*)(xb + (size_t)(k0 + bk) * HW + bj4);
        *(float4*)&Bs[bk][bj4] = xv;
        __syncthreads();
#pragma unroll
        for (int k = 0; k < 16; k++) {
            float4 a  = *(float4*)&As[k][ty * 4];
            float4 bb = *(float4*)&Bs[k][tx * 4];
            float av[4] = {a.x, a.y, a.z, a.w};
            float bv[4] = {bb.x, bb.y, bb.z, bb.w};
#pragma unroll
            for (int i = 0; i < 4; i++)
#pragma unroll
                for (int j = 0; j < 4; j++)
                    acc[i][j] = fmaf(av[i], bv[j], acc[i][j]);
        }
        __syncthreads();
    }
#pragma unroll
    for (int i = 0; i < 4; i++) {
        int o = o0 + ty * 4 + i;
        if (o < Co) {
            float bsv = bias[o];
            float4 ov = make_float4(acc[i][0] + bsv, acc[i][1] + bsv,
                                    acc[i][2] + bsv, acc[i][3] + bsv);
            *(float4*)(out + (size_t)b * Co * HW + (size_t)o * HW + hw0 + tx * 4) = ov;
        }
    }
}

__global__ void __launch_bounds__(256) concat_mn(
    const float* __restrict__ wm, const float* __restrict__ bm,
    const float* __restrict__ wn, const float* __restrict__ bn)
{
    int i = blockIdx.x * 256 + threadIdx.x;
    if (i < 32 * 256) { g_wmn[i] = wm[i]; g_wmn[32 * 256 + i] = wn[i]; }
    if (i < 32) { g_bmn[i] = bm[i]; g_bmn[32 + i] = bn[i]; }
}

// ---------------- FA2-style flash TSA with mma.sync bf16 ----------------
// Change vs R6: softmax denominator computed by an extra mma per P-chunk
// against constant all-ones bf16x2 B operands (row sums accumulate in l4
// across all 18 K-tiles); removes 64 FADD/iter and the end shuffles.
#define QS_STR 40
#define VS_STR 136
__global__ void __launch_bounds__(256) flash_mma()
{
    __shared__ __nv_bfloat16 Qs[128 * QS_STR];
    __shared__ __nv_bfloat16 Ks[128 * QS_STR];
    __shared__ __nv_bfloat16 Vs[32 * VS_STR];
    int tid = threadIdx.x, wid = tid >> 5, lane = tid & 31;
    int bh = blockIdx.y, i0 = blockIdx.x * 128;
    int gr = lane >> 2, gc = (lane & 3) * 2;
    const uint32_t ONES = 0x3F803F80u;   // bf16x2 {1.0, 1.0}

    const __nv_bfloat16* qsrc = g_qh + ((size_t)bh * HW + i0) * DK;
    const __nv_bfloat16* ksrc = g_kh + (size_t)bh * HW * DK;
    const __nv_bfloat16* vsrc = g_vh + (size_t)bh * DK * HW;

    for (int e = tid; e < 512; e += 256) {
        int r = e >> 2, c8 = (e & 3) * 8;
        *(uint4*)(Qs + r * QS_STR + c8) = *(const uint4*)(qsrc + r * DK + c8);
    }
    __syncthreads();

    uint32_t qa[2][4];
    {
        const __nv_bfloat16* qb = Qs + (wid * 16 + gr) * QS_STR;
#pragma unroll
        for (int kc = 0; kc < 2; kc++) {
            qa[kc][0] = *(const uint32_t*)(qb + kc * 16 + gc);
            qa[kc][1] = *(const uint32_t*)(qb + 8 * QS_STR + kc * 16 + gc);
            qa[kc][2] = *(const uint32_t*)(qb + kc * 16 + gc + 8);
            qa[kc][3] = *(const uint32_t*)(qb + 8 * QS_STR + kc * 16 + gc + 8);
        }
    }

    float o[4][4];
#pragma unroll
    for (int i = 0; i < 4; i++)
#pragma unroll
        for (int j = 0; j < 4; j++) o[i][j] = 0.f;
    float l4[4] = {0.f, 0.f, 0.f, 0.f};   // row-sum accumulator (ones-mma)

    for (int kt = 0; kt < 18; kt++) {
        int j0 = kt * 128;
        __syncthreads();
        for (int e = tid; e < 512; e += 256) {
            int r = e >> 2, c8 = (e & 3) * 8;
            *(uint4*)(Ks + r * QS_STR + c8) = *(const uint4*)(ksrc + (size_t)(j0 + r) * DK + c8);
        }
        for (int e = tid; e < 512; e += 256) {
            int d = e >> 4, c8 = (e & 15) * 8;
            *(uint4*)(Vs + d * VS_STR + c8) = *(const uint4*)(vsrc + (size_t)d * HW + j0 + c8);
        }
        __syncthreads();

        float s[16][4];
#pragma unroll
        for (int nt = 0; nt < 16; nt++) {
            s[nt][0] = 0.f; s[nt][1] = 0.f; s[nt][2] = 0.f; s[nt][3] = 0.f;
            const __nv_bfloat16* kb = Ks + (nt * 8 + gr) * QS_STR;
#pragma unroll
            for (int kc = 0; kc < 2; kc++) {
                uint32_t b0 = *(const uint32_t*)(kb + kc * 16 + gc);
                uint32_t b1 = *(const uint32_t*)(kb + kc * 16 + gc + 8);
                mma16816(s[nt], qa[kc], b0, b1);
            }
        }

        uint32_t pa_[8][4];
#pragma unroll
        for (int h2 = 0; h2 < 8; h2++) {
            float e00 = __expf(s[2 * h2][0]),     e01 = __expf(s[2 * h2][1]);
            float e02 = __expf(s[2 * h2][2]),     e03 = __expf(s[2 * h2][3]);
            float f00 = __expf(s[2 * h2 + 1][0]), f01 = __expf(s[2 * h2 + 1][1]);
            float f02 = __expf(s[2 * h2 + 1][2]), f03 = __expf(s[2 * h2 + 1][3]);
            pa_[h2][0] = pack_bf16x2(e01, e00);
            pa_[h2][1] = pack_bf16x2(e03, e02);
            pa_[h2][2] = pack_bf16x2(f01, f00);
            pa_[h2][3] = pack_bf16x2(f03, f02);
        }

#pragma unroll
        for (int kc2 = 0; kc2 < 8; kc2++) {
#pragma unroll
            for (int dt = 0; dt < 4; dt++) {
                const __nv_bfloat16* vb = Vs + (dt * 8 + gr) * VS_STR + kc2 * 16 + gc;
                uint32_t b0 = *(const uint32_t*)(vb);
                uint32_t b1 = *(const uint32_t*)(vb + 8);
                mma16816(o[dt], pa_[kc2], b0, b1);
            }
            mma16816(l4, pa_[kc2], ONES, ONES);   // row sums via tensor core
        }
    }

    // l4[0] = full row sum for row gr; l4[2] for row gr+8 (all cols equal)
    float inv0 = 1.f / l4[0], inv1 = 1.f / l4[2];

    int b = bh >> 3, h = bh & 7;
    float* ob = g_tsa + ((size_t)b * CC + h * DK) * HW;
    int tok0 = i0 + wid * 16 + gr;
#pragma unroll
    for (int dt = 0; dt < 4; dt++) {
        int d = dt * 8 + gc;
        ob[(size_t)(d)     * HW + tok0]     = o[dt][0] * inv0;
        ob[(size_t)(d + 1) * HW + tok0]     = o[dt][1] * inv0;
        ob[(size_t)(d)     * HW + tok0 + 8] = o[dt][2] * inv1;
        ob[(size_t)(d + 1) * HW + tok0 + 8] = o[dt][3] * inv1;
    }
}

// ---------------- launch ----------------
extern "C" void kernel_launch(void* const* d_in, const int* in_sizes, int n_in,
                              void* d_out, int out_size)
{
    const float* x   = (const float*)d_in[0];
    const float* wq  = (const float*)d_in[1];
    const float* bq  = (const float*)d_in[2];
    const float* wk  = (const float*)d_in[3];
    const float* bk  = (const float*)d_in[4];
    const float* wv  = (const float*)d_in[5];
    const float* bv  = (const float*)d_in[6];
    const float* wm  = (const float*)d_in[7];
    const float* bm  = (const float*)d_in[8];
    const float* wn  = (const float*)d_in[9];
    const float* bn  = (const float*)d_in[10];
    const float* ww  = (const float*)d_in[11];
    const float* bw  = (const float*)d_in[12];
    const float* wo  = (const float*)d_in[13];
    const float* bo  = (const float*)d_in[14];
    const float* gts = (const float*)d_in[15];
    const float* ggs = (const float*)d_in[16];
    float* out = (float*)d_out;

    float *pmn, *pwmn, *pbmn;
    cudaGetSymbolAddress((void**)&pmn, g_mn);
    cudaGetSymbolAddress((void**)&pwmn, g_wmn);
    cudaGetSymbolAddress((void**)&pbmn, g_bmn);

    static int smem_set = 0;
    const int DBUF_SMEM = (2 * ASZ + 2 * BSZ) * 4;   // 53248 B
    if (!smem_set) {
        cudaFuncSetAttribute(tf32_gsa, cudaFuncAttributeMaxDynamicSharedMemorySize, DBUF_SMEM);
        cudaFuncSetAttribute(tf32_final, cudaFuncAttributeMaxDynamicSharedMemorySize, DBUF_SMEM);
        smem_set = 1;
    }

    dim3 blk(256);

    concat_mn<<<32, blk>>>(wm, bm, wn, bn);

    tf32_proj4<<<dim3(36, 16), blk>>>(wq, bq, wk, bk, wv, bv, ww, bw, x);
    proj_gemm<<<dim3(BB * HW / 64, 1), blk>>>(pwmn, pbmn, x, pmn, 64);

    flash_mma<<<dim3(HW / 128, BB * HEADS), blk>>>();

    pa_softmax<<<dim3(HW / 32, BB), blk>>>();
    tf32_gsa<<<dim3(36, 4), blk, DBUF_SMEM>>>();

    tf32_final<<<dim3(36, 4), blk, DBUF_SMEM>>>(wo, bo, x, gts, ggs, out);
}

// round 11
// speedup vs baseline: 1.0876x; 1.0323x over previous
#include <cuda_runtime.h>
#include <cuda_bf16.h>
#include <cstdint>

#define BB    2
#define CC    256
#define HW    2304
#define HEADS 8
#define DK    32
#define CR    32
#define NCH   (BB*CC*HW)

// ---------------- scratch (device globals; no allocation) ----------------
__device__ float g_w[NCH];              // wf projection (fp32)
__device__ float g_mn[BB*64*HW];        // m (rows 0-31) and n (rows 32-63)
__device__ float g_wmn[64*256];
__device__ float g_bmn[64];
__device__ float g_tsa[NCH];
__device__ float g_gsa[NCH];
__device__ float g_l[BB*HW];            // GSA softmax row sums
__device__ float g_pa[(size_t)BB*HW*HW]; // unnormalized exp(scores), 42.5 MB
__device__ __nv_bfloat16 g_qh[NCH];     // [bh][t][d], pre-scaled
__device__ __nv_bfloat16 g_kh[NCH];     // [bh][t][d]
__device__ __nv_bfloat16 g_vh[NCH];     // [bh][d][t]

// ---------------- fast exp on the FMA pipe ----------------
__device__ __forceinline__ float fexp(float x) {
    float t = x * 1.4426950408889634f;
    t = fmaxf(t, -126.0f);
    float r = t + 12582912.0f;
    int   ii = __float_as_int(r) - 0x4B400000;
    float fi = r - 12582912.0f;
    float f  = t - fi;
    float p  = 1.3333558e-3f;
    p = fmaf(p, f, 9.6181291e-3f);
    p = fmaf(p, f, 5.5504109e-2f);
    p = fmaf(p, f, 2.4022651e-1f);
    p = fmaf(p, f, 6.9314718e-1f);
    p = fmaf(p, f, 1.0f);
    return __int_as_float(__float_as_int(p) + (ii << 23));
}

// ---------------- mma helpers ----------------
__device__ __forceinline__ void mma16816(float* c, const uint32_t* a, uint32_t b0, uint32_t b1) {
    asm volatile(
        "mma.sync.aligned.m16n8k16.row.col.f32.bf16.bf16.f32 "
        "{%0,%1,%2,%3}, {%4,%5,%6,%7}, {%8,%9}, {%0,%1,%2,%3};"
        : "+f"(c[0]), "+f"(c[1]), "+f"(c[2]), "+f"(c[3])
        : "r"(a[0]), "r"(a[1]), "r"(a[2]), "r"(a[3]), "r"(b0), "r"(b1));
}
__device__ __forceinline__ void mma_tf32(float* c, const uint32_t* a, uint32_t b0, uint32_t b1) {
    asm volatile(
        "mma.sync.aligned.m16n8k8.row.col.f32.tf32.tf32.f32 "
        "{%0,%1,%2,%3}, {%4,%5,%6,%7}, {%8,%9}, {%0,%1,%2,%3};"
        : "+f"(c[0]), "+f"(c[1]), "+f"(c[2]), "+f"(c[3])
        : "r"(a[0]), "r"(a[1]), "r"(a[2]), "r"(a[3]), "r"(b0), "r"(b1));
}
__device__ __forceinline__ uint32_t pack_bf16x2(float hi, float lo) {
    uint32_t w;
    asm("cvt.rn.satfinite.bf16x2.f32 %0, %1, %2;" : "=r"(w) : "f"(hi), "f"(lo));
    return w;
}
__device__ __forceinline__ uint32_t cvt_tf32(float f) {
    uint32_t r;
    asm("cvt.rna.tf32.f32 %0, %1;" : "=r"(r) : "f"(f));
    return r;
}
__device__ __forceinline__ uint4 cvt4_tf32(float4 v) {
    uint4 o;
    o.x = cvt_tf32(v.x); o.y = cvt_tf32(v.y); o.z = cvt_tf32(v.z); o.w = cvt_tf32(v.w);
    return o;
}

#define AS_STR 36
#define BS_STR 136
#define ASZ (64 * AS_STR)
#define BSZ (32 * BS_STR)

__device__ __forceinline__ void tf32_chunk(
    const uint32_t* Ap, const uint32_t* Bp, float c[2][4][4],
    int warpm, int warpn, int gr, int gc)
{
#pragma unroll
    for (int ks = 0; ks < 4; ks++) {
        uint32_t a[2][4], bq[4][2];
#pragma unroll
        for (int mt = 0; mt < 2; mt++) {
            const uint32_t* ab = Ap + (warpm * 32 + mt * 16) * AS_STR + ks * 8 + gc;
            a[mt][0] = ab[gr * AS_STR];
            a[mt][1] = ab[(gr + 8) * AS_STR];
            a[mt][2] = ab[gr * AS_STR + 4];
            a[mt][3] = ab[(gr + 8) * AS_STR + 4];
        }
#pragma unroll
        for (int nt = 0; nt < 4; nt++) {
            const uint32_t* bb = Bp + (ks * 8 + gc) * BS_STR + warpn * 32 + nt * 8 + gr;
            bq[nt][0] = bb[0];
            bq[nt][1] = bb[4 * BS_STR];
        }
#pragma unroll
        for (int mt = 0; mt < 2; mt++)
#pragma unroll
            for (int nt = 0; nt < 4; nt++)
                mma_tf32(c[mt][nt], a[mt], bq[nt][0], bq[nt][1]);
    }
}

// ---------------- fused QKVW projection + bf16 layout epilogues -----------
__global__ void __launch_bounds__(256) tf32_proj4(
    const float* __restrict__ wq, const float* __restrict__ bq,
    const float* __restrict__ wk, const float* __restrict__ bk,
    const float* __restrict__ wv, const float* __restrict__ bv,
    const float* __restrict__ ww, const float* __restrict__ bw,
    const float* __restrict__ x)
{
    __shared__ uint32_t As[ASZ];
    __shared__ uint32_t Bs[BSZ];
    int tid = threadIdx.x, lane = tid & 31, wid = tid >> 5;
    int gr = lane >> 2, gc = lane & 3;
    int sel  = blockIdx.y >> 2;
    int row0 = (blockIdx.y & 3) * 64;
    const float* W    = sel == 0 ? wq : sel == 1 ? wk : sel == 2 ? wv : ww;
    const float* bias = sel == 0 ? bq : sel == 1 ? bk : sel == 2 ? bv : bw;
    int b = blockIdx.x / 18, hw0 = (blockIdx.x % 18) * 128;
    const float* Bb = x + (size_t)b * CC * HW + hw0;
    int warpm = wid >> 2, warpn = wid & 3;
    float c[2][4][4];
#pragma unroll
    for (int i = 0; i < 2; i++)
#pragma unroll
        for (int j = 0; j < 4; j++)
#pragma unroll
            for (int k = 0; k < 4; k++) c[i][j][k] = 0.f;

    for (int k0 = 0; k0 < 256; k0 += 32) {
#pragma unroll
        for (int i = 0; i < 2; i++) {
            int e = tid + i * 256;
            int r = e >> 3, k4 = (e & 7) * 4;
            float4 w4 = *(const float4*)(W + (size_t)(row0 + r) * 256 + k0 + k4);
            *(uint4*)(As + r * AS_STR + k4) = cvt4_tf32(w4);
        }
#pragma unroll
        for (int i = 0; i < 4; i++) {
            int e = tid + i * 256;
            int k = e >> 5, n4 = (e & 31) * 4;
            float4 v4 = *(const float4*)(Bb + (size_t)(k0 + k) * HW + n4);
            *(uint4*)(Bs + k * BS_STR + n4) = cvt4_tf32(v4);
        }
        __syncthreads();
        tf32_chunk(As, Bs, c, warpm, warpn, gr, gc);
        __syncthreads();
    }

    if (sel == 3) {                       // wf: fp32, [b][c][t]
#pragma unroll
        for (int mt = 0; mt < 2; mt++)
#pragma unroll
            for (int rh = 0; rh < 2; rh++) {
                int r = row0 + warpm * 32 + mt * 16 + rh * 8 + gr;
                float bv2 = bias[r];
#pragma unroll
                for (int nt = 0; nt < 4; nt++) {
                    int col = hw0 + warpn * 32 + nt * 8 + gc * 2;
                    size_t idx = (size_t)b * CC * HW + (size_t)r * HW + col;
                    *(float2*)(g_w + idx) = make_float2(c[mt][nt][rh * 2 + 0] + bv2,
                                                        c[mt][nt][rh * 2 + 1] + bv2);
                }
            }
    } else if (sel == 2) {                // v: bf16 packed, [bh][d][t]
#pragma unroll
        for (int mt = 0; mt < 2; mt++)
#pragma unroll
            for (int rh = 0; rh < 2; rh++) {
                int r = row0 + warpm * 32 + mt * 16 + rh * 8 + gr;
                float bv2 = bias[r];
#pragma unroll
                for (int nt = 0; nt < 4; nt++) {
                    int col = hw0 + warpn * 32 + nt * 8 + gc * 2;
                    size_t idx = (size_t)(b * 256 + r) * HW + col;
                    uint32_t pw = pack_bf16x2(c[mt][nt][rh * 2 + 1] + bv2,
                                              c[mt][nt][rh * 2 + 0] + bv2);
                    *(uint32_t*)(g_vh + idx) = pw;
                }
            }
    } else {                              // q/k: bf16 scatter into [bh][t][d]
        float scale = sel == 0 ? 0.17677669529663687f : 1.0f;
        __nv_bfloat16* dst = sel == 0 ? g_qh : g_kh;
#pragma unroll
        for (int mt = 0; mt < 2; mt++)
#pragma unroll
            for (int rh = 0; rh < 2; rh++) {
                int r = row0 + warpm * 32 + mt * 16 + rh * 8 + gr;
                float bv2 = bias[r];
                size_t hb = (size_t)(b * 8 + (r >> 5)) * HW;
                int d = r & 31;
#pragma unroll
                for (int nt = 0; nt < 4; nt++) {
                    int col = hw0 + warpn * 32 + nt * 8 + gc * 2;
                    float v0 = (c[mt][nt][rh * 2 + 0] + bv2) * scale;
                    float v1 = (c[mt][nt][rh * 2 + 1] + bv2) * scale;
                    dst[(hb + col)     * 32 + d] = __float2bfloat16(v0);
                    dst[(hb + col + 1) * 32 + d] = __float2bfloat16(v1);
                }
            }
    }
}

// ---------------- fused GSA scores + exp (split-tf32, fp32-accurate) ------
#define PAB_STR 68
__global__ void __launch_bounds__(256) pa_softmax()
{
    __shared__ uint32_t Ahi[32 * 36], Alo[32 * 36];
    __shared__ uint32_t Bhi[32 * PAB_STR], Blo[32 * PAB_STR];
    __shared__ float red[32 * 8];
    int tid = threadIdx.x, lane = tid & 31, wid = tid >> 5;
    int gr = lane >> 2, gc = lane & 3;
    int b = blockIdx.y, n0 = blockIdx.x * 32;
    const float* Mp = g_mn + (size_t)b * 64 * HW;
    const float* Np = Mp + (size_t)32 * HW;

    for (int e = tid; e < 1024; e += 256) {
        int ch = e >> 5, n = e & 31;
        float v = Mp[(size_t)ch * HW + n0 + n];
        uint32_t h = cvt_tf32(v);
        Ahi[n * 36 + ch] = h;
        Alo[n * 36 + ch] = cvt_tf32(v - __uint_as_float(h));
    }

    int bm = tid & 63, bc0 = tid >> 6;
    float rbv[8];
#pragma unroll
    for (int i = 0; i < 8; i++)
        rbv[i] = Np[(size_t)(bc0 + i * 4) * HW + bm];

    float rs[2][2] = {{0.f, 0.f}, {0.f, 0.f}};
    float* pab = g_pa + (size_t)b * HW * HW;
    __syncthreads();

    for (int t = 0; t < 36; t++) {
#pragma unroll
        for (int i = 0; i < 8; i++) {
            int ch = bc0 + i * 4;
            uint32_t h = cvt_tf32(rbv[i]);
            Bhi[ch * PAB_STR + bm] = h;
            Blo[ch * PAB_STR + bm] = cvt_tf32(rbv[i] - __uint_as_float(h));
        }
        __syncthreads();
        if (t + 1 < 36) {
#pragma unroll
            for (int i = 0; i < 8; i++)
                rbv[i] = Np[(size_t)(bc0 + i * 4) * HW + (t + 1) * 64 + bm];
        }
        float c[2][4];
#pragma unroll
        for (int mt = 0; mt < 2; mt++)
#pragma unroll
            for (int j = 0; j < 4; j++) c[mt][j] = 0.f;
#pragma unroll
        for (int ks = 0; ks < 4; ks++) {
            uint32_t ah[2][4], al[2][4];
#pragma unroll
            for (int mt = 0; mt < 2; mt++) {
                int rb = mt * 16;
                ah[mt][0] = Ahi[(rb + gr) * 36 + ks * 8 + gc];
                ah[mt][1] = Ahi[(rb + gr + 8) * 36 + ks * 8 + gc];
                ah[mt][2] = Ahi[(rb + gr) * 36 + ks * 8 + gc + 4];
                ah[mt][3] = Ahi[(rb + gr + 8) * 36 + ks * 8 + gc + 4];
                al[mt][0] = Alo[(rb + gr) * 36 + ks * 8 + gc];
                al[mt][1] = Alo[(rb + gr + 8) * 36 + ks * 8 + gc];
                al[mt][2] = Alo[(rb + gr) * 36 + ks * 8 + gc + 4];
                al[mt][3] = Alo[(rb + gr + 8) * 36 + ks * 8 + gc + 4];
            }
            int colb = wid * 8 + gr;
            uint32_t bh0 = Bhi[(ks * 8 + gc) * PAB_STR + colb];
            uint32_t bh1 = Bhi[(ks * 8 + gc + 4) * PAB_STR + colb];
            uint32_t bl0 = Blo[(ks * 8 + gc) * PAB_STR + colb];
            uint32_t bl1 = Blo[(ks * 8 + gc + 4) * PAB_STR + colb];
#pragma unroll
            for (int mt = 0; mt < 2; mt++) {
                mma_tf32(c[mt], ah[mt], bh0, bh1);
                mma_tf32(c[mt], ah[mt], bl0, bl1);
                mma_tf32(c[mt], al[mt], bh0, bh1);
            }
        }
        int m_base = t * 64 + wid * 8 + gc * 2;
#pragma unroll
        for (int mt = 0; mt < 2; mt++)
#pragma unroll
            for (int rh = 0; rh < 2; rh++) {
                float p0 = __expf(c[mt][rh * 2 + 0]);
                float p1 = __expf(c[mt][rh * 2 + 1]);
                rs[mt][rh] += p0 + p1;
                int n = n0 + mt * 16 + rh * 8 + gr;
                *(float2*)(pab + (size_t)n * HW + m_base) = make_float2(p0, p1);
            }
        __syncthreads();
    }

#pragma unroll
    for (int mt = 0; mt < 2; mt++)
#pragma unroll
        for (int rh = 0; rh < 2; rh++) {
            float v = rs[mt][rh];
            v += __shfl_xor_sync(0xffffffffu, v, 1);
            v += __shfl_xor_sync(0xffffffffu, v, 2);
            if (gc == 0) red[(mt * 16 + rh * 8 + gr) * 8 + wid] = v;
        }
    __syncthreads();
    if (tid < 32) {
        float s = 0.f;
#pragma unroll
        for (int w = 0; w < 8; w++) s += red[tid * 8 + w];
        g_l[(size_t)b * HW + n0 + tid] = s;
    }
}

// ---------------- double-buffered tf32 GSA: gsa = (wf @ pa^T) / l ---------
__global__ void __launch_bounds__(256) tf32_gsa()
{
    extern __shared__ uint32_t dsm[];
    uint32_t* As = dsm;
    uint32_t* Bs = dsm + 2 * ASZ;
    int tid = threadIdx.x, lane = tid & 31, wid = tid >> 5;
    int gr = lane >> 2, gc = lane & 3;
    int c0 = blockIdx.y * 64;
    int b = blockIdx.x / 18, n0 = (blockIdx.x % 18) * 128;
    const float* wfb = g_w + (size_t)b * CC * HW;
    const float* pab = g_pa + (size_t)b * HW * HW;
    int warpm = wid >> 2, warpn = wid & 3;

    int ar = tid >> 3, ak4 = (tid & 7) * 4;
    int ar2 = (tid + 256) >> 3;
    int bn = tid & 127, bk4_0 = (tid >> 7) * 4;

    float4 ra[2], rb[4];
#pragma unroll
    for (int i = 0; i < 2; i++) {
        int r = (i == 0) ? ar : ar2;
        ra[i] = *(const float4*)(wfb + (size_t)(c0 + r) * HW + 0 + ak4);
    }
#pragma unroll
    for (int i = 0; i < 4; i++)
        rb[i] = *(const float4*)(pab + (size_t)(n0 + bn) * HW + 0 + (bk4_0 + i * 8));
#pragma unroll
    for (int i = 0; i < 2; i++) {
        int r = (i == 0) ? ar : ar2;
        *(uint4*)(As + r * AS_STR + ak4) = cvt4_tf32(ra[i]);
    }
#pragma unroll
    for (int i = 0; i < 4; i++) {
        int k4 = bk4_0 + i * 8;
        Bs[(k4 + 0) * BS_STR + bn] = cvt_tf32(rb[i].x);
        Bs[(k4 + 1) * BS_STR + bn] = cvt_tf32(rb[i].y);
        Bs[(k4 + 2) * BS_STR + bn] = cvt_tf32(rb[i].z);
        Bs[(k4 + 3) * BS_STR + bn] = cvt_tf32(rb[i].w);
    }
    __syncthreads();

    float c[2][4][4];
#pragma unroll
    for (int i = 0; i < 2; i++)
#pragma unroll
        for (int j = 0; j < 4; j++)
#pragma unroll
            for (int k = 0; k < 4; k++) c[i][j][k] = 0.f;

    for (int it = 0; it < 72; it++) {
        int p = it & 1;
        int m1 = (it + 1) * 32;
        if (it + 1 < 72) {
#pragma unroll
            for (int i = 0; i < 2; i++) {
                int r = (i == 0) ? ar : ar2;
                ra[i] = *(const float4*)(wfb + (size_t)(c0 + r) * HW + m1 + ak4);
            }
#pragma unroll
            for (int i = 0; i < 4; i++)
                rb[i] = *(const float4*)(pab + (size_t)(n0 + bn) * HW + m1 + (bk4_0 + i * 8));
        }
        tf32_chunk(As + p * ASZ, Bs + p * BSZ, c, warpm, warpn, gr, gc);
        if (it + 1 < 72) {
            uint32_t* Ad = As + (p ^ 1) * ASZ;
            uint32_t* Bd = Bs + (p ^ 1) * BSZ;
#pragma unroll
            for (int i = 0; i < 2; i++) {
                int r = (i == 0) ? ar : ar2;
                *(uint4*)(Ad + r * AS_STR + ak4) = cvt4_tf32(ra[i]);
            }
#pragma unroll
            for (int i = 0; i < 4; i++) {
                int k4 = bk4_0 + i * 8;
                Bd[(k4 + 0) * BS_STR + bn] = cvt_tf32(rb[i].x);
                Bd[(k4 + 1) * BS_STR + bn] = cvt_tf32(rb[i].y);
                Bd[(k4 + 2) * BS_STR + bn] = cvt_tf32(rb[i].z);
                Bd[(k4 + 3) * BS_STR + bn] = cvt_tf32(rb[i].w);
            }
        }
        __syncthreads();
    }

    float inv[4][2];
#pragma unroll
    for (int nt = 0; nt < 4; nt++) {
        int col = n0 + warpn * 32 + nt * 8 + gc * 2;
        inv[nt][0] = 1.f / g_l[(size_t)b * HW + col];
        inv[nt][1] = 1.f / g_l[(size_t)b * HW + col + 1];
    }
    float* ob = g_gsa + (size_t)b * CC * HW;
#pragma unroll
    for (int mt = 0; mt < 2; mt++)
#pragma unroll
        for (int rh = 0; rh < 2; rh++) {
            int r = c0 + warpm * 32 + mt * 16 + rh * 8 + gr;
#pragma unroll
            for (int nt = 0; nt < 4; nt++) {
                int col = n0 + warpn * 32 + nt * 8 + gc * 2;
                *(float2*)(ob + (size_t)r * HW + col) =
                    make_float2(c[mt][nt][rh * 2 + 0] * inv[nt][0],
                                c[mt][nt][rh * 2 + 1] * inv[nt][1]);
            }
        }
}

// ---------------- double-buffered final GEMM + fusion epilogue ------------
__global__ void __launch_bounds__(256) tf32_final(
    const float* __restrict__ wo, const float* __restrict__ bo,
    const float* __restrict__ xin,
    const float* __restrict__ gt_p, const float* __restrict__ gg_p,
    float* __restrict__ out)
{
    extern __shared__ uint32_t dsm[];
    uint32_t* As = dsm;
    uint32_t* Bs = dsm + 2 * ASZ;
    int tid = threadIdx.x, lane = tid & 31, wid = tid >> 5;
    int gr = lane >> 2, gc = lane & 3;
    int row0 = blockIdx.y * 64;
    int b = blockIdx.x / 18, hw0 = (blockIdx.x % 18) * 128;
    const float* Bb = g_gsa + (size_t)b * CC * HW + hw0;
    int warpm = wid >> 2, warpn = wid & 3;

    int ar = tid >> 3, ak4 = (tid & 7) * 4;
    int ar2 = (tid + 256) >> 3;
    int bk = tid >> 5, bn4 = (tid & 31) * 4;

    float4 ra[2], rb[4];
#pragma unroll
    for (int i = 0; i < 2; i++) {
        int r = (i == 0) ? ar : ar2;
        ra[i] = *(const float4*)(wo + (size_t)(row0 + r) * 256 + 0 + ak4);
    }
#pragma unroll
    for (int i = 0; i < 4; i++)
        rb[i] = *(const float4*)(Bb + (size_t)(0 + bk + i * 8) * HW + bn4);
#pragma unroll
    for (int i = 0; i < 2; i++) {
        int r = (i == 0) ? ar : ar2;
        *(uint4*)(As + r * AS_STR + ak4) = cvt4_tf32(ra[i]);
    }
#pragma unroll
    for (int i = 0; i < 4; i++)
        *(uint4*)(Bs + (bk + i * 8) * BS_STR + bn4) = cvt4_tf32(rb[i]);
    __syncthreads();

    float c[2][4][4];
#pragma unroll
    for (int i = 0; i < 2; i++)
#pragma unroll
        for (int j = 0; j < 4; j++)
#pragma unroll
            for (int k = 0; k < 4; k++) c[i][j][k] = 0.f;

    for (int it = 0; it < 8; it++) {
        int p = it & 1;
        int k1 = (it + 1) * 32;
        if (it + 1 < 8) {
#pragma unroll
            for (int i = 0; i < 2; i++) {
                int r = (i == 0) ? ar : ar2;
                ra[i] = *(const float4*)(wo + (size_t)(row0 + r) * 256 + k1 + ak4);
            }
#pragma unroll
            for (int i = 0; i < 4; i++)
                rb[i] = *(const float4*)(Bb + (size_t)(k1 + bk + i * 8) * HW + bn4);
        }
        tf32_chunk(As + p * ASZ, Bs + p * BSZ, c, warpm, warpn, gr, gc);
        if (it + 1 < 8) {
            uint32_t* Ad = As + (p ^ 1) * ASZ;
            uint32_t* Bd = Bs + (p ^ 1) * BSZ;
#pragma unroll
            for (int i = 0; i < 2; i++) {
                int r = (i == 0) ? ar : ar2;
                *(uint4*)(Ad + r * AS_STR + ak4) = cvt4_tf32(ra[i]);
            }
#pragma unroll
            for (int i = 0; i < 4; i++)
                *(uint4*)(Bd + (bk + i * 8) * BS_STR + bn4) = cvt4_tf32(rb[i]);
        }
        __syncthreads();
    }

    float gt = gt_p[0], gg = gg_p[0];
#pragma unroll
    for (int mt = 0; mt < 2; mt++)
#pragma unroll
        for (int rh = 0; rh < 2; rh++) {
            int r = row0 + warpm * 32 + mt * 16 + rh * 8 + gr;
            float bv = bo[r];
#pragma unroll
            for (int nt = 0; nt < 4; nt++) {
                int col = hw0 + warpn * 32 + nt * 8 + gc * 2;
                size_t idx = (size_t)b * CC * HW + (size_t)r * HW + col;
                float2 x2 = *(const float2*)(xin + idx);
                float2 t2 = *(const float2*)(g_tsa + idx);
                float2 o2;
                o2.x = gt * t2.x + gg * (c[mt][nt][rh * 2 + 0] + bv) + x2.x;
                o2.y = gt * t2.y + gg * (c[mt][nt][rh * 2 + 1] + bv) + x2.y;
                *(float2*)(out + idx) = o2;
            }
        }
}

// ---------------- fp32 proj (m/n, concentration-sensitive) ----------------
__global__ void __launch_bounds__(256) proj_gemm(
    const float* __restrict__ W, const float* __restrict__ bias,
    const float* __restrict__ x, float* __restrict__ out, int Co)
{
    __shared__ float As[16][64];
    __shared__ float Bs[16][64];
    int jt  = blockIdx.x;
    int o0  = blockIdx.y * 64;
    int b   = (jt * 64) / HW;
    int hw0 = (jt * 64) % HW;
    const float* xb = x + (size_t)b * CC * HW + hw0;
    int tid = threadIdx.x;
    int tx = tid & 15, ty = tid >> 4;
    float acc[4][4];
#pragma unroll
    for (int i = 0; i < 4; i++)
#pragma unroll
        for (int j = 0; j < 4; j++) acc[i][j] = 0.f;

    int lo  = tid >> 2;
    int lk4 = (tid & 3) * 4;
    int bk  = tid >> 4;
    int bj4 = (tid & 15) * 4;

    for (int k0 = 0; k0 < CC; k0 += 16) {
        float4 wv = make_float4(0.f, 0.f, 0.f, 0.f);
        if (o0 + lo < Co)
            wv = *(const float4*)(W + (size_t)(o0 + lo) * CC + k0 + lk4);
        As[lk4 + 0][lo] = wv.x; As[lk4 + 1][lo] = wv.y;
        As[lk4 + 2][lo] = wv.z; As[lk4 + 3][lo] = wv.w;
        float4 xv = *(const float4*)(xb + (size_t)(k0 + bk) * HW + bj4);
        *(float4*)&Bs[bk][bj4] = xv;
        __syncthreads();
#pragma unroll
        for (int k = 0; k < 16; k++) {
            float4 a  = *(float4*)&As[k][ty * 4];
            float4 bb = *(float4*)&Bs[k][tx * 4];
            float av[4] = {a.x, a.y, a.z, a.w};
            float bv[4] = {bb.x, bb.y, bb.z, bb.w};
#pragma unroll
            for (int i = 0; i < 4; i++)
#pragma unroll
                for (int j = 0; j < 4; j++)
                    acc[i][j] = fmaf(av[i], bv[j], acc[i][j]);
        }
        __syncthreads();
    }
#pragma unroll
    for (int i = 0; i < 4; i++) {
        int o = o0 + ty * 4 + i;
        if (o < Co) {
            float bsv = bias[o];
            float4 ov = make_float4(acc[i][0] + bsv, acc[i][1] + bsv,
                                    acc[i][2] + bsv, acc[i][3] + bsv);
            *(float4*)(out + (size_t)b * Co * HW + (size_t)o * HW + hw0 + tx * 4) = ov;
        }
    }
}

__global__ void __launch_bounds__(256) concat_mn(
    const float* __restrict__ wm, const float* __restrict__ bm,
    const float* __restrict__ wn, const float* __restrict__ bn)
{
    int i = blockIdx.x * 256 + threadIdx.x;
    if (i < 32 * 256) { g_wmn[i] = wm[i]; g_wmn[32 * 256 + i] = wn[i]; }
    if (i < 32) { g_bmn[i] = bm[i]; g_bmn[32 + i] = bn[i]; }
}

// ---------------- FA2-style flash TSA with mma.sync bf16 ----------------
// vs R6: K/V tiles are register-prefetched one iteration ahead so the LDG
// latency overlaps compute (single change; R6 softmax/l restored verbatim).
#define QS_STR 40
#define VS_STR 136
__global__ void __launch_bounds__(256) flash_mma()
{
    __shared__ __nv_bfloat16 Qs[128 * QS_STR];
    __shared__ __nv_bfloat16 Ks[128 * QS_STR];
    __shared__ __nv_bfloat16 Vs[32 * VS_STR];
    int tid = threadIdx.x, wid = tid >> 5, lane = tid & 31;
    int bh = blockIdx.y, i0 = blockIdx.x * 128;
    int gr = lane >> 2, gc = (lane & 3) * 2;

    const __nv_bfloat16* qsrc = g_qh + ((size_t)bh * HW + i0) * DK;
    const __nv_bfloat16* ksrc = g_kh + (size_t)bh * HW * DK;
    const __nv_bfloat16* vsrc = g_vh + (size_t)bh * DK * HW;

    for (int e = tid; e < 512; e += 256) {
        int r = e >> 2, c8 = (e & 3) * 8;
        *(uint4*)(Qs + r * QS_STR + c8) = *(const uint4*)(qsrc + r * DK + c8);
    }
    __syncthreads();

    uint32_t qa[2][4];
    {
        const __nv_bfloat16* qb = Qs + (wid * 16 + gr) * QS_STR;
#pragma unroll
        for (int kc = 0; kc < 2; kc++) {
            qa[kc][0] = *(const uint32_t*)(qb + kc * 16 + gc);
            qa[kc][1] = *(const uint32_t*)(qb + 8 * QS_STR + kc * 16 + gc);
            qa[kc][2] = *(const uint32_t*)(qb + kc * 16 + gc + 8);
            qa[kc][3] = *(const uint32_t*)(qb + 8 * QS_STR + kc * 16 + gc + 8);
        }
    }

    // per-thread smem/gmem slots for K and V tile pieces
    int kr  = tid >> 2,        kc8 = (tid & 3) * 8;        // K piece 0: row, col
    int kr1 = (tid + 256) >> 2;                            // K piece 1 row
    int vd  = tid >> 4,        vc8 = (tid & 15) * 8;       // V piece 0
    int vd1 = (tid + 256) >> 4;                            // V piece 1

    // prefetch tile 0
    uint4 kreg[2], vreg[2];
    kreg[0] = *(const uint4*)(ksrc + (size_t)kr  * DK + kc8);
    kreg[1] = *(const uint4*)(ksrc + (size_t)kr1 * DK + kc8);
    vreg[0] = *(const uint4*)(vsrc + (size_t)vd  * HW + vc8);
    vreg[1] = *(const uint4*)(vsrc + (size_t)vd1 * HW + vc8);

    float o[4][4];
#pragma unroll
    for (int i = 0; i < 4; i++)
#pragma unroll
        for (int j = 0; j < 4; j++) o[i][j] = 0.f;
    float l0 = 0.f, l1 = 0.f;

    for (int kt = 0; kt < 18; kt++) {
        __syncthreads();                 // prior iter finished reading smem
        *(uint4*)(Ks + kr  * QS_STR + kc8) = kreg[0];
        *(uint4*)(Ks + kr1 * QS_STR + kc8) = kreg[1];
        *(uint4*)(Vs + vd  * VS_STR + vc8) = vreg[0];
        *(uint4*)(Vs + vd1 * VS_STR + vc8) = vreg[1];
        __syncthreads();                 // tile ready
        if (kt + 1 < 18) {               // prefetch next tile (overlaps compute)
            int j1 = (kt + 1) * 128;
            kreg[0] = *(const uint4*)(ksrc + (size_t)(j1 + kr)  * DK + kc8);
            kreg[1] = *(const uint4*)(ksrc + (size_t)(j1 + kr1) * DK + kc8);
            vreg[0] = *(const uint4*)(vsrc + (size_t)vd  * HW + j1 + vc8);
            vreg[1] = *(const uint4*)(vsrc + (size_t)vd1 * HW + j1 + vc8);
        }

        float s[16][4];
#pragma unroll
        for (int nt = 0; nt < 16; nt++) {
            s[nt][0] = 0.f; s[nt][1] = 0.f; s[nt][2] = 0.f; s[nt][3] = 0.f;
            const __nv_bfloat16* kb = Ks + (nt * 8 + gr) * QS_STR;
#pragma unroll
            for (int kc = 0; kc < 2; kc++) {
                uint32_t b0 = *(const uint32_t*)(kb + kc * 16 + gc);
                uint32_t b1 = *(const uint32_t*)(kb + kc * 16 + gc + 8);
                mma16816(s[nt], qa[kc], b0, b1);
            }
        }

        uint32_t pa_[8][4];
#pragma unroll
        for (int h2 = 0; h2 < 8; h2++) {
            float e00 = __expf(s[2 * h2][0]),     e01 = __expf(s[2 * h2][1]);
            float e02 = __expf(s[2 * h2][2]),     e03 = __expf(s[2 * h2][3]);
            float f00 = __expf(s[2 * h2 + 1][0]), f01 = __expf(s[2 * h2 + 1][1]);
            float f02 = __expf(s[2 * h2 + 1][2]), f03 = __expf(s[2 * h2 + 1][3]);
            l0 += (e00 + e01) + (f00 + f01);
            l1 += (e02 + e03) + (f02 + f03);
            pa_[h2][0] = pack_bf16x2(e01, e00);
            pa_[h2][1] = pack_bf16x2(e03, e02);
            pa_[h2][2] = pack_bf16x2(f01, f00);
            pa_[h2][3] = pack_bf16x2(f03, f02);
        }

#pragma unroll
        for (int kc2 = 0; kc2 < 8; kc2++) {
#pragma unroll
            for (int dt = 0; dt < 4; dt++) {
                const __nv_bfloat16* vb = Vs + (dt * 8 + gr) * VS_STR + kc2 * 16 + gc;
                uint32_t b0 = *(const uint32_t*)(vb);
                uint32_t b1 = *(const uint32_t*)(vb + 8);
                mma16816(o[dt], pa_[kc2], b0, b1);
            }
        }
    }

    l0 += __shfl_xor_sync(0xffffffffu, l0, 1);
    l0 += __shfl_xor_sync(0xffffffffu, l0, 2);
    l1 += __shfl_xor_sync(0xffffffffu, l1, 1);
    l1 += __shfl_xor_sync(0xffffffffu, l1, 2);
    float inv0 = 1.f / l0, inv1 = 1.f / l1;

    int b = bh >> 3, h = bh & 7;
    float* ob = g_tsa + ((size_t)b * CC + h * DK) * HW;
    int tok0 = i0 + wid * 16 + gr;
#pragma unroll
    for (int dt = 0; dt < 4; dt++) {
        int d = dt * 8 + gc;
        ob[(size_t)(d)     * HW + tok0]     = o[dt][0] * inv0;
        ob[(size_t)(d + 1) * HW + tok0]     = o[dt][1] * inv0;
        ob[(size_t)(d)     * HW + tok0 + 8] = o[dt][2] * inv1;
        ob[(size_t)(d + 1) * HW + tok0 + 8] = o[dt][3] * inv1;
    }
}

// ---------------- launch ----------------
extern "C" void kernel_launch(void* const* d_in, const int* in_sizes, int n_in,
                              void* d_out, int out_size)
{
    const float* x   = (const float*)d_in[0];
    const float* wq  = (const float*)d_in[1];
    const float* bq  = (const float*)d_in[2];
    const float* wk  = (const float*)d_in[3];
    const float* bk  = (const float*)d_in[4];
    const float* wv  = (const float*)d_in[5];
    const float* bv  = (const float*)d_in[6];
    const float* wm  = (const float*)d_in[7];
    const float* bm  = (const float*)d_in[8];
    const float* wn  = (const float*)d_in[9];
    const float* bn  = (const float*)d_in[10];
    const float* ww  = (const float*)d_in[11];
    const float* bw  = (const float*)d_in[12];
    const float* wo  = (const float*)d_in[13];
    const float* bo  = (const float*)d_in[14];
    const float* gts = (const float*)d_in[15];
    const float* ggs = (const float*)d_in[16];
    float* out = (float*)d_out;

    float *pmn, *pwmn, *pbmn;
    cudaGetSymbolAddress((void**)&pmn, g_mn);
    cudaGetSymbolAddress((void**)&pwmn, g_wmn);
    cudaGetSymbolAddress((void**)&pbmn, g_bmn);

    static int smem_set = 0;
    const int DBUF_SMEM = (2 * ASZ + 2 * BSZ) * 4;   // 53248 B
    if (!smem_set) {
        cudaFuncSetAttribute(tf32_gsa, cudaFuncAttributeMaxDynamicSharedMemorySize, DBUF_SMEM);
        cudaFuncSetAttribute(tf32_final, cudaFuncAttributeMaxDynamicSharedMemorySize, DBUF_SMEM);
        smem_set = 1;
    }

    dim3 blk(256);

    concat_mn<<<32, blk>>>(wm, bm, wn, bn);

    tf32_proj4<<<dim3(36, 16), blk>>>(wq, bq, wk, bk, wv, bv, ww, bw, x);
    proj_gemm<<<dim3(BB * HW / 64, 1), blk>>>(pwmn, pbmn, x, pmn, 64);

    flash_mma<<<dim3(HW / 128, BB * HEADS), blk>>>();

    pa_softmax<<<dim3(HW / 32, BB), blk>>>();
    tf32_gsa<<<dim3(36, 4), blk, DBUF_SMEM>>>();

    tf32_final<<<dim3(36, 4), blk, DBUF_SMEM>>>(wo, bo, x, gts, ggs, out);
}

// round 12
// speedup vs baseline: 1.1054x; 1.0164x over previous
#include <cuda_runtime.h>
#include <cuda_bf16.h>
#include <cstdint>

#define BB    2
#define CC    256
#define HW    2304
#define HEADS 8
#define DK    32
#define CR    32
#define NCH   (BB*CC*HW)

// ---------------- scratch (device globals; no allocation) ----------------
__device__ float g_w[NCH];              // wf projection (fp32)
__device__ float g_mn[BB*64*HW];        // m (rows 0-31, pre-scaled by log2e) and n (rows 32-63)
__device__ float g_wmn[64*256];
__device__ float g_bmn[64];
__device__ float g_tsa[NCH];
__device__ float g_gsa[NCH];
__device__ float g_l[BB*HW];            // GSA softmax row sums
__device__ float g_pa[(size_t)BB*HW*HW]; // unnormalized exp(scores), 42.5 MB
__device__ __nv_bfloat16 g_qh[NCH];     // [bh][t][d], pre-scaled by log2e/sqrt(dk)
__device__ __nv_bfloat16 g_kh[NCH];     // [bh][t][d]
__device__ __nv_bfloat16 g_vh[NCH];     // [bh][d][t]

// ---------------- mma helpers ----------------
__device__ __forceinline__ void mma16816(float* c, const uint32_t* a, uint32_t b0, uint32_t b1) {
    asm volatile(
        "mma.sync.aligned.m16n8k16.row.col.f32.bf16.bf16.f32 "
        "{%0,%1,%2,%3}, {%4,%5,%6,%7}, {%8,%9}, {%0,%1,%2,%3};"
        : "+f"(c[0]), "+f"(c[1]), "+f"(c[2]), "+f"(c[3])
        : "r"(a[0]), "r"(a[1]), "r"(a[2]), "r"(a[3]), "r"(b0), "r"(b1));
}
__device__ __forceinline__ void mma_tf32(float* c, const uint32_t* a, uint32_t b0, uint32_t b1) {
    asm volatile(
        "mma.sync.aligned.m16n8k8.row.col.f32.tf32.tf32.f32 "
        "{%0,%1,%2,%3}, {%4,%5,%6,%7}, {%8,%9}, {%0,%1,%2,%3};"
        : "+f"(c[0]), "+f"(c[1]), "+f"(c[2]), "+f"(c[3])
        : "r"(a[0]), "r"(a[1]), "r"(a[2]), "r"(a[3]), "r"(b0), "r"(b1));
}
__device__ __forceinline__ uint32_t pack_bf16x2(float hi, float lo) {
    uint32_t w;
    asm("cvt.rn.satfinite.bf16x2.f32 %0, %1, %2;" : "=r"(w) : "f"(hi), "f"(lo));
    return w;
}
__device__ __forceinline__ uint32_t cvt_tf32(float f) {
    uint32_t r;
    asm("cvt.rna.tf32.f32 %0, %1;" : "=r"(r) : "f"(f));
    return r;
}
__device__ __forceinline__ uint4 cvt4_tf32(float4 v) {
    uint4 o;
    o.x = cvt_tf32(v.x); o.y = cvt_tf32(v.y); o.z = cvt_tf32(v.z); o.w = cvt_tf32(v.w);
    return o;
}
// raw exp2 on MUFU (no leading FMUL — operands are pre-scaled by log2e)
__device__ __forceinline__ float ex2(float x) {
    float r;
    asm("ex2.approx.f32 %0, %1;" : "=f"(r) : "f"(x));
    return r;
}

#define LOG2E 1.4426950408889634f

#define AS_STR 36
#define BS_STR 136
#define ASZ (64 * AS_STR)
#define BSZ (32 * BS_STR)

__device__ __forceinline__ void tf32_chunk(
    const uint32_t* Ap, const uint32_t* Bp, float c[2][4][4],
    int warpm, int warpn, int gr, int gc)
{
#pragma unroll
    for (int ks = 0; ks < 4; ks++) {
        uint32_t a[2][4], bq[4][2];
#pragma unroll
        for (int mt = 0; mt < 2; mt++) {
            const uint32_t* ab = Ap + (warpm * 32 + mt * 16) * AS_STR + ks * 8 + gc;
            a[mt][0] = ab[gr * AS_STR];
            a[mt][1] = ab[(gr + 8) * AS_STR];
            a[mt][2] = ab[gr * AS_STR + 4];
            a[mt][3] = ab[(gr + 8) * AS_STR + 4];
        }
#pragma unroll
        for (int nt = 0; nt < 4; nt++) {
            const uint32_t* bb = Bp + (ks * 8 + gc) * BS_STR + warpn * 32 + nt * 8 + gr;
            bq[nt][0] = bb[0];
            bq[nt][1] = bb[4 * BS_STR];
        }
#pragma unroll
        for (int mt = 0; mt < 2; mt++)
#pragma unroll
            for (int nt = 0; nt < 4; nt++)
                mma_tf32(c[mt][nt], a[mt], bq[nt][0], bq[nt][1]);
    }
}

// ---------------- fused QKVW projection + bf16 layout epilogues -----------
__global__ void __launch_bounds__(256) tf32_proj4(
    const float* __restrict__ wq, const float* __restrict__ bq,
    const float* __restrict__ wk, const float* __restrict__ bk,
    const float* __restrict__ wv, const float* __restrict__ bv,
    const float* __restrict__ ww, const float* __restrict__ bw,
    const float* __restrict__ x)
{
    __shared__ uint32_t As[ASZ];
    __shared__ uint32_t Bs[BSZ];
    int tid = threadIdx.x, lane = tid & 31, wid = tid >> 5;
    int gr = lane >> 2, gc = lane & 3;
    int sel  = blockIdx.y >> 2;
    int row0 = (blockIdx.y & 3) * 64;
    const float* W    = sel == 0 ? wq : sel == 1 ? wk : sel == 2 ? wv : ww;
    const float* bias = sel == 0 ? bq : sel == 1 ? bk : sel == 2 ? bv : bw;
    int b = blockIdx.x / 18, hw0 = (blockIdx.x % 18) * 128;
    const float* Bb = x + (size_t)b * CC * HW + hw0;
    int warpm = wid >> 2, warpn = wid & 3;
    float c[2][4][4];
#pragma unroll
    for (int i = 0; i < 2; i++)
#pragma unroll
        for (int j = 0; j < 4; j++)
#pragma unroll
            for (int k = 0; k < 4; k++) c[i][j][k] = 0.f;

    for (int k0 = 0; k0 < 256; k0 += 32) {
#pragma unroll
        for (int i = 0; i < 2; i++) {
            int e = tid + i * 256;
            int r = e >> 3, k4 = (e & 7) * 4;
            float4 w4 = *(const float4*)(W + (size_t)(row0 + r) * 256 + k0 + k4);
            *(uint4*)(As + r * AS_STR + k4) = cvt4_tf32(w4);
        }
#pragma unroll
        for (int i = 0; i < 4; i++) {
            int e = tid + i * 256;
            int k = e >> 5, n4 = (e & 31) * 4;
            float4 v4 = *(const float4*)(Bb + (size_t)(k0 + k) * HW + n4);
            *(uint4*)(Bs + k * BS_STR + n4) = cvt4_tf32(v4);
        }
        __syncthreads();
        tf32_chunk(As, Bs, c, warpm, warpn, gr, gc);
        __syncthreads();
    }

    if (sel == 3) {                       // wf: fp32, [b][c][t]
#pragma unroll
        for (int mt = 0; mt < 2; mt++)
#pragma unroll
            for (int rh = 0; rh < 2; rh++) {
                int r = row0 + warpm * 32 + mt * 16 + rh * 8 + gr;
                float bv2 = bias[r];
#pragma unroll
                for (int nt = 0; nt < 4; nt++) {
                    int col = hw0 + warpn * 32 + nt * 8 + gc * 2;
                    size_t idx = (size_t)b * CC * HW + (size_t)r * HW + col;
                    *(float2*)(g_w + idx) = make_float2(c[mt][nt][rh * 2 + 0] + bv2,
                                                        c[mt][nt][rh * 2 + 1] + bv2);
                }
            }
    } else if (sel == 2) {                // v: bf16 packed, [bh][d][t]
#pragma unroll
        for (int mt = 0; mt < 2; mt++)
#pragma unroll
            for (int rh = 0; rh < 2; rh++) {
                int r = row0 + warpm * 32 + mt * 16 + rh * 8 + gr;
                float bv2 = bias[r];
#pragma unroll
                for (int nt = 0; nt < 4; nt++) {
                    int col = hw0 + warpn * 32 + nt * 8 + gc * 2;
                    size_t idx = (size_t)(b * 256 + r) * HW + col;
                    uint32_t pw = pack_bf16x2(c[mt][nt][rh * 2 + 1] + bv2,
                                              c[mt][nt][rh * 2 + 0] + bv2);
                    *(uint32_t*)(g_vh + idx) = pw;
                }
            }
    } else {                              // q/k: bf16 scatter into [bh][t][d]
        // q is pre-scaled by log2e/sqrt(dk) so flash can use raw exp2
        float scale = sel == 0 ? (LOG2E * 0.17677669529663687f) : 1.0f;
        __nv_bfloat16* dst = sel == 0 ? g_qh : g_kh;
#pragma unroll
        for (int mt = 0; mt < 2; mt++)
#pragma unroll
            for (int rh = 0; rh < 2; rh++) {
                int r = row0 + warpm * 32 + mt * 16 + rh * 8 + gr;
                float bv2 = bias[r];
                size_t hb = (size_t)(b * 8 + (r >> 5)) * HW;
                int d = r & 31;
#pragma unroll
                for (int nt = 0; nt < 4; nt++) {
                    int col = hw0 + warpn * 32 + nt * 8 + gc * 2;
                    float v0 = (c[mt][nt][rh * 2 + 0] + bv2) * scale;
                    float v1 = (c[mt][nt][rh * 2 + 1] + bv2) * scale;
                    dst[(hb + col)     * 32 + d] = __float2bfloat16(v0);
                    dst[(hb + col + 1) * 32 + d] = __float2bfloat16(v1);
                }
            }
    }
}

// ---------------- fused GSA scores + exp (split-tf32, fp32-accurate) ------
// m-channel operands are pre-scaled by log2e (concat_mn), so exp(s)=exp2(s').
#define PAB_STR 68
__global__ void __launch_bounds__(256) pa_softmax()
{
    __shared__ uint32_t Ahi[32 * 36], Alo[32 * 36];
    __shared__ uint32_t Bhi[32 * PAB_STR], Blo[32 * PAB_STR];
    __shared__ float red[32 * 8];
    int tid = threadIdx.x, lane = tid & 31, wid = tid >> 5;
    int gr = lane >> 2, gc = lane & 3;
    int b = blockIdx.y, n0 = blockIdx.x * 32;
    const float* Mp = g_mn + (size_t)b * 64 * HW;
    const float* Np = Mp + (size_t)32 * HW;

    for (int e = tid; e < 1024; e += 256) {
        int ch = e >> 5, n = e & 31;
        float v = Mp[(size_t)ch * HW + n0 + n];
        uint32_t h = cvt_tf32(v);
        Ahi[n * 36 + ch] = h;
        Alo[n * 36 + ch] = cvt_tf32(v - __uint_as_float(h));
    }

    int bm = tid & 63, bc0 = tid >> 6;
    float rbv[8];
#pragma unroll
    for (int i = 0; i < 8; i++)
        rbv[i] = Np[(size_t)(bc0 + i * 4) * HW + bm];

    float rs[2][2] = {{0.f, 0.f}, {0.f, 0.f}};
    float* pab = g_pa + (size_t)b * HW * HW;
    __syncthreads();

    for (int t = 0; t < 36; t++) {
#pragma unroll
        for (int i = 0; i < 8; i++) {
            int ch = bc0 + i * 4;
            uint32_t h = cvt_tf32(rbv[i]);
            Bhi[ch * PAB_STR + bm] = h;
            Blo[ch * PAB_STR + bm] = cvt_tf32(rbv[i] - __uint_as_float(h));
        }
        __syncthreads();
        if (t + 1 < 36) {
#pragma unroll
            for (int i = 0; i < 8; i++)
                rbv[i] = Np[(size_t)(bc0 + i * 4) * HW + (t + 1) * 64 + bm];
        }
        float c[2][4];
#pragma unroll
        for (int mt = 0; mt < 2; mt++)
#pragma unroll
            for (int j = 0; j < 4; j++) c[mt][j] = 0.f;
#pragma unroll
        for (int ks = 0; ks < 4; ks++) {
            uint32_t ah[2][4], al[2][4];
#pragma unroll
            for (int mt = 0; mt < 2; mt++) {
                int rb = mt * 16;
                ah[mt][0] = Ahi[(rb + gr) * 36 + ks * 8 + gc];
                ah[mt][1] = Ahi[(rb + gr + 8) * 36 + ks * 8 + gc];
                ah[mt][2] = Ahi[(rb + gr) * 36 + ks * 8 + gc + 4];
                ah[mt][3] = Ahi[(rb + gr + 8) * 36 + ks * 8 + gc + 4];
                al[mt][0] = Alo[(rb + gr) * 36 + ks * 8 + gc];
                al[mt][1] = Alo[(rb + gr + 8) * 36 + ks * 8 + gc];
                al[mt][2] = Alo[(rb + gr) * 36 + ks * 8 + gc + 4];
                al[mt][3] = Alo[(rb + gr + 8) * 36 + ks * 8 + gc + 4];
            }
            int colb = wid * 8 + gr;
            uint32_t bh0 = Bhi[(ks * 8 + gc) * PAB_STR + colb];
            uint32_t bh1 = Bhi[(ks * 8 + gc + 4) * PAB_STR + colb];
            uint32_t bl0 = Blo[(ks * 8 + gc) * PAB_STR + colb];
            uint32_t bl1 = Blo[(ks * 8 + gc + 4) * PAB_STR + colb];
#pragma unroll
            for (int mt = 0; mt < 2; mt++) {
                mma_tf32(c[mt], ah[mt], bh0, bh1);
                mma_tf32(c[mt], ah[mt], bl0, bl1);
                mma_tf32(c[mt], al[mt], bh0, bh1);
            }
        }
        int m_base = t * 64 + wid * 8 + gc * 2;
#pragma unroll
        for (int mt = 0; mt < 2; mt++)
#pragma unroll
            for (int rh = 0; rh < 2; rh++) {
                float p0 = ex2(c[mt][rh * 2 + 0]);
                float p1 = ex2(c[mt][rh * 2 + 1]);
                rs[mt][rh] += p0 + p1;
                int n = n0 + mt * 16 + rh * 8 + gr;
                *(float2*)(pab + (size_t)n * HW + m_base) = make_float2(p0, p1);
            }
        __syncthreads();
    }

#pragma unroll
    for (int mt = 0; mt < 2; mt++)
#pragma unroll
        for (int rh = 0; rh < 2; rh++) {
            float v = rs[mt][rh];
            v += __shfl_xor_sync(0xffffffffu, v, 1);
            v += __shfl_xor_sync(0xffffffffu, v, 2);
            if (gc == 0) red[(mt * 16 + rh * 8 + gr) * 8 + wid] = v;
        }
    __syncthreads();
    if (tid < 32) {
        float s = 0.f;
#pragma unroll
        for (int w = 0; w < 8; w++) s += red[tid * 8 + w];
        g_l[(size_t)b * HW + n0 + tid] = s;
    }
}

// ---------------- double-buffered tf32 GSA: gsa = (wf @ pa^T) / l ---------
__global__ void __launch_bounds__(256) tf32_gsa()
{
    extern __shared__ uint32_t dsm[];
    uint32_t* As = dsm;
    uint32_t* Bs = dsm + 2 * ASZ;
    int tid = threadIdx.x, lane = tid & 31, wid = tid >> 5;
    int gr = lane >> 2, gc = lane & 3;
    int c0 = blockIdx.y * 64;
    int b = blockIdx.x / 18, n0 = (blockIdx.x % 18) * 128;
    const float* wfb = g_w + (size_t)b * CC * HW;
    const float* pab = g_pa + (size_t)b * HW * HW;
    int warpm = wid >> 2, warpn = wid & 3;

    int ar = tid >> 3, ak4 = (tid & 7) * 4;
    int ar2 = (tid + 256) >> 3;
    int bn = tid & 127, bk4_0 = (tid >> 7) * 4;

    float4 ra[2], rb[4];
#pragma unroll
    for (int i = 0; i < 2; i++) {
        int r = (i == 0) ? ar : ar2;
        ra[i] = *(const float4*)(wfb + (size_t)(c0 + r) * HW + 0 + ak4);
    }
#pragma unroll
    for (int i = 0; i < 4; i++)
        rb[i] = *(const float4*)(pab + (size_t)(n0 + bn) * HW + 0 + (bk4_0 + i * 8));
#pragma unroll
    for (int i = 0; i < 2; i++) {
        int r = (i == 0) ? ar : ar2;
        *(uint4*)(As + r * AS_STR + ak4) = cvt4_tf32(ra[i]);
    }
#pragma unroll
    for (int i = 0; i < 4; i++) {
        int k4 = bk4_0 + i * 8;
        Bs[(k4 + 0) * BS_STR + bn] = cvt_tf32(rb[i].x);
        Bs[(k4 + 1) * BS_STR + bn] = cvt_tf32(rb[i].y);
        Bs[(k4 + 2) * BS_STR + bn] = cvt_tf32(rb[i].z);
        Bs[(k4 + 3) * BS_STR + bn] = cvt_tf32(rb[i].w);
    }
    __syncthreads();

    float c[2][4][4];
#pragma unroll
    for (int i = 0; i < 2; i++)
#pragma unroll
        for (int j = 0; j < 4; j++)
#pragma unroll
            for (int k = 0; k < 4; k++) c[i][j][k] = 0.f;

    for (int it = 0; it < 72; it++) {
        int p = it & 1;
        int m1 = (it + 1) * 32;
        if (it + 1 < 72) {
#pragma unroll
            for (int i = 0; i < 2; i++) {
                int r = (i == 0) ? ar : ar2;
                ra[i] = *(const float4*)(wfb + (size_t)(c0 + r) * HW + m1 + ak4);
            }
#pragma unroll
            for (int i = 0; i < 4; i++)
                rb[i] = *(const float4*)(pab + (size_t)(n0 + bn) * HW + m1 + (bk4_0 + i * 8));
        }
        tf32_chunk(As + p * ASZ, Bs + p * BSZ, c, warpm, warpn, gr, gc);
        if (it + 1 < 72) {
            uint32_t* Ad = As + (p ^ 1) * ASZ;
            uint32_t* Bd = Bs + (p ^ 1) * BSZ;
#pragma unroll
            for (int i = 0; i < 2; i++) {
                int r = (i == 0) ? ar : ar2;
                *(uint4*)(Ad + r * AS_STR + ak4) = cvt4_tf32(ra[i]);
            }
#pragma unroll
            for (int i = 0; i < 4; i++) {
                int k4 = bk4_0 + i * 8;
                Bd[(k4 + 0) * BS_STR + bn] = cvt_tf32(rb[i].x);
                Bd[(k4 + 1) * BS_STR + bn] = cvt_tf32(rb[i].y);
                Bd[(k4 + 2) * BS_STR + bn] = cvt_tf32(rb[i].z);
                Bd[(k4 + 3) * BS_STR + bn] = cvt_tf32(rb[i].w);
            }
        }
        __syncthreads();
    }

    float inv[4][2];
#pragma unroll
    for (int nt = 0; nt < 4; nt++) {
        int col = n0 + warpn * 32 + nt * 8 + gc * 2;
        inv[nt][0] = 1.f / g_l[(size_t)b * HW + col];
        inv[nt][1] = 1.f / g_l[(size_t)b * HW + col + 1];
    }
    float* ob = g_gsa + (size_t)b * CC * HW;
#pragma unroll
    for (int mt = 0; mt < 2; mt++)
#pragma unroll
        for (int rh = 0; rh < 2; rh++) {
            int r = c0 + warpm * 32 + mt * 16 + rh * 8 + gr;
#pragma unroll
            for (int nt = 0; nt < 4; nt++) {
                int col = n0 + warpn * 32 + nt * 8 + gc * 2;
                *(float2*)(ob + (size_t)r * HW + col) =
                    make_float2(c[mt][nt][rh * 2 + 0] * inv[nt][0],
                                c[mt][nt][rh * 2 + 1] * inv[nt][1]);
            }
        }
}

// ---------------- double-buffered final GEMM + fusion epilogue ------------
__global__ void __launch_bounds__(256) tf32_final(
    const float* __restrict__ wo, const float* __restrict__ bo,
    const float* __restrict__ xin,
    const float* __restrict__ gt_p, const float* __restrict__ gg_p,
    float* __restrict__ out)
{
    extern __shared__ uint32_t dsm[];
    uint32_t* As = dsm;
    uint32_t* Bs = dsm + 2 * ASZ;
    int tid = threadIdx.x, lane = tid & 31, wid = tid >> 5;
    int gr = lane >> 2, gc = lane & 3;
    int row0 = blockIdx.y * 64;
    int b = blockIdx.x / 18, hw0 = (blockIdx.x % 18) * 128;
    const float* Bb = g_gsa + (size_t)b * CC * HW + hw0;
    int warpm = wid >> 2, warpn = wid & 3;

    int ar = tid >> 3, ak4 = (tid & 7) * 4;
    int ar2 = (tid + 256) >> 3;
    int bk = tid >> 5, bn4 = (tid & 31) * 4;

    float4 ra[2], rb[4];
#pragma unroll
    for (int i = 0; i < 2; i++) {
        int r = (i == 0) ? ar : ar2;
        ra[i] = *(const float4*)(wo + (size_t)(row0 + r) * 256 + 0 + ak4);
    }
#pragma unroll
    for (int i = 0; i < 4; i++)
        rb[i] = *(const float4*)(Bb + (size_t)(0 + bk + i * 8) * HW + bn4);
#pragma unroll
    for (int i = 0; i < 2; i++) {
        int r = (i == 0) ? ar : ar2;
        *(uint4*)(As + r * AS_STR + ak4) = cvt4_tf32(ra[i]);
    }
#pragma unroll
    for (int i = 0; i < 4; i++)
        *(uint4*)(Bs + (bk + i * 8) * BS_STR + bn4) = cvt4_tf32(rb[i]);
    __syncthreads();

    float c[2][4][4];
#pragma unroll
    for (int i = 0; i < 2; i++)
#pragma unroll
        for (int j = 0; j < 4; j++)
#pragma unroll
            for (int k = 0; k < 4; k++) c[i][j][k] = 0.f;

    for (int it = 0; it < 8; it++) {
        int p = it & 1;
        int k1 = (it + 1) * 32;
        if (it + 1 < 8) {
#pragma unroll
            for (int i = 0; i < 2; i++) {
                int r = (i == 0) ? ar : ar2;
                ra[i] = *(const float4*)(wo + (size_t)(row0 + r) * 256 + k1 + ak4);
            }
#pragma unroll
            for (int i = 0; i < 4; i++)
                rb[i] = *(const float4*)(Bb + (size_t)(k1 + bk + i * 8) * HW + bn4);
        }
        tf32_chunk(As + p * ASZ, Bs + p * BSZ, c, warpm, warpn, gr, gc);
        if (it + 1 < 8) {
            uint32_t* Ad = As + (p ^ 1) * ASZ;
            uint32_t* Bd = Bs + (p ^ 1) * BSZ;
#pragma unroll
            for (int i = 0; i < 2; i++) {
                int r = (i == 0) ? ar : ar2;
                *(uint4*)(Ad + r * AS_STR + ak4) = cvt4_tf32(ra[i]);
            }
#pragma unroll
            for (int i = 0; i < 4; i++)
                *(uint4*)(Bd + (bk + i * 8) * BS_STR + bn4) = cvt4_tf32(rb[i]);
        }
        __syncthreads();
    }

    float gt = gt_p[0], gg = gg_p[0];
#pragma unroll
    for (int mt = 0; mt < 2; mt++)
#pragma unroll
        for (int rh = 0; rh < 2; rh++) {
            int r = row0 + warpm * 32 + mt * 16 + rh * 8 + gr;
            float bv = bo[r];
#pragma unroll
            for (int nt = 0; nt < 4; nt++) {
                int col = hw0 + warpn * 32 + nt * 8 + gc * 2;
                size_t idx = (size_t)b * CC * HW + (size_t)r * HW + col;
                float2 x2 = *(const float2*)(xin + idx);
                float2 t2 = *(const float2*)(g_tsa + idx);
                float2 o2;
                o2.x = gt * t2.x + gg * (c[mt][nt][rh * 2 + 0] + bv) + x2.x;
                o2.y = gt * t2.y + gg * (c[mt][nt][rh * 2 + 1] + bv) + x2.y;
                *(float2*)(out + idx) = o2;
            }
        }
}

// ---------------- fp32 proj (m/n, concentration-sensitive) ----------------
__global__ void __launch_bounds__(256) proj_gemm(
    const float* __restrict__ W, const float* __restrict__ bias,
    const float* __restrict__ x, float* __restrict__ out, int Co)
{
    __shared__ float As[16][64];
    __shared__ float Bs[16][64];
    int jt  = blockIdx.x;
    int o0  = blockIdx.y * 64;
    int b   = (jt * 64) / HW;
    int hw0 = (jt * 64) % HW;
    const float* xb = x + (size_t)b * CC * HW + hw0;
    int tid = threadIdx.x;
    int tx = tid & 15, ty = tid >> 4;
    float acc[4][4];
#pragma unroll
    for (int i = 0; i < 4; i++)
#pragma unroll
        for (int j = 0; j < 4; j++) acc[i][j] = 0.f;

    int lo  = tid >> 2;
    int lk4 = (tid & 3) * 4;
    int bk  = tid >> 4;
    int bj4 = (tid & 15) * 4;

    for (int k0 = 0; k0 < CC; k0 += 16) {
        float4 wv = make_float4(0.f, 0.f, 0.f, 0.f);
        if (o0 + lo < Co)
            wv = *(const float4*)(W + (size_t)(o0 + lo) * CC + k0 + lk4);
        As[lk4 + 0][lo] = wv.x; As[lk4 + 1][lo] = wv.y;
        As[lk4 + 2][lo] = wv.z; As[lk4 + 3][lo] = wv.w;
        float4 xv = *(const float4*)(xb + (size_t)(k0 + bk) * HW + bj4);
        *(float4*)&Bs[bk][bj4] = xv;
        __syncthreads();
#pragma unroll
        for (int k = 0; k < 16; k++) {
            float4 a  = *(float4*)&As[k][ty * 4];
            float4 bb = *(float4*)&Bs[k][tx * 4];
            float av[4] = {a.x, a.y, a.z, a.w};
            float bv[4] = {bb.x, bb.y, bb.z, bb.w};
#pragma unroll
            for (int i = 0; i < 4; i++)
#pragma unroll
                for (int j = 0; j < 4; j++)
                    acc[i][j] = fmaf(av[i], bv[j], acc[i][j]);
        }
        __syncthreads();
    }
#pragma unroll
    for (int i = 0; i < 4; i++) {
        int o = o0 + ty * 4 + i;
        if (o < Co) {
            float bsv = bias[o];
            float4 ov = make_float4(acc[i][0] + bsv, acc[i][1] + bsv,
                                    acc[i][2] + bsv, acc[i][3] + bsv);
            *(float4*)(out + (size_t)b * Co * HW + (size_t)o * HW + hw0 + tx * 4) = ov;
        }
    }
}

// wm/bm are pre-scaled by log2e so pa_softmax can use raw exp2.
__global__ void __launch_bounds__(256) concat_mn(
    const float* __restrict__ wm, const float* __restrict__ bm,
    const float* __restrict__ wn, const float* __restrict__ bn)
{
    int i = blockIdx.x * 256 + threadIdx.x;
    if (i < 32 * 256) { g_wmn[i] = wm[i] * LOG2E; g_wmn[32 * 256 + i] = wn[i]; }
    if (i < 32) { g_bmn[i] = bm[i] * LOG2E; g_bmn[32 + i] = bn[i]; }
}

// ---------------- FA2-style flash TSA with mma.sync bf16 ----------------
// R11 winner + exp2 fold: q pre-scaled by log2e/sqrt(dk), raw ex2 here.
#define QS_STR 40
#define VS_STR 136
__global__ void __launch_bounds__(256) flash_mma()
{
    __shared__ __nv_bfloat16 Qs[128 * QS_STR];
    __shared__ __nv_bfloat16 Ks[128 * QS_STR];
    __shared__ __nv_bfloat16 Vs[32 * VS_STR];
    int tid = threadIdx.x, wid = tid >> 5, lane = tid & 31;
    int bh = blockIdx.y, i0 = blockIdx.x * 128;
    int gr = lane >> 2, gc = (lane & 3) * 2;

    const __nv_bfloat16* qsrc = g_qh + ((size_t)bh * HW + i0) * DK;
    const __nv_bfloat16* ksrc = g_kh + (size_t)bh * HW * DK;
    const __nv_bfloat16* vsrc = g_vh + (size_t)bh * DK * HW;

    for (int e = tid; e < 512; e += 256) {
        int r = e >> 2, c8 = (e & 3) * 8;
        *(uint4*)(Qs + r * QS_STR + c8) = *(const uint4*)(qsrc + r * DK + c8);
    }
    __syncthreads();

    uint32_t qa[2][4];
    {
        const __nv_bfloat16* qb = Qs + (wid * 16 + gr) * QS_STR;
#pragma unroll
        for (int kc = 0; kc < 2; kc++) {
            qa[kc][0] = *(const uint32_t*)(qb + kc * 16 + gc);
            qa[kc][1] = *(const uint32_t*)(qb + 8 * QS_STR + kc * 16 + gc);
            qa[kc][2] = *(const uint32_t*)(qb + kc * 16 + gc + 8);
            qa[kc][3] = *(const uint32_t*)(qb + 8 * QS_STR + kc * 16 + gc + 8);
        }
    }

    int kr  = tid >> 2,        kc8 = (tid & 3) * 8;
    int kr1 = (tid + 256) >> 2;
    int vd  = tid >> 4,        vc8 = (tid & 15) * 8;
    int vd1 = (tid + 256) >> 4;

    uint4 kreg[2], vreg[2];
    kreg[0] = *(const uint4*)(ksrc + (size_t)kr  * DK + kc8);
    kreg[1] = *(const uint4*)(ksrc + (size_t)kr1 * DK + kc8);
    vreg[0] = *(const uint4*)(vsrc + (size_t)vd  * HW + vc8);
    vreg[1] = *(const uint4*)(vsrc + (size_t)vd1 * HW + vc8);

    float o[4][4];
#pragma unroll
    for (int i = 0; i < 4; i++)
#pragma unroll
        for (int j = 0; j < 4; j++) o[i][j] = 0.f;
    float l0 = 0.f, l1 = 0.f;

    for (int kt = 0; kt < 18; kt++) {
        __syncthreads();
        *(uint4*)(Ks + kr  * QS_STR + kc8) = kreg[0];
        *(uint4*)(Ks + kr1 * QS_STR + kc8) = kreg[1];
        *(uint4*)(Vs + vd  * VS_STR + vc8) = vreg[0];
        *(uint4*)(Vs + vd1 * VS_STR + vc8) = vreg[1];
        __syncthreads();
        if (kt + 1 < 18) {
            int j1 = (kt + 1) * 128;
            kreg[0] = *(const uint4*)(ksrc + (size_t)(j1 + kr)  * DK + kc8);
            kreg[1] = *(const uint4*)(ksrc + (size_t)(j1 + kr1) * DK + kc8);
            vreg[0] = *(const uint4*)(vsrc + (size_t)vd  * HW + j1 + vc8);
            vreg[1] = *(const uint4*)(vsrc + (size_t)vd1 * HW + j1 + vc8);
        }

        float s[16][4];
#pragma unroll
        for (int nt = 0; nt < 16; nt++) {
            s[nt][0] = 0.f; s[nt][1] = 0.f; s[nt][2] = 0.f; s[nt][3] = 0.f;
            const __nv_bfloat16* kb = Ks + (nt * 8 + gr) * QS_STR;
#pragma unroll
            for (int kc = 0; kc < 2; kc++) {
                uint32_t b0 = *(const uint32_t*)(kb + kc * 16 + gc);
                uint32_t b1 = *(const uint32_t*)(kb + kc * 16 + gc + 8);
                mma16816(s[nt], qa[kc], b0, b1);
            }
        }

        uint32_t pa_[8][4];
#pragma unroll
        for (int h2 = 0; h2 < 8; h2++) {
            float e00 = ex2(s[2 * h2][0]),     e01 = ex2(s[2 * h2][1]);
            float e02 = ex2(s[2 * h2][2]),     e03 = ex2(s[2 * h2][3]);
            float f00 = ex2(s[2 * h2 + 1][0]), f01 = ex2(s[2 * h2 + 1][1]);
            float f02 = ex2(s[2 * h2 + 1][2]), f03 = ex2(s[2 * h2 + 1][3]);
            l0 += (e00 + e01) + (f00 + f01);
            l1 += (e02 + e03) + (f02 + f03);
            pa_[h2][0] = pack_bf16x2(e01, e00);
            pa_[h2][1] = pack_bf16x2(e03, e02);
            pa_[h2][2] = pack_bf16x2(f01, f00);
            pa_[h2][3] = pack_bf16x2(f03, f02);
        }

#pragma unroll
        for (int kc2 = 0; kc2 < 8; kc2++) {
#pragma unroll
            for (int dt = 0; dt < 4; dt++) {
                const __nv_bfloat16* vb = Vs + (dt * 8 + gr) * VS_STR + kc2 * 16 + gc;
                uint32_t b0 = *(const uint32_t*)(vb);
                uint32_t b1 = *(const uint32_t*)(vb + 8);
                mma16816(o[dt], pa_[kc2], b0, b1);
            }
        }
    }

    l0 += __shfl_xor_sync(0xffffffffu, l0, 1);
    l0 += __shfl_xor_sync(0xffffffffu, l0, 2);
    l1 += __shfl_xor_sync(0xffffffffu, l1, 1);
    l1 += __shfl_xor_sync(0xffffffffu, l1, 2);
    float inv0 = 1.f / l0, inv1 = 1.f / l1;

    int b = bh >> 3, h = bh & 7;
    float* ob = g_tsa + ((size_t)b * CC + h * DK) * HW;
    int tok0 = i0 + wid * 16 + gr;
#pragma unroll
    for (int dt = 0; dt < 4; dt++) {
        int d = dt * 8 + gc;
        ob[(size_t)(d)     * HW + tok0]     = o[dt][0] * inv0;
        ob[(size_t)(d + 1) * HW + tok0]     = o[dt][1] * inv0;
        ob[(size_t)(d)     * HW + tok0 + 8] = o[dt][2] * inv1;
        ob[(size_t)(d + 1) * HW + tok0 + 8] = o[dt][3] * inv1;
    }
}

// ---------------- launch ----------------
extern "C" void kernel_launch(void* const* d_in, const int* in_sizes, int n_in,
                              void* d_out, int out_size)
{
    const float* x   = (const float*)d_in[0];
    const float* wq  = (const float*)d_in[1];
    const float* bq  = (const float*)d_in[2];
    const float* wk  = (const float*)d_in[3];
    const float* bk  = (const float*)d_in[4];
    const float* wv  = (const float*)d_in[5];
    const float* bv  = (const float*)d_in[6];
    const float* wm  = (const float*)d_in[7];
    const float* bm  = (const float*)d_in[8];
    const float* wn  = (const float*)d_in[9];
    const float* bn  = (const float*)d_in[10];
    const float* ww  = (const float*)d_in[11];
    const float* bw  = (const float*)d_in[12];
    const float* wo  = (const float*)d_in[13];
    const float* bo  = (const float*)d_in[14];
    const float* gts = (const float*)d_in[15];
    const float* ggs = (const float*)d_in[16];
    float* out = (float*)d_out;

    float *pmn, *pwmn, *pbmn;
    cudaGetSymbolAddress((void**)&pmn, g_mn);
    cudaGetSymbolAddress((void**)&pwmn, g_wmn);
    cudaGetSymbolAddress((void**)&pbmn, g_bmn);

    static int smem_set = 0;
    const int DBUF_SMEM = (2 * ASZ + 2 * BSZ) * 4;   // 53248 B
    if (!smem_set) {
        cudaFuncSetAttribute(tf32_gsa, cudaFuncAttributeMaxDynamicSharedMemorySize, DBUF_SMEM);
        cudaFuncSetAttribute(tf32_final, cudaFuncAttributeMaxDynamicSharedMemorySize, DBUF_SMEM);
        smem_set = 1;
    }

    dim3 blk(256);

    concat_mn<<<32, blk>>>(wm, bm, wn, bn);

    tf32_proj4<<<dim3(36, 16), blk>>>(wq, bq, wk, bk, wv, bv, ww, bw, x);
    proj_gemm<<<dim3(BB * HW / 64, 1), blk>>>(pwmn, pbmn, x, pmn, 64);

    flash_mma<<<dim3(HW / 128, BB * HEADS), blk>>>();

    pa_softmax<<<dim3(HW / 32, BB), blk>>>();
    tf32_gsa<<<dim3(36, 4), blk, DBUF_SMEM>>>();

    tf32_final<<<dim3(36, 4), blk, DBUF_SMEM>>>(wo, bo, x, gts, ggs, out);
}

// round 13
// speedup vs baseline: 1.1074x; 1.0018x over previous
#include <cuda_runtime.h>
#include <cuda_bf16.h>
#include <cstdint>

#define BB    2
#define CC    256
#define HW    2304
#define HEADS 8
#define DK    32
#define CR    32
#define NCH   (BB*CC*HW)

// ---------------- scratch (device globals; no allocation) ----------------
__device__ float g_w[NCH];              // wf projection (fp32)
__device__ float g_mn[BB*64*HW];        // m (rows 0-31, pre-scaled by log2e) and n (rows 32-63)
__device__ float g_wmn[64*256];
__device__ float g_bmn[64];
__device__ float g_tsa[NCH];
__device__ float g_gsa[NCH];
__device__ float g_l[BB*HW];            // GSA softmax row sums
__device__ float g_pa[(size_t)BB*HW*HW]; // unnormalized exp(scores), 42.5 MB
__device__ __nv_bfloat16 g_qh[NCH];     // [bh][t][d], pre-scaled by log2e/sqrt(dk)
__device__ __nv_bfloat16 g_kh[NCH];     // [bh][t][d]
__device__ __nv_bfloat16 g_vh[NCH];     // [bh][d][t]

// ---------------- mma helpers ----------------
__device__ __forceinline__ void mma16816(float* c, const uint32_t* a, uint32_t b0, uint32_t b1) {
    asm volatile(
        "mma.sync.aligned.m16n8k16.row.col.f32.bf16.bf16.f32 "
        "{%0,%1,%2,%3}, {%4,%5,%6,%7}, {%8,%9}, {%0,%1,%2,%3};"
        : "+f"(c[0]), "+f"(c[1]), "+f"(c[2]), "+f"(c[3])
        : "r"(a[0]), "r"(a[1]), "r"(a[2]), "r"(a[3]), "r"(b0), "r"(b1));
}
__device__ __forceinline__ void mma_tf32(float* c, const uint32_t* a, uint32_t b0, uint32_t b1) {
    asm volatile(
        "mma.sync.aligned.m16n8k8.row.col.f32.tf32.tf32.f32 "
        "{%0,%1,%2,%3}, {%4,%5,%6,%7}, {%8,%9}, {%0,%1,%2,%3};"
        : "+f"(c[0]), "+f"(c[1]), "+f"(c[2]), "+f"(c[3])
        : "r"(a[0]), "r"(a[1]), "r"(a[2]), "r"(a[3]), "r"(b0), "r"(b1));
}
__device__ __forceinline__ uint32_t pack_bf16x2(float hi, float lo) {
    uint32_t w;
    asm("cvt.rn.satfinite.bf16x2.f32 %0, %1, %2;" : "=r"(w) : "f"(hi), "f"(lo));
    return w;
}
__device__ __forceinline__ uint32_t cvt_tf32(float f) {
    uint32_t r;
    asm("cvt.rna.tf32.f32 %0, %1;" : "=r"(r) : "f"(f));
    return r;
}
__device__ __forceinline__ uint4 cvt4_tf32(float4 v) {
    uint4 o;
    o.x = cvt_tf32(v.x); o.y = cvt_tf32(v.y); o.z = cvt_tf32(v.z); o.w = cvt_tf32(v.w);
    return o;
}
__device__ __forceinline__ float ex2(float x) {
    float r;
    asm("ex2.approx.f32 %0, %1;" : "=f"(r) : "f"(x));
    return r;
}

#define LOG2E 1.4426950408889634f

#define AS_STR 36
#define BS_STR 136
#define ASZ (64 * AS_STR)
#define BSZ (32 * BS_STR)

__device__ __forceinline__ void tf32_chunk(
    const uint32_t* Ap, const uint32_t* Bp, float c[2][4][4],
    int warpm, int warpn, int gr, int gc)
{
#pragma unroll
    for (int ks = 0; ks < 4; ks++) {
        uint32_t a[2][4], bq[4][2];
#pragma unroll
        for (int mt = 0; mt < 2; mt++) {
            const uint32_t* ab = Ap + (warpm * 32 + mt * 16) * AS_STR + ks * 8 + gc;
            a[mt][0] = ab[gr * AS_STR];
            a[mt][1] = ab[(gr + 8) * AS_STR];
            a[mt][2] = ab[gr * AS_STR + 4];
            a[mt][3] = ab[(gr + 8) * AS_STR + 4];
        }
#pragma unroll
        for (int nt = 0; nt < 4; nt++) {
            const uint32_t* bb = Bp + (ks * 8 + gc) * BS_STR + warpn * 32 + nt * 8 + gr;
            bq[nt][0] = bb[0];
            bq[nt][1] = bb[4 * BS_STR];
        }
#pragma unroll
        for (int mt = 0; mt < 2; mt++)
#pragma unroll
            for (int nt = 0; nt < 4; nt++)
                mma_tf32(c[mt][nt], a[mt], bq[nt][0], bq[nt][1]);
    }
}

// ---------------- fused QKVW projection + bf16 layout epilogues -----------
__global__ void __launch_bounds__(256) tf32_proj4(
    const float* __restrict__ wq, const float* __restrict__ bq,
    const float* __restrict__ wk, const float* __restrict__ bk,
    const float* __restrict__ wv, const float* __restrict__ bv,
    const float* __restrict__ ww, const float* __restrict__ bw,
    const float* __restrict__ x)
{
    __shared__ uint32_t As[ASZ];
    __shared__ uint32_t Bs[BSZ];
    int tid = threadIdx.x, lane = tid & 31, wid = tid >> 5;
    int gr = lane >> 2, gc = lane & 3;
    int sel  = blockIdx.y >> 2;
    int row0 = (blockIdx.y & 3) * 64;
    const float* W    = sel == 0 ? wq : sel == 1 ? wk : sel == 2 ? wv : ww;
    const float* bias = sel == 0 ? bq : sel == 1 ? bk : sel == 2 ? bv : bw;
    int b = blockIdx.x / 18, hw0 = (blockIdx.x % 18) * 128;
    const float* Bb = x + (size_t)b * CC * HW + hw0;
    int warpm = wid >> 2, warpn = wid & 3;
    float c[2][4][4];
#pragma unroll
    for (int i = 0; i < 2; i++)
#pragma unroll
        for (int j = 0; j < 4; j++)
#pragma unroll
            for (int k = 0; k < 4; k++) c[i][j][k] = 0.f;

    for (int k0 = 0; k0 < 256; k0 += 32) {
#pragma unroll
        for (int i = 0; i < 2; i++) {
            int e = tid + i * 256;
            int r = e >> 3, k4 = (e & 7) * 4;
            float4 w4 = *(const float4*)(W + (size_t)(row0 + r) * 256 + k0 + k4);
            *(uint4*)(As + r * AS_STR + k4) = cvt4_tf32(w4);
        }
#pragma unroll
        for (int i = 0; i < 4; i++) {
            int e = tid + i * 256;
            int k = e >> 5, n4 = (e & 31) * 4;
            float4 v4 = *(const float4*)(Bb + (size_t)(k0 + k) * HW + n4);
            *(uint4*)(Bs + k * BS_STR + n4) = cvt4_tf32(v4);
        }
        __syncthreads();
        tf32_chunk(As, Bs, c, warpm, warpn, gr, gc);
        __syncthreads();
    }

    if (sel == 3) {                       // wf: fp32, [b][c][t]
#pragma unroll
        for (int mt = 0; mt < 2; mt++)
#pragma unroll
            for (int rh = 0; rh < 2; rh++) {
                int r = row0 + warpm * 32 + mt * 16 + rh * 8 + gr;
                float bv2 = bias[r];
#pragma unroll
                for (int nt = 0; nt < 4; nt++) {
                    int col = hw0 + warpn * 32 + nt * 8 + gc * 2;
                    size_t idx = (size_t)b * CC * HW + (size_t)r * HW + col;
                    *(float2*)(g_w + idx) = make_float2(c[mt][nt][rh * 2 + 0] + bv2,
                                                        c[mt][nt][rh * 2 + 1] + bv2);
                }
            }
    } else if (sel == 2) {                // v: bf16 packed, [bh][d][t]
#pragma unroll
        for (int mt = 0; mt < 2; mt++)
#pragma unroll
            for (int rh = 0; rh < 2; rh++) {
                int r = row0 + warpm * 32 + mt * 16 + rh * 8 + gr;
                float bv2 = bias[r];
#pragma unroll
                for (int nt = 0; nt < 4; nt++) {
                    int col = hw0 + warpn * 32 + nt * 8 + gc * 2;
                    size_t idx = (size_t)(b * 256 + r) * HW + col;
                    uint32_t pw = pack_bf16x2(c[mt][nt][rh * 2 + 1] + bv2,
                                              c[mt][nt][rh * 2 + 0] + bv2);
                    *(uint32_t*)(g_vh + idx) = pw;
                }
            }
    } else {                              // q/k: bf16 scatter into [bh][t][d]
        float scale = sel == 0 ? (LOG2E * 0.17677669529663687f) : 1.0f;
        __nv_bfloat16* dst = sel == 0 ? g_qh : g_kh;
#pragma unroll
        for (int mt = 0; mt < 2; mt++)
#pragma unroll
            for (int rh = 0; rh < 2; rh++) {
                int r = row0 + warpm * 32 + mt * 16 + rh * 8 + gr;
                float bv2 = bias[r];
                size_t hb = (size_t)(b * 8 + (r >> 5)) * HW;
                int d = r & 31;
#pragma unroll
                for (int nt = 0; nt < 4; nt++) {
                    int col = hw0 + warpn * 32 + nt * 8 + gc * 2;
                    float v0 = (c[mt][nt][rh * 2 + 0] + bv2) * scale;
                    float v1 = (c[mt][nt][rh * 2 + 1] + bv2) * scale;
                    dst[(hb + col)     * 32 + d] = __float2bfloat16(v0);
                    dst[(hb + col + 1) * 32 + d] = __float2bfloat16(v1);
                }
            }
    }
}

// ---------------- fused GSA scores + exp (split-tf32, fp32-accurate) ------
#define PAB_STR 68
__global__ void __launch_bounds__(256) pa_softmax()
{
    __shared__ uint32_t Ahi[32 * 36], Alo[32 * 36];
    __shared__ uint32_t Bhi[32 * PAB_STR], Blo[32 * PAB_STR];
    __shared__ float red[32 * 8];
    int tid = threadIdx.x, lane = tid & 31, wid = tid >> 5;
    int gr = lane >> 2, gc = lane & 3;
    int b = blockIdx.y, n0 = blockIdx.x * 32;
    const float* Mp = g_mn + (size_t)b * 64 * HW;
    const float* Np = Mp + (size_t)32 * HW;

    for (int e = tid; e < 1024; e += 256) {
        int ch = e >> 5, n = e & 31;
        float v = Mp[(size_t)ch * HW + n0 + n];
        uint32_t h = cvt_tf32(v);
        Ahi[n * 36 + ch] = h;
        Alo[n * 36 + ch] = cvt_tf32(v - __uint_as_float(h));
    }

    int bm = tid & 63, bc0 = tid >> 6;
    float rbv[8];
#pragma unroll
    for (int i = 0; i < 8; i++)
        rbv[i] = Np[(size_t)(bc0 + i * 4) * HW + bm];

    float rs[2][2] = {{0.f, 0.f}, {0.f, 0.f}};
    float* pab = g_pa + (size_t)b * HW * HW;
    __syncthreads();

    for (int t = 0; t < 36; t++) {
#pragma unroll
        for (int i = 0; i < 8; i++) {
            int ch = bc0 + i * 4;
            uint32_t h = cvt_tf32(rbv[i]);
            Bhi[ch * PAB_STR + bm] = h;
            Blo[ch * PAB_STR + bm] = cvt_tf32(rbv[i] - __uint_as_float(h));
        }
        __syncthreads();
        if (t + 1 < 36) {
#pragma unroll
            for (int i = 0; i < 8; i++)
                rbv[i] = Np[(size_t)(bc0 + i * 4) * HW + (t + 1) * 64 + bm];
        }
        float c[2][4];
#pragma unroll
        for (int mt = 0; mt < 2; mt++)
#pragma unroll
            for (int j = 0; j < 4; j++) c[mt][j] = 0.f;
#pragma unroll
        for (int ks = 0; ks < 4; ks++) {
            uint32_t ah[2][4], al[2][4];
#pragma unroll
            for (int mt = 0; mt < 2; mt++) {
                int rb = mt * 16;
                ah[mt][0] = Ahi[(rb + gr) * 36 + ks * 8 + gc];
                ah[mt][1] = Ahi[(rb + gr + 8) * 36 + ks * 8 + gc];
                ah[mt][2] = Ahi[(rb + gr) * 36 + ks * 8 + gc + 4];
                ah[mt][3] = Ahi[(rb + gr + 8) * 36 + ks * 8 + gc + 4];
                al[mt][0] = Alo[(rb + gr) * 36 + ks * 8 + gc];
                al[mt][1] = Alo[(rb + gr + 8) * 36 + ks * 8 + gc];
                al[mt][2] = Alo[(rb + gr) * 36 + ks * 8 + gc + 4];
                al[mt][3] = Alo[(rb + gr + 8) * 36 + ks * 8 + gc + 4];
            }
            int colb = wid * 8 + gr;
            uint32_t bh0 = Bhi[(ks * 8 + gc) * PAB_STR + colb];
            uint32_t bh1 = Bhi[(ks * 8 + gc + 4) * PAB_STR + colb];
            uint32_t bl0 = Blo[(ks * 8 + gc) * PAB_STR + colb];
            uint32_t bl1 = Blo[(ks * 8 + gc + 4) * PAB_STR + colb];
#pragma unroll
            for (int mt = 0; mt < 2; mt++) {
                mma_tf32(c[mt], ah[mt], bh0, bh1);
                mma_tf32(c[mt], ah[mt], bl0, bl1);
                mma_tf32(c[mt], al[mt], bh0, bh1);
            }
        }
        int m_base = t * 64 + wid * 8 + gc * 2;
#pragma unroll
        for (int mt = 0; mt < 2; mt++)
#pragma unroll
            for (int rh = 0; rh < 2; rh++) {
                float p0 = ex2(c[mt][rh * 2 + 0]);
                float p1 = ex2(c[mt][rh * 2 + 1]);
                rs[mt][rh] += p0 + p1;
                int n = n0 + mt * 16 + rh * 8 + gr;
                *(float2*)(pab + (size_t)n * HW + m_base) = make_float2(p0, p1);
            }
        __syncthreads();
    }

#pragma unroll
    for (int mt = 0; mt < 2; mt++)
#pragma unroll
        for (int rh = 0; rh < 2; rh++) {
            float v = rs[mt][rh];
            v += __shfl_xor_sync(0xffffffffu, v, 1);
            v += __shfl_xor_sync(0xffffffffu, v, 2);
            if (gc == 0) red[(mt * 16 + rh * 8 + gr) * 8 + wid] = v;
        }
    __syncthreads();
    if (tid < 32) {
        float s = 0.f;
#pragma unroll
        for (int w = 0; w < 8; w++) s += red[tid * 8 + w];
        g_l[(size_t)b * HW + n0 + tid] = s;
    }
}

// ---------------- double-buffered tf32 GSA: gsa = (wf @ pa^T) / l ---------
__global__ void __launch_bounds__(256) tf32_gsa()
{
    extern __shared__ uint32_t dsm[];
    uint32_t* As = dsm;
    uint32_t* Bs = dsm + 2 * ASZ;
    int tid = threadIdx.x, lane = tid & 31, wid = tid >> 5;
    int gr = lane >> 2, gc = lane & 3;
    int c0 = blockIdx.y * 64;
    int b = blockIdx.x / 18, n0 = (blockIdx.x % 18) * 128;
    const float* wfb = g_w + (size_t)b * CC * HW;
    const float* pab = g_pa + (size_t)b * HW * HW;
    int warpm = wid >> 2, warpn = wid & 3;

    int ar = tid >> 3, ak4 = (tid & 7) * 4;
    int ar2 = (tid + 256) >> 3;
    int bn = tid & 127, bk4_0 = (tid >> 7) * 4;

    float4 ra[2], rb[4];
#pragma unroll
    for (int i = 0; i < 2; i++) {
        int r = (i == 0) ? ar : ar2;
        ra[i] = *(const float4*)(wfb + (size_t)(c0 + r) * HW + 0 + ak4);
    }
#pragma unroll
    for (int i = 0; i < 4; i++)
        rb[i] = *(const float4*)(pab + (size_t)(n0 + bn) * HW + 0 + (bk4_0 + i * 8));
#pragma unroll
    for (int i = 0; i < 2; i++) {
        int r = (i == 0) ? ar : ar2;
        *(uint4*)(As + r * AS_STR + ak4) = cvt4_tf32(ra[i]);
    }
#pragma unroll
    for (int i = 0; i < 4; i++) {
        int k4 = bk4_0 + i * 8;
        Bs[(k4 + 0) * BS_STR + bn] = cvt_tf32(rb[i].x);
        Bs[(k4 + 1) * BS_STR + bn] = cvt_tf32(rb[i].y);
        Bs[(k4 + 2) * BS_STR + bn] = cvt_tf32(rb[i].z);
        Bs[(k4 + 3) * BS_STR + bn] = cvt_tf32(rb[i].w);
    }
    __syncthreads();

    float c[2][4][4];
#pragma unroll
    for (int i = 0; i < 2; i++)
#pragma unroll
        for (int j = 0; j < 4; j++)
#pragma unroll
            for (int k = 0; k < 4; k++) c[i][j][k] = 0.f;

    for (int it = 0; it < 72; it++) {
        int p = it & 1;
        int m1 = (it + 1) * 32;
        if (it + 1 < 72) {
#pragma unroll
            for (int i = 0; i < 2; i++) {
                int r = (i == 0) ? ar : ar2;
                ra[i] = *(const float4*)(wfb + (size_t)(c0 + r) * HW + m1 + ak4);
            }
#pragma unroll
            for (int i = 0; i < 4; i++)
                rb[i] = *(const float4*)(pab + (size_t)(n0 + bn) * HW + m1 + (bk4_0 + i * 8));
        }
        tf32_chunk(As + p * ASZ, Bs + p * BSZ, c, warpm, warpn, gr, gc);
        if (it + 1 < 72) {
            uint32_t* Ad = As + (p ^ 1) * ASZ;
            uint32_t* Bd = Bs + (p ^ 1) * BSZ;
#pragma unroll
            for (int i = 0; i < 2; i++) {
                int r = (i == 0) ? ar : ar2;
                *(uint4*)(Ad + r * AS_STR + ak4) = cvt4_tf32(ra[i]);
            }
#pragma unroll
            for (int i = 0; i < 4; i++) {
                int k4 = bk4_0 + i * 8;
                Bd[(k4 + 0) * BS_STR + bn] = cvt_tf32(rb[i].x);
                Bd[(k4 + 1) * BS_STR + bn] = cvt_tf32(rb[i].y);
                Bd[(k4 + 2) * BS_STR + bn] = cvt_tf32(rb[i].z);
                Bd[(k4 + 3) * BS_STR + bn] = cvt_tf32(rb[i].w);
            }
        }
        __syncthreads();
    }

    float inv[4][2];
#pragma unroll
    for (int nt = 0; nt < 4; nt++) {
        int col = n0 + warpn * 32 + nt * 8 + gc * 2;
        inv[nt][0] = 1.f / g_l[(size_t)b * HW + col];
        inv[nt][1] = 1.f / g_l[(size_t)b * HW + col + 1];
    }
    float* ob = g_gsa + (size_t)b * CC * HW;
#pragma unroll
    for (int mt = 0; mt < 2; mt++)
#pragma unroll
        for (int rh = 0; rh < 2; rh++) {
            int r = c0 + warpm * 32 + mt * 16 + rh * 8 + gr;
#pragma unroll
            for (int nt = 0; nt < 4; nt++) {
                int col = n0 + warpn * 32 + nt * 8 + gc * 2;
                *(float2*)(ob + (size_t)r * HW + col) =
                    make_float2(c[mt][nt][rh * 2 + 0] * inv[nt][0],
                                c[mt][nt][rh * 2 + 1] * inv[nt][1]);
            }
        }
}

// ---------------- double-buffered final GEMM + fusion epilogue ------------
__global__ void __launch_bounds__(256) tf32_final(
    const float* __restrict__ wo, const float* __restrict__ bo,
    const float* __restrict__ xin,
    const float* __restrict__ gt_p, const float* __restrict__ gg_p,
    float* __restrict__ out)
{
    extern __shared__ uint32_t dsm[];
    uint32_t* As = dsm;
    uint32_t* Bs = dsm + 2 * ASZ;
    int tid = threadIdx.x, lane = tid & 31, wid = tid >> 5;
    int gr = lane >> 2, gc = lane & 3;
    int row0 = blockIdx.y * 64;
    int b = blockIdx.x / 18, hw0 = (blockIdx.x % 18) * 128;
    const float* Bb = g_gsa + (size_t)b * CC * HW + hw0;
    int warpm = wid >> 2, warpn = wid & 3;

    int ar = tid >> 3, ak4 = (tid & 7) * 4;
    int ar2 = (tid + 256) >> 3;
    int bk = tid >> 5, bn4 = (tid & 31) * 4;

    float4 ra[2], rb[4];
#pragma unroll
    for (int i = 0; i < 2; i++) {
        int r = (i == 0) ? ar : ar2;
        ra[i] = *(const float4*)(wo + (size_t)(row0 + r) * 256 + 0 + ak4);
    }
#pragma unroll
    for (int i = 0; i < 4; i++)
        rb[i] = *(const float4*)(Bb + (size_t)(0 + bk + i * 8) * HW + bn4);
#pragma unroll
    for (int i = 0; i < 2; i++) {
        int r = (i == 0) ? ar : ar2;
        *(uint4*)(As + r * AS_STR + ak4) = cvt4_tf32(ra[i]);
    }
#pragma unroll
    for (int i = 0; i < 4; i++)
        *(uint4*)(Bs + (bk + i * 8) * BS_STR + bn4) = cvt4_tf32(rb[i]);
    __syncthreads();

    float c[2][4][4];
#pragma unroll
    for (int i = 0; i < 2; i++)
#pragma unroll
        for (int j = 0; j < 4; j++)
#pragma unroll
            for (int k = 0; k < 4; k++) c[i][j][k] = 0.f;

    for (int it = 0; it < 8; it++) {
        int p = it & 1;
        int k1 = (it + 1) * 32;
        if (it + 1 < 8) {
#pragma unroll
            for (int i = 0; i < 2; i++) {
                int r = (i == 0) ? ar : ar2;
                ra[i] = *(const float4*)(wo + (size_t)(row0 + r) * 256 + k1 + ak4);
            }
#pragma unroll
            for (int i = 0; i < 4; i++)
                rb[i] = *(const float4*)(Bb + (size_t)(k1 + bk + i * 8) * HW + bn4);
        }
        tf32_chunk(As + p * ASZ, Bs + p * BSZ, c, warpm, warpn, gr, gc);
        if (it + 1 < 8) {
            uint32_t* Ad = As + (p ^ 1) * ASZ;
            uint32_t* Bd = Bs + (p ^ 1) * BSZ;
#pragma unroll
            for (int i = 0; i < 2; i++) {
                int r = (i == 0) ? ar : ar2;
                *(uint4*)(Ad + r * AS_STR + ak4) = cvt4_tf32(ra[i]);
            }
#pragma unroll
            for (int i = 0; i < 4; i++)
                *(uint4*)(Bd + (bk + i * 8) * BS_STR + bn4) = cvt4_tf32(rb[i]);
        }
        __syncthreads();
    }

    float gt = gt_p[0], gg = gg_p[0];
#pragma unroll
    for (int mt = 0; mt < 2; mt++)
#pragma unroll
        for (int rh = 0; rh < 2; rh++) {
            int r = row0 + warpm * 32 + mt * 16 + rh * 8 + gr;
            float bv = bo[r];
#pragma unroll
            for (int nt = 0; nt < 4; nt++) {
                int col = hw0 + warpn * 32 + nt * 8 + gc * 2;
                size_t idx = (size_t)b * CC * HW + (size_t)r * HW + col;
                float2 x2 = *(const float2*)(xin + idx);
                float2 t2 = *(const float2*)(g_tsa + idx);
                float2 o2;
                o2.x = gt * t2.x + gg * (c[mt][nt][rh * 2 + 0] + bv) + x2.x;
                o2.y = gt * t2.y + gg * (c[mt][nt][rh * 2 + 1] + bv) + x2.y;
                *(float2*)(out + idx) = o2;
            }
        }
}

// ---------------- fp32 proj (m/n, concentration-sensitive) ----------------
__global__ void __launch_bounds__(256) proj_gemm(
    const float* __restrict__ W, const float* __restrict__ bias,
    const float* __restrict__ x, float* __restrict__ out, int Co)
{
    __shared__ float As[16][64];
    __shared__ float Bs[16][64];
    int jt  = blockIdx.x;
    int o0  = blockIdx.y * 64;
    int b   = (jt * 64) / HW;
    int hw0 = (jt * 64) % HW;
    const float* xb = x + (size_t)b * CC * HW + hw0;
    int tid = threadIdx.x;
    int tx = tid & 15, ty = tid >> 4;
    float acc[4][4];
#pragma unroll
    for (int i = 0; i < 4; i++)
#pragma unroll
        for (int j = 0; j < 4; j++) acc[i][j] = 0.f;

    int lo  = tid >> 2;
    int lk4 = (tid & 3) * 4;
    int bk  = tid >> 4;
    int bj4 = (tid & 15) * 4;

    for (int k0 = 0; k0 < CC; k0 += 16) {
        float4 wv = make_float4(0.f, 0.f, 0.f, 0.f);
        if (o0 + lo < Co)
            wv = *(const float4*)(W + (size_t)(o0 + lo) * CC + k0 + lk4);
        As[lk4 + 0][lo] = wv.x; As[lk4 + 1][lo] = wv.y;
        As[lk4 + 2][lo] = wv.z; As[lk4 + 3][lo] = wv.w;
        float4 xv = *(const float4*)(xb + (size_t)(k0 + bk) * HW + bj4);
        *(float4*)&Bs[bk][bj4] = xv;
        __syncthreads();
#pragma unroll
        for (int k = 0; k < 16; k++) {
            float4 a  = *(float4*)&As[k][ty * 4];
            float4 bb = *(float4*)&Bs[k][tx * 4];
            float av[4] = {a.x, a.y, a.z, a.w};
            float bv[4] = {bb.x, bb.y, bb.z, bb.w};
#pragma unroll
            for (int i = 0; i < 4; i++)
#pragma unroll
                for (int j = 0; j < 4; j++)
                    acc[i][j] = fmaf(av[i], bv[j], acc[i][j]);
        }
        __syncthreads();
    }
#pragma unroll
    for (int i = 0; i < 4; i++) {
        int o = o0 + ty * 4 + i;
        if (o < Co) {
            float bsv = bias[o];
            float4 ov = make_float4(acc[i][0] + bsv, acc[i][1] + bsv,
                                    acc[i][2] + bsv, acc[i][3] + bsv);
            *(float4*)(out + (size_t)b * Co * HW + (size_t)o * HW + hw0 + tx * 4) = ov;
        }
    }
}

// wm/bm are pre-scaled by log2e so pa_softmax can use raw exp2.
__global__ void __launch_bounds__(256) concat_mn(
    const float* __restrict__ wm, const float* __restrict__ bm,
    const float* __restrict__ wn, const float* __restrict__ bn)
{
    int i = blockIdx.x * 256 + threadIdx.x;
    if (i < 32 * 256) { g_wmn[i] = wm[i] * LOG2E; g_wmn[32 * 256 + i] = wn[i]; }
    if (i < 32) { g_bmn[i] = bm[i] * LOG2E; g_bmn[32 + i] = bn[i]; }
}

// ---------------- FA2-style flash TSA with mma.sync bf16 ----------------
#define QS_STR 40
#define VS_STR 136
__global__ void __launch_bounds__(256) flash_mma()
{
    __shared__ __nv_bfloat16 Qs[128 * QS_STR];
    __shared__ __nv_bfloat16 Ks[128 * QS_STR];
    __shared__ __nv_bfloat16 Vs[32 * VS_STR];
    int tid = threadIdx.x, wid = tid >> 5, lane = tid & 31;
    int bh = blockIdx.y, i0 = blockIdx.x * 128;
    int gr = lane >> 2, gc = (lane & 3) * 2;

    const __nv_bfloat16* qsrc = g_qh + ((size_t)bh * HW + i0) * DK;
    const __nv_bfloat16* ksrc = g_kh + (size_t)bh * HW * DK;
    const __nv_bfloat16* vsrc = g_vh + (size_t)bh * DK * HW;

    for (int e = tid; e < 512; e += 256) {
        int r = e >> 2, c8 = (e & 3) * 8;
        *(uint4*)(Qs + r * QS_STR + c8) = *(const uint4*)(qsrc + r * DK + c8);
    }
    __syncthreads();

    uint32_t qa[2][4];
    {
        const __nv_bfloat16* qb = Qs + (wid * 16 + gr) * QS_STR;
#pragma unroll
        for (int kc = 0; kc < 2; kc++) {
            qa[kc][0] = *(const uint32_t*)(qb + kc * 16 + gc);
            qa[kc][1] = *(const uint32_t*)(qb + 8 * QS_STR + kc * 16 + gc);
            qa[kc][2] = *(const uint32_t*)(qb + kc * 16 + gc + 8);
            qa[kc][3] = *(const uint32_t*)(qb + 8 * QS_STR + kc * 16 + gc + 8);
        }
    }

    int kr  = tid >> 2,        kc8 = (tid & 3) * 8;
    int kr1 = (tid + 256) >> 2;
    int vd  = tid >> 4,        vc8 = (tid & 15) * 8;
    int vd1 = (tid + 256) >> 4;

    uint4 kreg[2], vreg[2];
    kreg[0] = *(const uint4*)(ksrc + (size_t)kr  * DK + kc8);
    kreg[1] = *(const uint4*)(ksrc + (size_t)kr1 * DK + kc8);
    vreg[0] = *(const uint4*)(vsrc + (size_t)vd  * HW + vc8);
    vreg[1] = *(const uint4*)(vsrc + (size_t)vd1 * HW + vc8);

    float o[4][4];
#pragma unroll
    for (int i = 0; i < 4; i++)
#pragma unroll
        for (int j = 0; j < 4; j++) o[i][j] = 0.f;
    float l0 = 0.f, l1 = 0.f;

    for (int kt = 0; kt < 18; kt++) {
        __syncthreads();
        *(uint4*)(Ks + kr  * QS_STR + kc8) = kreg[0];
        *(uint4*)(Ks + kr1 * QS_STR + kc8) = kreg[1];
        *(uint4*)(Vs + vd  * VS_STR + vc8) = vreg[0];
        *(uint4*)(Vs + vd1 * VS_STR + vc8) = vreg[1];
        __syncthreads();
        if (kt + 1 < 18) {
            int j1 = (kt + 1) * 128;
            kreg[0] = *(const uint4*)(ksrc + (size_t)(j1 + kr)  * DK + kc8);
            kreg[1] = *(const uint4*)(ksrc + (size_t)(j1 + kr1) * DK + kc8);
            vreg[0] = *(const uint4*)(vsrc + (size_t)vd  * HW + j1 + vc8);
            vreg[1] = *(const uint4*)(vsrc + (size_t)vd1 * HW + j1 + vc8);
        }

        float s[16][4];
#pragma unroll
        for (int nt = 0; nt < 16; nt++) {
            s[nt][0] = 0.f; s[nt][1] = 0.f; s[nt][2] = 0.f; s[nt][3] = 0.f;
            const __nv_bfloat16* kb = Ks + (nt * 8 + gr) * QS_STR;
#pragma unroll
            for (int kc = 0; kc < 2; kc++) {
                uint32_t b0 = *(const uint32_t*)(kb + kc * 16 + gc);
                uint32_t b1 = *(const uint32_t*)(kb + kc * 16 + gc + 8);
                mma16816(s[nt], qa[kc], b0, b1);
            }
        }

        uint32_t pa_[8][4];
#pragma unroll
        for (int h2 = 0; h2 < 8; h2++) {
            float e00 = ex2(s[2 * h2][0]),     e01 = ex2(s[2 * h2][1]);
            float e02 = ex2(s[2 * h2][2]),     e03 = ex2(s[2 * h2][3]);
            float f00 = ex2(s[2 * h2 + 1][0]), f01 = ex2(s[2 * h2 + 1][1]);
            float f02 = ex2(s[2 * h2 + 1][2]), f03 = ex2(s[2 * h2 + 1][3]);
            l0 += (e00 + e01) + (f00 + f01);
            l1 += (e02 + e03) + (f02 + f03);
            pa_[h2][0] = pack_bf16x2(e01, e00);
            pa_[h2][1] = pack_bf16x2(e03, e02);
            pa_[h2][2] = pack_bf16x2(f01, f00);
            pa_[h2][3] = pack_bf16x2(f03, f02);
        }

#pragma unroll
        for (int kc2 = 0; kc2 < 8; kc2++) {
#pragma unroll
            for (int dt = 0; dt < 4; dt++) {
                const __nv_bfloat16* vb = Vs + (dt * 8 + gr) * VS_STR + kc2 * 16 + gc;
                uint32_t b0 = *(const uint32_t*)(vb);
                uint32_t b1 = *(const uint32_t*)(vb + 8);
                mma16816(o[dt], pa_[kc2], b0, b1);
            }
        }
    }

    l0 += __shfl_xor_sync(0xffffffffu, l0, 1);
    l0 += __shfl_xor_sync(0xffffffffu, l0, 2);
    l1 += __shfl_xor_sync(0xffffffffu, l1, 1);
    l1 += __shfl_xor_sync(0xffffffffu, l1, 2);
    float inv0 = 1.f / l0, inv1 = 1.f / l1;

    int b = bh >> 3, h = bh & 7;
    float* ob = g_tsa + ((size_t)b * CC + h * DK) * HW;
    int tok0 = i0 + wid * 16 + gr;
#pragma unroll
    for (int dt = 0; dt < 4; dt++) {
        int d = dt * 8 + gc;
        ob[(size_t)(d)     * HW + tok0]     = o[dt][0] * inv0;
        ob[(size_t)(d + 1) * HW + tok0]     = o[dt][1] * inv0;
        ob[(size_t)(d)     * HW + tok0 + 8] = o[dt][2] * inv1;
        ob[(size_t)(d + 1) * HW + tok0 + 8] = o[dt][3] * inv1;
    }
}

// ---------------- launch ----------------
extern "C" void kernel_launch(void* const* d_in, const int* in_sizes, int n_in,
                              void* d_out, int out_size)
{
    const float* x   = (const float*)d_in[0];
    const float* wq  = (const float*)d_in[1];
    const float* bq  = (const float*)d_in[2];
    const float* wk  = (const float*)d_in[3];
    const float* bk  = (const float*)d_in[4];
    const float* wv  = (const float*)d_in[5];
    const float* bv  = (const float*)d_in[6];
    const float* wm  = (const float*)d_in[7];
    const float* bm  = (const float*)d_in[8];
    const float* wn  = (const float*)d_in[9];
    const float* bn  = (const float*)d_in[10];
    const float* ww  = (const float*)d_in[11];
    const float* bw  = (const float*)d_in[12];
    const float* wo  = (const float*)d_in[13];
    const float* bo  = (const float*)d_in[14];
    const float* gts = (const float*)d_in[15];
    const float* ggs = (const float*)d_in[16];
    float* out = (float*)d_out;

    float *pmn, *pwmn, *pbmn;
    cudaGetSymbolAddress((void**)&pmn, g_mn);
    cudaGetSymbolAddress((void**)&pwmn, g_wmn);
    cudaGetSymbolAddress((void**)&pbmn, g_bmn);

    static int init_done = 0;
    static cudaStream_t s1;
    static cudaEvent_t ev_fork, ev_join;
    const int DBUF_SMEM = (2 * ASZ + 2 * BSZ) * 4;   // 53248 B
    if (!init_done) {
        cudaFuncSetAttribute(tf32_gsa, cudaFuncAttributeMaxDynamicSharedMemorySize, DBUF_SMEM);
        cudaFuncSetAttribute(tf32_final, cudaFuncAttributeMaxDynamicSharedMemorySize, DBUF_SMEM);
        cudaStreamCreateWithFlags(&s1, cudaStreamNonBlocking);
        cudaEventCreateWithFlags(&ev_fork, cudaEventDisableTiming);
        cudaEventCreateWithFlags(&ev_join, cudaEventDisableTiming);
        init_done = 1;
    }

    dim3 blk(256);

    // fork: side stream runs the GSA-score branch concurrently with QKVW+flash
    cudaEventRecord(ev_fork, 0);
    cudaStreamWaitEvent(s1, ev_fork, 0);

    // branch B (s1): mn weights -> mn projection -> pa scores+exp
    concat_mn<<<32, blk, 0, s1>>>(wm, bm, wn, bn);
    proj_gemm<<<dim3(BB * HW / 64, 1), blk, 0, s1>>>(pwmn, pbmn, x, pmn, 64);
    pa_softmax<<<dim3(HW / 32, BB), blk, 0, s1>>>();

    // branch A (default): QKVW projection -> flash attention
    tf32_proj4<<<dim3(36, 16), blk>>>(wq, bq, wk, bk, wv, bv, ww, bw, x);
    flash_mma<<<dim3(HW / 128, BB * HEADS), blk>>>();

    // join: gsa needs pa/l (branch B) and w (branch A)
    cudaEventRecord(ev_join, s1);
    cudaStreamWaitEvent(0, ev_join, 0);

    tf32_gsa<<<dim3(36, 4), blk, DBUF_SMEM>>>();
    tf32_final<<<dim3(36, 4), blk, DBUF_SMEM>>>(wo, bo, x, gts, ggs, out);
}

// round 14
// speedup vs baseline: 1.1141x; 1.0061x over previous
#include <cuda_runtime.h>
#include <cuda_bf16.h>
#include <cstdint>

#define BB    2
#define CC    256
#define HW    2304
#define HEADS 8
#define DK    32
#define CR    32
#define NCH   (BB*CC*HW)

// ---------------- scratch (device globals; no allocation) ----------------
__device__ float g_w[NCH];              // wf projection (fp32)
__device__ float g_mn[BB*64*HW];        // m (rows 0-31, pre-scaled by log2e) and n (rows 32-63)
__device__ float g_wmn[64*256];
__device__ float g_bmn[64];
__device__ float g_tsa[NCH];
__device__ float g_gsa[NCH];
__device__ float g_l[BB*HW];            // GSA softmax row sums
__device__ float g_pa[(size_t)BB*HW*HW]; // unnormalized exp(scores), 42.5 MB
__device__ __nv_bfloat16 g_qh[NCH];     // [bh][t][d], pre-scaled by log2e/sqrt(dk)
__device__ __nv_bfloat16 g_kh[NCH];     // [bh][t][d]
__device__ __nv_bfloat16 g_vh[NCH];     // [bh][d][t]

// ---------------- mma helpers ----------------
__device__ __forceinline__ void mma16816(float* c, const uint32_t* a, uint32_t b0, uint32_t b1) {
    asm volatile(
        "mma.sync.aligned.m16n8k16.row.col.f32.bf16.bf16.f32 "
        "{%0,%1,%2,%3}, {%4,%5,%6,%7}, {%8,%9}, {%0,%1,%2,%3};"
        : "+f"(c[0]), "+f"(c[1]), "+f"(c[2]), "+f"(c[3])
        : "r"(a[0]), "r"(a[1]), "r"(a[2]), "r"(a[3]), "r"(b0), "r"(b1));
}
__device__ __forceinline__ void mma_tf32(float* c, const uint32_t* a, uint32_t b0, uint32_t b1) {
    asm volatile(
        "mma.sync.aligned.m16n8k8.row.col.f32.tf32.tf32.f32 "
        "{%0,%1,%2,%3}, {%4,%5,%6,%7}, {%8,%9}, {%0,%1,%2,%3};"
        : "+f"(c[0]), "+f"(c[1]), "+f"(c[2]), "+f"(c[3])
        : "r"(a[0]), "r"(a[1]), "r"(a[2]), "r"(a[3]), "r"(b0), "r"(b1));
}
__device__ __forceinline__ uint32_t pack_bf16x2(float hi, float lo) {
    uint32_t w;
    asm("cvt.rn.satfinite.bf16x2.f32 %0, %1, %2;" : "=r"(w) : "f"(hi), "f"(lo));
    return w;
}
__device__ __forceinline__ uint32_t cvt_tf32(float f) {
    uint32_t r;
    asm("cvt.rna.tf32.f32 %0, %1;" : "=r"(r) : "f"(f));
    return r;
}
__device__ __forceinline__ uint4 cvt4_tf32(float4 v) {
    uint4 o;
    o.x = cvt_tf32(v.x); o.y = cvt_tf32(v.y); o.z = cvt_tf32(v.z); o.w = cvt_tf32(v.w);
    return o;
}
__device__ __forceinline__ float ex2(float x) {
    float r;
    asm("ex2.approx.f32 %0, %1;" : "=f"(r) : "f"(x));
    return r;
}

#define LOG2E 1.4426950408889634f

#define AS_STR 36
#define BS_STR 136
#define ASZ (64 * AS_STR)
#define BSZ (32 * BS_STR)

__device__ __forceinline__ void tf32_chunk(
    const uint32_t* Ap, const uint32_t* Bp, float c[2][4][4],
    int warpm, int warpn, int gr, int gc)
{
#pragma unroll
    for (int ks = 0; ks < 4; ks++) {
        uint32_t a[2][4], bq[4][2];
#pragma unroll
        for (int mt = 0; mt < 2; mt++) {
            const uint32_t* ab = Ap + (warpm * 32 + mt * 16) * AS_STR + ks * 8 + gc;
            a[mt][0] = ab[gr * AS_STR];
            a[mt][1] = ab[(gr + 8) * AS_STR];
            a[mt][2] = ab[gr * AS_STR + 4];
            a[mt][3] = ab[(gr + 8) * AS_STR + 4];
        }
#pragma unroll
        for (int nt = 0; nt < 4; nt++) {
            const uint32_t* bb = Bp + (ks * 8 + gc) * BS_STR + warpn * 32 + nt * 8 + gr;
            bq[nt][0] = bb[0];
            bq[nt][1] = bb[4 * BS_STR];
        }
#pragma unroll
        for (int mt = 0; mt < 2; mt++)
#pragma unroll
            for (int nt = 0; nt < 4; nt++)
                mma_tf32(c[mt][nt], a[mt], bq[nt][0], bq[nt][1]);
    }
}

// ---------------- fused QKVW projection + bf16 layout epilogues -----------
// R14: register-prefetch double buffering in the K-loop (flash R11 pattern).
__global__ void __launch_bounds__(256) tf32_proj4(
    const float* __restrict__ wq, const float* __restrict__ bq,
    const float* __restrict__ wk, const float* __restrict__ bk,
    const float* __restrict__ wv, const float* __restrict__ bv,
    const float* __restrict__ ww, const float* __restrict__ bw,
    const float* __restrict__ x)
{
    __shared__ uint32_t As[ASZ];
    __shared__ uint32_t Bs[BSZ];
    int tid = threadIdx.x, lane = tid & 31, wid = tid >> 5;
    int gr = lane >> 2, gc = lane & 3;
    int sel  = blockIdx.y >> 2;
    int row0 = (blockIdx.y & 3) * 64;
    const float* W    = sel == 0 ? wq : sel == 1 ? wk : sel == 2 ? wv : ww;
    const float* bias = sel == 0 ? bq : sel == 1 ? bk : sel == 2 ? bv : bw;
    int b = blockIdx.x / 18, hw0 = (blockIdx.x % 18) * 128;
    const float* Bb = x + (size_t)b * CC * HW + hw0;
    int warpm = wid >> 2, warpn = wid & 3;

    int ar  = tid >> 3,  ak4 = (tid & 7) * 4;      // A piece 0: e = tid
    int ar2 = (tid + 256) >> 3;                    // A piece 1
    int bkk = tid >> 5,  bn4 = (tid & 31) * 4;     // B: e = tid + i*256 -> k = bkk + i*8

    float c[2][4][4];
#pragma unroll
    for (int i = 0; i < 2; i++)
#pragma unroll
        for (int j = 0; j < 4; j++)
#pragma unroll
            for (int k = 0; k < 4; k++) c[i][j][k] = 0.f;

    // prologue: load chunk 0 into registers
    float4 wreg[2], xreg[4];
    wreg[0] = *(const float4*)(W + (size_t)(row0 + ar)  * 256 + 0 + ak4);
    wreg[1] = *(const float4*)(W + (size_t)(row0 + ar2) * 256 + 0 + ak4);
#pragma unroll
    for (int i = 0; i < 4; i++)
        xreg[i] = *(const float4*)(Bb + (size_t)(0 + bkk + i * 8) * HW + bn4);

    for (int it = 0; it < 8; it++) {
        // store current chunk (smem free: trailing sync of prev iter)
        *(uint4*)(As + ar  * AS_STR + ak4) = cvt4_tf32(wreg[0]);
        *(uint4*)(As + ar2 * AS_STR + ak4) = cvt4_tf32(wreg[1]);
#pragma unroll
        for (int i = 0; i < 4; i++)
            *(uint4*)(Bs + (bkk + i * 8) * BS_STR + bn4) = cvt4_tf32(xreg[i]);
        __syncthreads();
        if (it + 1 < 8) {                 // prefetch next chunk (overlaps compute)
            int k1 = (it + 1) * 32;
            wreg[0] = *(const float4*)(W + (size_t)(row0 + ar)  * 256 + k1 + ak4);
            wreg[1] = *(const float4*)(W + (size_t)(row0 + ar2) * 256 + k1 + ak4);
#pragma unroll
            for (int i = 0; i < 4; i++)
                xreg[i] = *(const float4*)(Bb + (size_t)(k1 + bkk + i * 8) * HW + bn4);
        }
        tf32_chunk(As, Bs, c, warpm, warpn, gr, gc);
        __syncthreads();
    }

    if (sel == 3) {                       // wf: fp32, [b][c][t]
#pragma unroll
        for (int mt = 0; mt < 2; mt++)
#pragma unroll
            for (int rh = 0; rh < 2; rh++) {
                int r = row0 + warpm * 32 + mt * 16 + rh * 8 + gr;
                float bv2 = bias[r];
#pragma unroll
                for (int nt = 0; nt < 4; nt++) {
                    int col = hw0 + warpn * 32 + nt * 8 + gc * 2;
                    size_t idx = (size_t)b * CC * HW + (size_t)r * HW + col;
                    *(float2*)(g_w + idx) = make_float2(c[mt][nt][rh * 2 + 0] + bv2,
                                                        c[mt][nt][rh * 2 + 1] + bv2);
                }
            }
    } else if (sel == 2) {                // v: bf16 packed, [bh][d][t]
#pragma unroll
        for (int mt = 0; mt < 2; mt++)
#pragma unroll
            for (int rh = 0; rh < 2; rh++) {
                int r = row0 + warpm * 32 + mt * 16 + rh * 8 + gr;
                float bv2 = bias[r];
#pragma unroll
                for (int nt = 0; nt < 4; nt++) {
                    int col = hw0 + warpn * 32 + nt * 8 + gc * 2;
                    size_t idx = (size_t)(b * 256 + r) * HW + col;
                    uint32_t pw = pack_bf16x2(c[mt][nt][rh * 2 + 1] + bv2,
                                              c[mt][nt][rh * 2 + 0] + bv2);
                    *(uint32_t*)(g_vh + idx) = pw;
                }
            }
    } else {                              // q/k: bf16 scatter into [bh][t][d]
        float scale = sel == 0 ? (LOG2E * 0.17677669529663687f) : 1.0f;
        __nv_bfloat16* dst = sel == 0 ? g_qh : g_kh;
#pragma unroll
        for (int mt = 0; mt < 2; mt++)
#pragma unroll
            for (int rh = 0; rh < 2; rh++) {
                int r = row0 + warpm * 32 + mt * 16 + rh * 8 + gr;
                float bv2 = bias[r];
                size_t hb = (size_t)(b * 8 + (r >> 5)) * HW;
                int d = r & 31;
#pragma unroll
                for (int nt = 0; nt < 4; nt++) {
                    int col = hw0 + warpn * 32 + nt * 8 + gc * 2;
                    float v0 = (c[mt][nt][rh * 2 + 0] + bv2) * scale;
                    float v1 = (c[mt][nt][rh * 2 + 1] + bv2) * scale;
                    dst[(hb + col)     * 32 + d] = __float2bfloat16(v0);
                    dst[(hb + col + 1) * 32 + d] = __float2bfloat16(v1);
                }
            }
    }
}

// ---------------- fused GSA scores + exp (split-tf32, fp32-accurate) ------
#define PAB_STR 68
__global__ void __launch_bounds__(256) pa_softmax()
{
    __shared__ uint32_t Ahi[32 * 36], Alo[32 * 36];
    __shared__ uint32_t Bhi[32 * PAB_STR], Blo[32 * PAB_STR];
    __shared__ float red[32 * 8];
    int tid = threadIdx.x, lane = tid & 31, wid = tid >> 5;
    int gr = lane >> 2, gc = lane & 3;
    int b = blockIdx.y, n0 = blockIdx.x * 32;
    const float* Mp = g_mn + (size_t)b * 64 * HW;
    const float* Np = Mp + (size_t)32 * HW;

    for (int e = tid; e < 1024; e += 256) {
        int ch = e >> 5, n = e & 31;
        float v = Mp[(size_t)ch * HW + n0 + n];
        uint32_t h = cvt_tf32(v);
        Ahi[n * 36 + ch] = h;
        Alo[n * 36 + ch] = cvt_tf32(v - __uint_as_float(h));
    }

    int bm = tid & 63, bc0 = tid >> 6;
    float rbv[8];
#pragma unroll
    for (int i = 0; i < 8; i++)
        rbv[i] = Np[(size_t)(bc0 + i * 4) * HW + bm];

    float rs[2][2] = {{0.f, 0.f}, {0.f, 0.f}};
    float* pab = g_pa + (size_t)b * HW * HW;
    __syncthreads();

    for (int t = 0; t < 36; t++) {
#pragma unroll
        for (int i = 0; i < 8; i++) {
            int ch = bc0 + i * 4;
            uint32_t h = cvt_tf32(rbv[i]);
            Bhi[ch * PAB_STR + bm] = h;
            Blo[ch * PAB_STR + bm] = cvt_tf32(rbv[i] - __uint_as_float(h));
        }
        __syncthreads();
        if (t + 1 < 36) {
#pragma unroll
            for (int i = 0; i < 8; i++)
                rbv[i] = Np[(size_t)(bc0 + i * 4) * HW + (t + 1) * 64 + bm];
        }
        float c[2][4];
#pragma unroll
        for (int mt = 0; mt < 2; mt++)
#pragma unroll
            for (int j = 0; j < 4; j++) c[mt][j] = 0.f;
#pragma unroll
        for (int ks = 0; ks < 4; ks++) {
            uint32_t ah[2][4], al[2][4];
#pragma unroll
            for (int mt = 0; mt < 2; mt++) {
                int rb = mt * 16;
                ah[mt][0] = Ahi[(rb + gr) * 36 + ks * 8 + gc];
                ah[mt][1] = Ahi[(rb + gr + 8) * 36 + ks * 8 + gc];
                ah[mt][2] = Ahi[(rb + gr) * 36 + ks * 8 + gc + 4];
                ah[mt][3] = Ahi[(rb + gr + 8) * 36 + ks * 8 + gc + 4];
                al[mt][0] = Alo[(rb + gr) * 36 + ks * 8 + gc];
                al[mt][1] = Alo[(rb + gr + 8) * 36 + ks * 8 + gc];
                al[mt][2] = Alo[(rb + gr) * 36 + ks * 8 + gc + 4];
                al[mt][3] = Alo[(rb + gr + 8) * 36 + ks * 8 + gc + 4];
            }
            int colb = wid * 8 + gr;
            uint32_t bh0 = Bhi[(ks * 8 + gc) * PAB_STR + colb];
            uint32_t bh1 = Bhi[(ks * 8 + gc + 4) * PAB_STR + colb];
            uint32_t bl0 = Blo[(ks * 8 + gc) * PAB_STR + colb];
            uint32_t bl1 = Blo[(ks * 8 + gc + 4) * PAB_STR + colb];
#pragma unroll
            for (int mt = 0; mt < 2; mt++) {
                mma_tf32(c[mt], ah[mt], bh0, bh1);
                mma_tf32(c[mt], ah[mt], bl0, bl1);
                mma_tf32(c[mt], al[mt], bh0, bh1);
            }
        }
        int m_base = t * 64 + wid * 8 + gc * 2;
#pragma unroll
        for (int mt = 0; mt < 2; mt++)
#pragma unroll
            for (int rh = 0; rh < 2; rh++) {
                float p0 = ex2(c[mt][rh * 2 + 0]);
                float p1 = ex2(c[mt][rh * 2 + 1]);
                rs[mt][rh] += p0 + p1;
                int n = n0 + mt * 16 + rh * 8 + gr;
                *(float2*)(pab + (size_t)n * HW + m_base) = make_float2(p0, p1);
            }
        __syncthreads();
    }

#pragma unroll
    for (int mt = 0; mt < 2; mt++)
#pragma unroll
        for (int rh = 0; rh < 2; rh++) {
            float v = rs[mt][rh];
            v += __shfl_xor_sync(0xffffffffu, v, 1);
            v += __shfl_xor_sync(0xffffffffu, v, 2);
            if (gc == 0) red[(mt * 16 + rh * 8 + gr) * 8 + wid] = v;
        }
    __syncthreads();
    if (tid < 32) {
        float s = 0.f;
#pragma unroll
        for (int w = 0; w < 8; w++) s += red[tid * 8 + w];
        g_l[(size_t)b * HW + n0 + tid] = s;
    }
}

// ---------------- double-buffered tf32 GSA: gsa = (wf @ pa^T) / l ---------
__global__ void __launch_bounds__(256) tf32_gsa()
{
    extern __shared__ uint32_t dsm[];
    uint32_t* As = dsm;
    uint32_t* Bs = dsm + 2 * ASZ;
    int tid = threadIdx.x, lane = tid & 31, wid = tid >> 5;
    int gr = lane >> 2, gc = lane & 3;
    int c0 = blockIdx.y * 64;
    int b = blockIdx.x / 18, n0 = (blockIdx.x % 18) * 128;
    const float* wfb = g_w + (size_t)b * CC * HW;
    const float* pab = g_pa + (size_t)b * HW * HW;
    int warpm = wid >> 2, warpn = wid & 3;

    int ar = tid >> 3, ak4 = (tid & 7) * 4;
    int ar2 = (tid + 256) >> 3;
    int bn = tid & 127, bk4_0 = (tid >> 7) * 4;

    float4 ra[2], rb[4];
#pragma unroll
    for (int i = 0; i < 2; i++) {
        int r = (i == 0) ? ar : ar2;
        ra[i] = *(const float4*)(wfb + (size_t)(c0 + r) * HW + 0 + ak4);
    }
#pragma unroll
    for (int i = 0; i < 4; i++)
        rb[i] = *(const float4*)(pab + (size_t)(n0 + bn) * HW + 0 + (bk4_0 + i * 8));
#pragma unroll
    for (int i = 0; i < 2; i++) {
        int r = (i == 0) ? ar : ar2;
        *(uint4*)(As + r * AS_STR + ak4) = cvt4_tf32(ra[i]);
    }
#pragma unroll
    for (int i = 0; i < 4; i++) {
        int k4 = bk4_0 + i * 8;
        Bs[(k4 + 0) * BS_STR + bn] = cvt_tf32(rb[i].x);
        Bs[(k4 + 1) * BS_STR + bn] = cvt_tf32(rb[i].y);
        Bs[(k4 + 2) * BS_STR + bn] = cvt_tf32(rb[i].z);
        Bs[(k4 + 3) * BS_STR + bn] = cvt_tf32(rb[i].w);
    }
    __syncthreads();

    float c[2][4][4];
#pragma unroll
    for (int i = 0; i < 2; i++)
#pragma unroll
        for (int j = 0; j < 4; j++)
#pragma unroll
            for (int k = 0; k < 4; k++) c[i][j][k] = 0.f;

    for (int it = 0; it < 72; it++) {
        int p = it & 1;
        int m1 = (it + 1) * 32;
        if (it + 1 < 72) {
#pragma unroll
            for (int i = 0; i < 2; i++) {
                int r = (i == 0) ? ar : ar2;
                ra[i] = *(const float4*)(wfb + (size_t)(c0 + r) * HW + m1 + ak4);
            }
#pragma unroll
            for (int i = 0; i < 4; i++)
                rb[i] = *(const float4*)(pab + (size_t)(n0 + bn) * HW + m1 + (bk4_0 + i * 8));
        }
        tf32_chunk(As + p * ASZ, Bs + p * BSZ, c, warpm, warpn, gr, gc);
        if (it + 1 < 72) {
            uint32_t* Ad = As + (p ^ 1) * ASZ;
            uint32_t* Bd = Bs + (p ^ 1) * BSZ;
#pragma unroll
            for (int i = 0; i < 2; i++) {
                int r = (i == 0) ? ar : ar2;
                *(uint4*)(Ad + r * AS_STR + ak4) = cvt4_tf32(ra[i]);
            }
#pragma unroll
            for (int i = 0; i < 4; i++) {
                int k4 = bk4_0 + i * 8;
                Bd[(k4 + 0) * BS_STR + bn] = cvt_tf32(rb[i].x);
                Bd[(k4 + 1) * BS_STR + bn] = cvt_tf32(rb[i].y);
                Bd[(k4 + 2) * BS_STR + bn] = cvt_tf32(rb[i].z);
                Bd[(k4 + 3) * BS_STR + bn] = cvt_tf32(rb[i].w);
            }
        }
        __syncthreads();
    }

    float inv[4][2];
#pragma unroll
    for (int nt = 0; nt < 4; nt++) {
        int col = n0 + warpn * 32 + nt * 8 + gc * 2;
        inv[nt][0] = 1.f / g_l[(size_t)b * HW + col];
        inv[nt][1] = 1.f / g_l[(size_t)b * HW + col + 1];
    }
    float* ob = g_gsa + (size_t)b * CC * HW;
#pragma unroll
    for (int mt = 0; mt < 2; mt++)
#pragma unroll
        for (int rh = 0; rh < 2; rh++) {
            int r = c0 + warpm * 32 + mt * 16 + rh * 8 + gr;
#pragma unroll
            for (int nt = 0; nt < 4; nt++) {
                int col = n0 + warpn * 32 + nt * 8 + gc * 2;
                *(float2*)(ob + (size_t)r * HW + col) =
                    make_float2(c[mt][nt][rh * 2 + 0] * inv[nt][0],
                                c[mt][nt][rh * 2 + 1] * inv[nt][1]);
            }
        }
}

// ---------------- double-buffered final GEMM + fusion epilogue ------------
__global__ void __launch_bounds__(256) tf32_final(
    const float* __restrict__ wo, const float* __restrict__ bo,
    const float* __restrict__ xin,
    const float* __restrict__ gt_p, const float* __restrict__ gg_p,
    float* __restrict__ out)
{
    extern __shared__ uint32_t dsm[];
    uint32_t* As = dsm;
    uint32_t* Bs = dsm + 2 * ASZ;
    int tid = threadIdx.x, lane = tid & 31, wid = tid >> 5;
    int gr = lane >> 2, gc = lane & 3;
    int row0 = blockIdx.y * 64;
    int b = blockIdx.x / 18, hw0 = (blockIdx.x % 18) * 128;
    const float* Bb = g_gsa + (size_t)b * CC * HW + hw0;
    int warpm = wid >> 2, warpn = wid & 3;

    int ar = tid >> 3, ak4 = (tid & 7) * 4;
    int ar2 = (tid + 256) >> 3;
    int bk = tid >> 5, bn4 = (tid & 31) * 4;

    float4 ra[2], rb[4];
#pragma unroll
    for (int i = 0; i < 2; i++) {
        int r = (i == 0) ? ar : ar2;
        ra[i] = *(const float4*)(wo + (size_t)(row0 + r) * 256 + 0 + ak4);
    }
#pragma unroll
    for (int i = 0; i < 4; i++)
        rb[i] = *(const float4*)(Bb + (size_t)(0 + bk + i * 8) * HW + bn4);
#pragma unroll
    for (int i = 0; i < 2; i++) {
        int r = (i == 0) ? ar : ar2;
        *(uint4*)(As + r * AS_STR + ak4) = cvt4_tf32(ra[i]);
    }
#pragma unroll
    for (int i = 0; i < 4; i++)
        *(uint4*)(Bs + (bk + i * 8) * BS_STR + bn4) = cvt4_tf32(rb[i]);
    __syncthreads();

    float c[2][4][4];
#pragma unroll
    for (int i = 0; i < 2; i++)
#pragma unroll
        for (int j = 0; j < 4; j++)
#pragma unroll
            for (int k = 0; k < 4; k++) c[i][j][k] = 0.f;

    for (int it = 0; it < 8; it++) {
        int p = it & 1;
        int k1 = (it + 1) * 32;
        if (it + 1 < 8) {
#pragma unroll
            for (int i = 0; i < 2; i++) {
                int r = (i == 0) ? ar : ar2;
                ra[i] = *(const float4*)(wo + (size_t)(row0 + r) * 256 + k1 + ak4);
            }
#pragma unroll
            for (int i = 0; i < 4; i++)
                rb[i] = *(const float4*)(Bb + (size_t)(k1 + bk + i * 8) * HW + bn4);
        }
        tf32_chunk(As + p * ASZ, Bs + p * BSZ, c, warpm, warpn, gr, gc);
        if (it + 1 < 8) {
            uint32_t* Ad = As + (p ^ 1) * ASZ;
            uint32_t* Bd = Bs + (p ^ 1) * BSZ;
#pragma unroll
            for (int i = 0; i < 2; i++) {
                int r = (i == 0) ? ar : ar2;
                *(uint4*)(Ad + r * AS_STR + ak4) = cvt4_tf32(ra[i]);
            }
#pragma unroll
            for (int i = 0; i < 4; i++)
                *(uint4*)(Bd + (bk + i * 8) * BS_STR + bn4) = cvt4_tf32(rb[i]);
        }
        __syncthreads();
    }

    float gt = gt_p[0], gg = gg_p[0];
#pragma unroll
    for (int mt = 0; mt < 2; mt++)
#pragma unroll
        for (int rh = 0; rh < 2; rh++) {
            int r = row0 + warpm * 32 + mt * 16 + rh * 8 + gr;
            float bv = bo[r];
#pragma unroll
            for (int nt = 0; nt < 4; nt++) {
                int col = hw0 + warpn * 32 + nt * 8 + gc * 2;
                size_t idx = (size_t)b * CC * HW + (size_t)r * HW + col;
                float2 x2 = *(const float2*)(xin + idx);
                float2 t2 = *(const float2*)(g_tsa + idx);
                float2 o2;
                o2.x = gt * t2.x + gg * (c[mt][nt][rh * 2 + 0] + bv) + x2.x;
                o2.y = gt * t2.y + gg * (c[mt][nt][rh * 2 + 1] + bv) + x2.y;
                *(float2*)(out + idx) = o2;
            }
        }
}

// ---------------- fp32 proj (m/n, concentration-sensitive) ----------------
__global__ void __launch_bounds__(256) proj_gemm(
    const float* __restrict__ W, const float* __restrict__ bias,
    const float* __restrict__ x, float* __restrict__ out, int Co)
{
    __shared__ float As[16][64];
    __shared__ float Bs[16][64];
    int jt  = blockIdx.x;
    int o0  = blockIdx.y * 64;
    int b   = (jt * 64) / HW;
    int hw0 = (jt * 64) % HW;
    const float* xb = x + (size_t)b * CC * HW + hw0;
    int tid = threadIdx.x;
    int tx = tid & 15, ty = tid >> 4;
    float acc[4][4];
#pragma unroll
    for (int i = 0; i < 4; i++)
#pragma unroll
        for (int j = 0; j < 4; j++) acc[i][j] = 0.f;

    int lo  = tid >> 2;
    int lk4 = (tid & 3) * 4;
    int bk  = tid >> 4;
    int bj4 = (tid & 15) * 4;

    for (int k0 = 0; k0 < CC; k0 += 16) {
        float4 wv = make_float4(0.f, 0.f, 0.f, 0.f);
        if (o0 + lo < Co)
            wv = *(const float4*)(W + (size_t)(o0 + lo) * CC + k0 + lk4);
        As[lk4 + 0][lo] = wv.x; As[lk4 + 1][lo] = wv.y;
        As[lk4 + 2][lo] = wv.z; As[lk4 + 3][lo] = wv.w;
        float4 xv = *(const float4*)(xb + (size_t)(k0 + bk) * HW + bj4);
        *(float4*)&Bs[bk][bj4] = xv;
        __syncthreads();
#pragma unroll
        for (int k = 0; k < 16; k++) {
            float4 a  = *(float4*)&As[k][ty * 4];
            float4 bb = *(float4*)&Bs[k][tx * 4];
            float av[4] = {a.x, a.y, a.z, a.w};
            float bv[4] = {bb.x, bb.y, bb.z, bb.w};
#pragma unroll
            for (int i = 0; i < 4; i++)
#pragma unroll
                for (int j = 0; j < 4; j++)
                    acc[i][j] = fmaf(av[i], bv[j], acc[i][j]);
        }
        __syncthreads();
    }
#pragma unroll
    for (int i = 0; i < 4; i++) {
        int o = o0 + ty * 4 + i;
        if (o < Co) {
            float bsv = bias[o];
            float4 ov = make_float4(acc[i][0] + bsv, acc[i][1] + bsv,
                                    acc[i][2] + bsv, acc[i][3] + bsv);
            *(float4*)(out + (size_t)b * Co * HW + (size_t)o * HW + hw0 + tx * 4) = ov;
        }
    }
}

// wm/bm are pre-scaled by log2e so pa_softmax can use raw exp2.
__global__ void __launch_bounds__(256) concat_mn(
    const float* __restrict__ wm, const float* __restrict__ bm,
    const float* __restrict__ wn, const float* __restrict__ bn)
{
    int i = blockIdx.x * 256 + threadIdx.x;
    if (i < 32 * 256) { g_wmn[i] = wm[i] * LOG2E; g_wmn[32 * 256 + i] = wn[i]; }
    if (i < 32) { g_bmn[i] = bm[i] * LOG2E; g_bmn[32 + i] = bn[i]; }
}

// ---------------- FA2-style flash TSA with mma.sync bf16 ----------------
#define QS_STR 40
#define VS_STR 136
__global__ void __launch_bounds__(256) flash_mma()
{
    __shared__ __nv_bfloat16 Qs[128 * QS_STR];
    __shared__ __nv_bfloat16 Ks[128 * QS_STR];
    __shared__ __nv_bfloat16 Vs[32 * VS_STR];
    int tid = threadIdx.x, wid = tid >> 5, lane = tid & 31;
    int bh = blockIdx.y, i0 = blockIdx.x * 128;
    int gr = lane >> 2, gc = (lane & 3) * 2;

    const __nv_bfloat16* qsrc = g_qh + ((size_t)bh * HW + i0) * DK;
    const __nv_bfloat16* ksrc = g_kh + (size_t)bh * HW * DK;
    const __nv_bfloat16* vsrc = g_vh + (size_t)bh * DK * HW;

    for (int e = tid; e < 512; e += 256) {
        int r = e >> 2, c8 = (e & 3) * 8;
        *(uint4*)(Qs + r * QS_STR + c8) = *(const uint4*)(qsrc + r * DK + c8);
    }
    __syncthreads();

    uint32_t qa[2][4];
    {
        const __nv_bfloat16* qb = Qs + (wid * 16 + gr) * QS_STR;
#pragma unroll
        for (int kc = 0; kc < 2; kc++) {
            qa[kc][0] = *(const uint32_t*)(qb + kc * 16 + gc);
            qa[kc][1] = *(const uint32_t*)(qb + 8 * QS_STR + kc * 16 + gc);
            qa[kc][2] = *(const uint32_t*)(qb + kc * 16 + gc + 8);
            qa[kc][3] = *(const uint32_t*)(qb + 8 * QS_STR + kc * 16 + gc + 8);
        }
    }

    int kr  = tid >> 2,        kc8 = (tid & 3) * 8;
    int kr1 = (tid + 256) >> 2;
    int vd  = tid >> 4,        vc8 = (tid & 15) * 8;
    int vd1 = (tid + 256) >> 4;

    uint4 kreg[2], vreg[2];
    kreg[0] = *(const uint4*)(ksrc + (size_t)kr  * DK + kc8);
    kreg[1] = *(const uint4*)(ksrc + (size_t)kr1 * DK + kc8);
    vreg[0] = *(const uint4*)(vsrc + (size_t)vd  * HW + vc8);
    vreg[1] = *(const uint4*)(vsrc + (size_t)vd1 * HW + vc8);

    float o[4][4];
#pragma unroll
    for (int i = 0; i < 4; i++)
#pragma unroll
        for (int j = 0; j < 4; j++) o[i][j] = 0.f;
    float l0 = 0.f, l1 = 0.f;

    for (int kt = 0; kt < 18; kt++) {
        __syncthreads();
        *(uint4*)(Ks + kr  * QS_STR + kc8) = kreg[0];
        *(uint4*)(Ks + kr1 * QS_STR + kc8) = kreg[1];
        *(uint4*)(Vs + vd  * VS_STR + vc8) = vreg[0];
        *(uint4*)(Vs + vd1 * VS_STR + vc8) = vreg[1];
        __syncthreads();
        if (kt + 1 < 18) {
            int j1 = (kt + 1) * 128;
            kreg[0] = *(const uint4*)(ksrc + (size_t)(j1 + kr)  * DK + kc8);
            kreg[1] = *(const uint4*)(ksrc + (size_t)(j1 + kr1) * DK + kc8);
            vreg[0] = *(const uint4*)(vsrc + (size_t)vd  * HW + j1 + vc8);
            vreg[1] = *(const uint4*)(vsrc + (size_t)vd1 * HW + j1 + vc8);
        }

        float s[16][4];
#pragma unroll
        for (int nt = 0; nt < 16; nt++) {
            s[nt][0] = 0.f; s[nt][1] = 0.f; s[nt][2] = 0.f; s[nt][3] = 0.f;
            const __nv_bfloat16* kb = Ks + (nt * 8 + gr) * QS_STR;
#pragma unroll
            for (int kc = 0; kc < 2; kc++) {
                uint32_t b0 = *(const uint32_t*)(kb + kc * 16 + gc);
                uint32_t b1 = *(const uint32_t*)(kb + kc * 16 + gc + 8);
                mma16816(s[nt], qa[kc], b0, b1);
            }
        }

        uint32_t pa_[8][4];
#pragma unroll
        for (int h2 = 0; h2 < 8; h2++) {
            float e00 = ex2(s[2 * h2][0]),     e01 = ex2(s[2 * h2][1]);
            float e02 = ex2(s[2 * h2][2]),     e03 = ex2(s[2 * h2][3]);
            float f00 = ex2(s[2 * h2 + 1][0]), f01 = ex2(s[2 * h2 + 1][1]);
            float f02 = ex2(s[2 * h2 + 1][2]), f03 = ex2(s[2 * h2 + 1][3]);
            l0 += (e00 + e01) + (f00 + f01);
            l1 += (e02 + e03) + (f02 + f03);
            pa_[h2][0] = pack_bf16x2(e01, e00);
            pa_[h2][1] = pack_bf16x2(e03, e02);
            pa_[h2][2] = pack_bf16x2(f01, f00);
            pa_[h2][3] = pack_bf16x2(f03, f02);
        }

#pragma unroll
        for (int kc2 = 0; kc2 < 8; kc2++) {
#pragma unroll
            for (int dt = 0; dt < 4; dt++) {
                const __nv_bfloat16* vb = Vs + (dt * 8 + gr) * VS_STR + kc2 * 16 + gc;
                uint32_t b0 = *(const uint32_t*)(vb);
                uint32_t b1 = *(const uint32_t*)(vb + 8);
                mma16816(o[dt], pa_[kc2], b0, b1);
            }
        }
    }

    l0 += __shfl_xor_sync(0xffffffffu, l0, 1);
    l0 += __shfl_xor_sync(0xffffffffu, l0, 2);
    l1 += __shfl_xor_sync(0xffffffffu, l1, 1);
    l1 += __shfl_xor_sync(0xffffffffu, l1, 2);
    float inv0 = 1.f / l0, inv1 = 1.f / l1;

    int b = bh >> 3, h = bh & 7;
    float* ob = g_tsa + ((size_t)b * CC + h * DK) * HW;
    int tok0 = i0 + wid * 16 + gr;
#pragma unroll
    for (int dt = 0; dt < 4; dt++) {
        int d = dt * 8 + gc;
        ob[(size_t)(d)     * HW + tok0]     = o[dt][0] * inv0;
        ob[(size_t)(d + 1) * HW + tok0]     = o[dt][1] * inv0;
        ob[(size_t)(d)     * HW + tok0 + 8] = o[dt][2] * inv1;
        ob[(size_t)(d + 1) * HW + tok0 + 8] = o[dt][3] * inv1;
    }
}

// ---------------- launch ----------------
extern "C" void kernel_launch(void* const* d_in, const int* in_sizes, int n_in,
                              void* d_out, int out_size)
{
    const float* x   = (const float*)d_in[0];
    const float* wq  = (const float*)d_in[1];
    const float* bq  = (const float*)d_in[2];
    const float* wk  = (const float*)d_in[3];
    const float* bk  = (const float*)d_in[4];
    const float* wv  = (const float*)d_in[5];
    const float* bv  = (const float*)d_in[6];
    const float* wm  = (const float*)d_in[7];
    const float* bm  = (const float*)d_in[8];
    const float* wn  = (const float*)d_in[9];
    const float* bn  = (const float*)d_in[10];
    const float* ww  = (const float*)d_in[11];
    const float* bw  = (const float*)d_in[12];
    const float* wo  = (const float*)d_in[13];
    const float* bo  = (const float*)d_in[14];
    const float* gts = (const float*)d_in[15];
    const float* ggs = (const float*)d_in[16];
    float* out = (float*)d_out;

    float *pmn, *pwmn, *pbmn;
    cudaGetSymbolAddress((void**)&pmn, g_mn);
    cudaGetSymbolAddress((void**)&pwmn, g_wmn);
    cudaGetSymbolAddress((void**)&pbmn, g_bmn);

    static int init_done = 0;
    static cudaStream_t s1;
    static cudaEvent_t ev_fork, ev_join;
    const int DBUF_SMEM = (2 * ASZ + 2 * BSZ) * 4;   // 53248 B
    if (!init_done) {
        cudaFuncSetAttribute(tf32_gsa, cudaFuncAttributeMaxDynamicSharedMemorySize, DBUF_SMEM);
        cudaFuncSetAttribute(tf32_final, cudaFuncAttributeMaxDynamicSharedMemorySize, DBUF_SMEM);
        cudaStreamCreateWithFlags(&s1, cudaStreamNonBlocking);
        cudaEventCreateWithFlags(&ev_fork, cudaEventDisableTiming);
        cudaEventCreateWithFlags(&ev_join, cudaEventDisableTiming);
        init_done = 1;
    }

    dim3 blk(256);

    // fork: side stream runs the GSA-score branch concurrently with QKVW+flash
    cudaEventRecord(ev_fork, 0);
    cudaStreamWaitEvent(s1, ev_fork, 0);

    // branch B (s1): mn weights -> mn projection -> pa scores+exp
    concat_mn<<<32, blk, 0, s1>>>(wm, bm, wn, bn);
    proj_gemm<<<dim3(BB * HW / 64, 1), blk, 0, s1>>>(pwmn, pbmn, x, pmn, 64);
    pa_softmax<<<dim3(HW / 32, BB), blk, 0, s1>>>();

    // branch A (default): QKVW projection -> flash attention
    tf32_proj4<<<dim3(36, 16), blk>>>(wq, bq, wk, bk, wv, bv, ww, bw, x);
    flash_mma<<<dim3(HW / 128, BB * HEADS), blk>>>();

    // join: gsa needs pa/l (branch B) and w (branch A)
    cudaEventRecord(ev_join, s1);
    cudaStreamWaitEvent(0, ev_join, 0);

    tf32_gsa<<<dim3(36, 4), blk, DBUF_SMEM>>>();
    tf32_final<<<dim3(36, 4), blk, DBUF_SMEM>>>(wo, bo, x, gts, ggs, out);
}